// round 1
// baseline (speedup 1.0000x reference)
#include <cuda_runtime.h>
#include <math.h>

#define BB    4
#define TT    2048
#define DIM   1024
#define NH    16
#define HP    64
#define FFD   4096
#define BT    (BB*TT)          // 8192

// ---------------- scratch (static device globals; no runtime allocs) ----------------
__device__ float g_nX[(size_t)BT*DIM];
__device__ float g_Q [(size_t)BT*DIM];
__device__ float g_K [(size_t)BT*DIM];
__device__ float g_V [(size_t)BT*DIM];
__device__ float g_nv[(size_t)BT*DIM];
__device__ float g_seq[(size_t)BT*DIM];
__device__ float g_preff[(size_t)BT*DIM];
__device__ float g_hidden[(size_t)BT*FFD];
__device__ float g_Wt[(size_t)3*DIM*DIM];          // permuted WQ,WK,WV
__device__ float g_Sfb[(size_t)BB*NH*TT*TT];       // attn fallback if d_out lacks room

// ---------------- layernorm (optionally + residual) ----------------
// out[row] = (resid? resid[row] : 0) + LN(x[row]) * g + b     (D = 1024)
__global__ void ln_kernel(const float* __restrict__ x,
                          const float* __restrict__ g,
                          const float* __restrict__ b,
                          const float* __restrict__ resid,
                          float* __restrict__ out)
{
    const size_t row = blockIdx.x;
    const float4* xr = (const float4*)(x + row * (size_t)DIM);
    const int tid = threadIdx.x;                 // 256 threads, 1 float4 each
    float4 xv = xr[tid];

    float s  = xv.x + xv.y + xv.z + xv.w;
    float ss = xv.x*xv.x + xv.y*xv.y + xv.z*xv.z + xv.w*xv.w;

    // block reduce (sum, sumsq)
    #pragma unroll
    for (int o = 16; o > 0; o >>= 1) {
        s  += __shfl_xor_sync(0xffffffffu, s,  o);
        ss += __shfl_xor_sync(0xffffffffu, ss, o);
    }
    __shared__ float rs[8], rss[8];
    int wid = tid >> 5, lane = tid & 31;
    if (lane == 0) { rs[wid] = s; rss[wid] = ss; }
    __syncthreads();
    __shared__ float s_mean, s_rstd;
    if (tid == 0) {
        float ts = 0.f, tss = 0.f;
        #pragma unroll
        for (int i = 0; i < 8; i++) { ts += rs[i]; tss += rss[i]; }
        float mean = ts * (1.0f / DIM);
        float var  = tss * (1.0f / DIM) - mean * mean;
        s_mean = mean;
        s_rstd = rsqrtf(var + 1e-5f);
    }
    __syncthreads();
    const float mean = s_mean, rstd = s_rstd;

    const float4 gv = ((const float4*)g)[tid];
    const float4 bv = ((const float4*)b)[tid];
    float4 o4;
    o4.x = (xv.x - mean) * rstd * gv.x + bv.x;
    o4.y = (xv.y - mean) * rstd * gv.y + bv.y;
    o4.z = (xv.z - mean) * rstd * gv.z + bv.z;
    o4.w = (xv.w - mean) * rstd * gv.w + bv.w;
    if (resid) {
        const float4 rv = ((const float4*)(resid + row * (size_t)DIM))[tid];
        o4.x += rv.x; o4.y += rv.y; o4.z += rv.z; o4.w += rv.w;
    }
    ((float4*)(out + row * (size_t)DIM))[tid] = o4;
}

// ---------------- permute (H,D,P) -> (D, H*P) ----------------
__global__ void wtrans_kernel(const float* __restrict__ w, float* __restrict__ o)
{
    int idx = blockIdx.x * blockDim.x + threadIdx.x;     // over DIM*DIM = 1M
    if (idx >= DIM * DIM) return;
    int p = idx & 63;
    int d = (idx >> 6) & 1023;
    int h = idx >> 16;
    o[(size_t)d * DIM + h * HP + p] = w[idx];
}

// ---------------- in-place row softmax over 2048 ----------------
__global__ void softmax_kernel(float* __restrict__ a)
{
    const size_t row = blockIdx.x;
    float4* p4 = (float4*)(a + row * (size_t)TT);
    const int tid = threadIdx.x;                  // 256 threads * 2 float4 = 2048
    float4 v0 = p4[tid], v1 = p4[tid + 256];

    float mx = fmaxf(fmaxf(fmaxf(v0.x, v0.y), fmaxf(v0.z, v0.w)),
                     fmaxf(fmaxf(v1.x, v1.y), fmaxf(v1.z, v1.w)));
    #pragma unroll
    for (int o = 16; o > 0; o >>= 1) mx = fmaxf(mx, __shfl_xor_sync(0xffffffffu, mx, o));
    __shared__ float red[8];
    int wid = tid >> 5, lane = tid & 31;
    if (lane == 0) red[wid] = mx;
    __syncthreads();
    __shared__ float s_b;
    if (tid == 0) {
        float m = red[0];
        #pragma unroll
        for (int i = 1; i < 8; i++) m = fmaxf(m, red[i]);
        s_b = m;
    }
    __syncthreads();
    mx = s_b;

    v0.x = expf(v0.x - mx); v0.y = expf(v0.y - mx); v0.z = expf(v0.z - mx); v0.w = expf(v0.w - mx);
    v1.x = expf(v1.x - mx); v1.y = expf(v1.y - mx); v1.z = expf(v1.z - mx); v1.w = expf(v1.w - mx);
    float s = v0.x + v0.y + v0.z + v0.w + v1.x + v1.y + v1.z + v1.w;
    #pragma unroll
    for (int o = 16; o > 0; o >>= 1) s += __shfl_xor_sync(0xffffffffu, s, o);
    if (lane == 0) red[wid] = s;
    __syncthreads();
    if (tid == 0) {
        float t = 0.f;
        #pragma unroll
        for (int i = 0; i < 8; i++) t += red[i];
        s_b = 1.0f / t;
    }
    __syncthreads();
    const float inv = s_b;
    v0.x *= inv; v0.y *= inv; v0.z *= inv; v0.w *= inv;
    v1.x *= inv; v1.y *= inv; v1.z *= inv; v1.w *= inv;
    p4[tid] = v0; p4[tid + 256] = v1;
}

// ---------------- generic batched SGEMM, 128x128x16, 256 thr, 8x8/thread ----------------
// C[m,n] = alpha * sum_k A[m,k] * (TRANSB ? B[n,k] : B[k,n])      (+ epilogue)
// epi: 0 = none, 1 = gelu(x + bias[n]), 2 = x + bias[n] + resid[m*ldr+n]
// batch: z -> (bb = z/nh, hh = z%nh); pointers advanced by bb*s?b + hh*s?h
__device__ __forceinline__ float gelu_exact(float x)
{
    return 0.5f * x * (1.0f + erff(x * 0.70710678118654752440f));
}

template<bool TRANSB>
__global__ __launch_bounds__(256) void sgemm_kernel(
    int M, int N, int K,
    const float* __restrict__ A, int lda, long long sAb, long long sAh,
    const float* __restrict__ B, int ldb, long long sBb, long long sBh,
    float* __restrict__ C, int ldc, long long sCb, long long sCh,
    int nh, float alpha, int epi,
    const float* __restrict__ bias,
    const float* __restrict__ resid, int ldr)
{
    const int z = blockIdx.z;
    const int bb = z / nh, hh = z % nh;
    A += (size_t)bb * sAb + (size_t)hh * sAh;
    B += (size_t)bb * sBb + (size_t)hh * sBh;
    C += (size_t)bb * sCb + (size_t)hh * sCh;

    __shared__ float As[16][132];
    __shared__ float Bs[16][132];

    const int tid = threadIdx.x;
    const int m0 = blockIdx.y * 128;
    const int n0 = blockIdx.x * 128;

    float acc[8][8];
    #pragma unroll
    for (int i = 0; i < 8; i++)
        #pragma unroll
        for (int j = 0; j < 8; j++) acc[i][j] = 0.f;

    const int arow = tid >> 2;          // 0..63
    const int acol = (tid & 3) * 4;     // 0,4,8,12
    const int ty = tid >> 4, tx = tid & 15;

    for (int k0 = 0; k0 < K; k0 += 16) {
        // load A tile: 128 rows x 16 k  (store transposed -> As[k][m])
        #pragma unroll
        for (int i = 0; i < 2; i++) {
            int m = m0 + arow + i * 64;
            float4 av = make_float4(0.f, 0.f, 0.f, 0.f);
            if (m < M) av = *(const float4*)(A + (size_t)m * lda + k0 + acol);
            As[acol + 0][arow + i * 64] = av.x;
            As[acol + 1][arow + i * 64] = av.y;
            As[acol + 2][arow + i * 64] = av.z;
            As[acol + 3][arow + i * 64] = av.w;
        }
        // load B tile
        if (!TRANSB) {
            const int brow = tid >> 5;          // 0..7
            const int bcol = (tid & 31) * 4;    // 0..124
            #pragma unroll
            for (int i = 0; i < 2; i++) {
                int kk = brow + i * 8;
                int n = n0 + bcol;
                float4 bv = make_float4(0.f, 0.f, 0.f, 0.f);
                if (n < N) bv = *(const float4*)(B + (size_t)(k0 + kk) * ldb + n);
                *(float4*)&Bs[kk][bcol] = bv;
            }
        } else {
            const int brow = tid >> 2;          // n index 0..63
            const int bcol = (tid & 3) * 4;     // k index 0,4,8,12
            #pragma unroll
            for (int i = 0; i < 2; i++) {
                int n = n0 + brow + i * 64;
                float4 bv = make_float4(0.f, 0.f, 0.f, 0.f);
                if (n < N) bv = *(const float4*)(B + (size_t)n * ldb + k0 + bcol);
                Bs[bcol + 0][brow + i * 64] = bv.x;
                Bs[bcol + 1][brow + i * 64] = bv.y;
                Bs[bcol + 2][brow + i * 64] = bv.z;
                Bs[bcol + 3][brow + i * 64] = bv.w;
            }
        }
        __syncthreads();

        #pragma unroll
        for (int kk = 0; kk < 16; kk++) {
            float4 a0 = *(float4*)&As[kk][ty * 8];
            float4 a1 = *(float4*)&As[kk][ty * 8 + 4];
            float4 b0 = *(float4*)&Bs[kk][tx * 8];
            float4 b1 = *(float4*)&Bs[kk][tx * 8 + 4];
            float ar[8] = {a0.x, a0.y, a0.z, a0.w, a1.x, a1.y, a1.z, a1.w};
            float br[8] = {b0.x, b0.y, b0.z, b0.w, b1.x, b1.y, b1.z, b1.w};
            #pragma unroll
            for (int i = 0; i < 8; i++)
                #pragma unroll
                for (int j = 0; j < 8; j++)
                    acc[i][j] += ar[i] * br[j];
        }
        __syncthreads();
    }

    // epilogue
    #pragma unroll
    for (int i = 0; i < 8; i++) {
        int m = m0 + ty * 8 + i;
        if (m >= M) continue;
        #pragma unroll
        for (int j = 0; j < 8; j += 4) {
            int n = n0 + tx * 8 + j;
            if (n >= N) continue;
            float4 v;
            v.x = alpha * acc[i][j + 0];
            v.y = alpha * acc[i][j + 1];
            v.z = alpha * acc[i][j + 2];
            v.w = alpha * acc[i][j + 3];
            if (epi == 1) {
                const float4 bi = *(const float4*)(bias + n);
                v.x = gelu_exact(v.x + bi.x);
                v.y = gelu_exact(v.y + bi.y);
                v.z = gelu_exact(v.z + bi.z);
                v.w = gelu_exact(v.w + bi.w);
            } else if (epi == 2) {
                const float4 bi = *(const float4*)(bias + n);
                const float4 rv = *(const float4*)(resid + (size_t)m * ldr + n);
                v.x += bi.x + rv.x;
                v.y += bi.y + rv.y;
                v.z += bi.z + rv.z;
                v.w += bi.w + rv.w;
            }
            *(float4*)(C + (size_t)m * ldc + n) = v;
        }
    }
}

// ---------------- host launch ----------------
static inline dim3 gemm_grid(int M, int N, int Z)
{
    return dim3((N + 127) / 128, (M + 127) / 128, Z);
}

extern "C" void kernel_launch(void* const* d_in, const int* in_sizes, int n_in,
                              void* d_out, int out_size)
{
    const float* X      = (const float*)d_in[0];
    const float* WQ     = (const float*)d_in[1];
    const float* WK     = (const float*)d_in[2];
    const float* WV     = (const float*)d_in[3];
    const float* WO     = (const float*)d_in[4];
    const float* attn_g = (const float*)d_in[5];
    const float* attn_b = (const float*)d_in[6];
    const float* ff_g   = (const float*)d_in[7];
    const float* ff_b   = (const float*)d_in[8];
    const float* fW1    = (const float*)d_in[9];
    const float* fb1    = (const float*)d_in[10];
    const float* fW2    = (const float*)d_in[11];
    const float* fb2    = (const float*)d_in[12];
    float* out0 = (float*)d_out;

    // scratch pointers
    float *nX, *Q, *K, *V, *nv, *seq, *preff, *hidden, *Wt, *Sfb;
    cudaGetSymbolAddress((void**)&nX,     g_nX);
    cudaGetSymbolAddress((void**)&Q,      g_Q);
    cudaGetSymbolAddress((void**)&K,      g_K);
    cudaGetSymbolAddress((void**)&V,      g_V);
    cudaGetSymbolAddress((void**)&nv,     g_nv);
    cudaGetSymbolAddress((void**)&seq,    g_seq);
    cudaGetSymbolAddress((void**)&preff,  g_preff);
    cudaGetSymbolAddress((void**)&hidden, g_hidden);
    cudaGetSymbolAddress((void**)&Wt,     g_Wt);
    cudaGetSymbolAddress((void**)&Sfb,    g_Sfb);

    const long long xel     = (long long)BT * DIM;                 // 8,388,608
    const long long attn_el = (long long)BB * NH * TT * TT;        // 268,435,456
    float* attn = ((long long)out_size >= xel + attn_el) ? (out0 + xel) : Sfb;

    // 1) nX = LN(X)
    ln_kernel<<<BT, 256>>>(X, attn_g, attn_b, nullptr, nX);

    // 2) permute weights (H,D,P) -> (D,H*P)
    wtrans_kernel<<<(DIM * DIM + 255) / 256, 256>>>(WQ, Wt + 0 * (size_t)DIM * DIM);
    wtrans_kernel<<<(DIM * DIM + 255) / 256, 256>>>(WK, Wt + 1 * (size_t)DIM * DIM);
    wtrans_kernel<<<(DIM * DIM + 255) / 256, 256>>>(WV, Wt + 2 * (size_t)DIM * DIM);

    // 3) Q/K/V = nX @ Wt   (8192 x 1024 x 1024)
    sgemm_kernel<false><<<gemm_grid(BT, DIM, 1), 256>>>(
        BT, DIM, DIM, nX, DIM, 0, 0, Wt + 0 * (size_t)DIM * DIM, DIM, 0, 0,
        Q, DIM, 0, 0, 1, 1.0f, 0, nullptr, nullptr, 0);
    sgemm_kernel<false><<<gemm_grid(BT, DIM, 1), 256>>>(
        BT, DIM, DIM, nX, DIM, 0, 0, Wt + 1 * (size_t)DIM * DIM, DIM, 0, 0,
        K, DIM, 0, 0, 1, 1.0f, 0, nullptr, nullptr, 0);
    sgemm_kernel<false><<<gemm_grid(BT, DIM, 1), 256>>>(
        BT, DIM, DIM, nX, DIM, 0, 0, Wt + 2 * (size_t)DIM * DIM, DIM, 0, 0,
        V, DIM, 0, 0, 1, 1.0f, 0, nullptr, nullptr, 0);

    // 4) scores: S[b,h,q,k] = (1/8) * sum_p K[b,q,h,p] * Q[b,k,h,p]   (NT, batched over b*h)
    sgemm_kernel<true><<<gemm_grid(TT, TT, BB * NH), 256>>>(
        TT, TT, HP,
        K, DIM, (long long)TT * DIM, HP,
        Q, DIM, (long long)TT * DIM, HP,
        attn, TT, (long long)NH * TT * TT, (long long)TT * TT,
        NH, 0.125f, 0, nullptr, nullptr, 0);

    // 5) softmax over k, in place
    softmax_kernel<<<BB * NH * TT, 256>>>(attn);

    // 6) AV: nv[b,q,h,p] = sum_k attn[b,h,q,k] * V[b,k,h,p]
    sgemm_kernel<false><<<gemm_grid(TT, HP, BB * NH), 256>>>(
        TT, HP, TT,
        attn, TT, (long long)NH * TT * TT, (long long)TT * TT,
        V, DIM, (long long)TT * DIM, HP,
        nv, DIM, (long long)TT * DIM, HP,
        NH, 1.0f, 0, nullptr, nullptr, 0);

    // 7) seq = nv @ WO   (WO (H,P,D) is already [1024,1024] row-major)
    sgemm_kernel<false><<<gemm_grid(BT, DIM, 1), 256>>>(
        BT, DIM, DIM, nv, DIM, 0, 0, WO, DIM, 0, 0,
        seq, DIM, 0, 0, 1, 1.0f, 0, nullptr, nullptr, 0);

    // 8) pre_ff = X + LN(seq)
    ln_kernel<<<BT, 256>>>(seq, ff_g, ff_b, X, preff);

    // 9) hidden = gelu(pre_ff @ fW1 + fb1)
    sgemm_kernel<false><<<gemm_grid(BT, FFD, 1), 256>>>(
        BT, FFD, DIM, preff, DIM, 0, 0, fW1, FFD, 0, 0,
        hidden, FFD, 0, 0, 1, 1.0f, 1, fb1, nullptr, 0);

    // 10) out = hidden @ fW2 + fb2 + pre_ff
    sgemm_kernel<false><<<gemm_grid(BT, DIM, 1), 256>>>(
        BT, DIM, FFD, hidden, FFD, 0, 0, fW2, DIM, 0, 0,
        out0, DIM, 0, 0, 1, 1.0f, 2, fb2, preff, DIM);
}

// round 2
// speedup vs baseline: 2.5703x; 2.5703x over previous
#include <cuda_runtime.h>
#include <math.h>
#include <stdint.h>

#define BB    4
#define TT    2048
#define DIM   1024
#define NH    16
#define HP    64
#define FFD   4096
#define BT    (BB*TT)          // 8192
#define D3    (3*DIM)          // 3072

// ---------------- scratch (static device globals; no runtime allocs) ----------------
__device__ float g_nX[(size_t)BT*DIM];
__device__ float g_QKV[(size_t)BT*D3];
__device__ float g_nv[(size_t)BT*DIM];
__device__ float g_seq[(size_t)BT*DIM];
__device__ float g_preff[(size_t)BT*DIM];
__device__ float g_hidden[(size_t)BT*FFD];
__device__ float g_Wt[(size_t)DIM*D3];             // permuted WQ|WK|WV  [D][3D]
__device__ float g_Sfb[(size_t)BB*NH*TT*TT];       // attn fallback if d_out lacks room

// ---------------- layernorm (optionally + residual) ----------------
__global__ void ln_kernel(const float* __restrict__ x,
                          const float* __restrict__ g,
                          const float* __restrict__ b,
                          const float* __restrict__ resid,
                          float* __restrict__ out)
{
    const size_t row = blockIdx.x;
    const float4* xr = (const float4*)(x + row * (size_t)DIM);
    const int tid = threadIdx.x;                 // 256 threads, 1 float4 each
    float4 xv = xr[tid];

    float s  = xv.x + xv.y + xv.z + xv.w;
    float ss = xv.x*xv.x + xv.y*xv.y + xv.z*xv.z + xv.w*xv.w;

    #pragma unroll
    for (int o = 16; o > 0; o >>= 1) {
        s  += __shfl_xor_sync(0xffffffffu, s,  o);
        ss += __shfl_xor_sync(0xffffffffu, ss, o);
    }
    __shared__ float rs[8], rss[8];
    int wid = tid >> 5, lane = tid & 31;
    if (lane == 0) { rs[wid] = s; rss[wid] = ss; }
    __syncthreads();
    __shared__ float s_mean, s_rstd;
    if (tid == 0) {
        float ts = 0.f, tss = 0.f;
        #pragma unroll
        for (int i = 0; i < 8; i++) { ts += rs[i]; tss += rss[i]; }
        float mean = ts * (1.0f / DIM);
        float var  = tss * (1.0f / DIM) - mean * mean;
        s_mean = mean;
        s_rstd = rsqrtf(var + 1e-5f);
    }
    __syncthreads();
    const float mean = s_mean, rstd = s_rstd;

    const float4 gv = ((const float4*)g)[tid];
    const float4 bv = ((const float4*)b)[tid];
    float4 o4;
    o4.x = (xv.x - mean) * rstd * gv.x + bv.x;
    o4.y = (xv.y - mean) * rstd * gv.y + bv.y;
    o4.z = (xv.z - mean) * rstd * gv.z + bv.z;
    o4.w = (xv.w - mean) * rstd * gv.w + bv.w;
    if (resid) {
        const float4 rv = ((const float4*)(resid + row * (size_t)DIM))[tid];
        o4.x += rv.x; o4.y += rv.y; o4.z += rv.z; o4.w += rv.w;
    }
    ((float4*)(out + row * (size_t)DIM))[tid] = o4;
}

// ---------------- permute (H,D,P) -> column block of (D, 3D) ----------------
__global__ void wtrans_kernel(const float* __restrict__ w, float* __restrict__ o, int coloff)
{
    int idx = blockIdx.x * blockDim.x + threadIdx.x;     // over DIM*DIM = 1M
    if (idx >= DIM * DIM) return;
    int p = idx & 63;
    int d = (idx >> 6) & 1023;
    int h = idx >> 16;
    o[(size_t)d * D3 + coloff + h * HP + p] = w[idx];
}

// ---------------- in-place row softmax over 2048 ----------------
__global__ void softmax_kernel(float* __restrict__ a)
{
    const size_t row = blockIdx.x;
    float4* p4 = (float4*)(a + row * (size_t)TT);
    const int tid = threadIdx.x;                  // 256 threads * 2 float4 = 2048
    float4 v0 = p4[tid], v1 = p4[tid + 256];

    float mx = fmaxf(fmaxf(fmaxf(v0.x, v0.y), fmaxf(v0.z, v0.w)),
                     fmaxf(fmaxf(v1.x, v1.y), fmaxf(v1.z, v1.w)));
    #pragma unroll
    for (int o = 16; o > 0; o >>= 1) mx = fmaxf(mx, __shfl_xor_sync(0xffffffffu, mx, o));
    __shared__ float red[8];
    int wid = tid >> 5, lane = tid & 31;
    if (lane == 0) red[wid] = mx;
    __syncthreads();
    __shared__ float s_b;
    if (tid == 0) {
        float m = red[0];
        #pragma unroll
        for (int i = 1; i < 8; i++) m = fmaxf(m, red[i]);
        s_b = m;
    }
    __syncthreads();
    mx = s_b;

    v0.x = expf(v0.x - mx); v0.y = expf(v0.y - mx); v0.z = expf(v0.z - mx); v0.w = expf(v0.w - mx);
    v1.x = expf(v1.x - mx); v1.y = expf(v1.y - mx); v1.z = expf(v1.z - mx); v1.w = expf(v1.w - mx);
    float s = v0.x + v0.y + v0.z + v0.w + v1.x + v1.y + v1.z + v1.w;
    #pragma unroll
    for (int o = 16; o > 0; o >>= 1) s += __shfl_xor_sync(0xffffffffu, s, o);
    if (lane == 0) red[wid] = s;
    __syncthreads();
    if (tid == 0) {
        float t = 0.f;
        #pragma unroll
        for (int i = 0; i < 8; i++) t += red[i];
        s_b = 1.0f / t;
    }
    __syncthreads();
    const float inv = s_b;
    v0.x *= inv; v0.y *= inv; v0.z *= inv; v0.w *= inv;
    v1.x *= inv; v1.y *= inv; v1.z *= inv; v1.w *= inv;
    p4[tid] = v0; p4[tid + 256] = v1;
}

// ---------------- TF32 tensor-core batched GEMM ----------------
// C[m,n] = alpha * sum_k A[m,k] * (TRANSB ? B[n,k] : B[k,n])   (+ epilogue)
// epi: 0 none, 1 gelu(x + bias[n]), 2 x + bias[n] + resid[m*ldr+n]
// tile 128x128x16, 256 thr (8 warps 2x4), warp tile 64x32, mma m16n8k8 tf32

__device__ __forceinline__ float gelu_exact(float x)
{
    return 0.5f * x * (1.0f + erff(x * 0.70710678118654752440f));
}

__device__ __forceinline__ unsigned f2tf(float x)
{
    unsigned r;
    asm("cvt.rna.tf32.f32 %0, %1;" : "=r"(r) : "f"(x));
    return r;
}

__device__ __forceinline__ uint4 cvt4(float4 v)
{
    uint4 r;
    r.x = f2tf(v.x); r.y = f2tf(v.y); r.z = f2tf(v.z); r.w = f2tf(v.w);
    return r;
}

__device__ __forceinline__ void mma_tf32(float c[4], const unsigned a[4], const unsigned b[2])
{
    asm volatile(
        "mma.sync.aligned.m16n8k8.row.col.f32.tf32.tf32.f32 "
        "{%0,%1,%2,%3}, {%4,%5,%6,%7}, {%8,%9}, {%0,%1,%2,%3};"
        : "+f"(c[0]), "+f"(c[1]), "+f"(c[2]), "+f"(c[3])
        : "r"(a[0]), "r"(a[1]), "r"(a[2]), "r"(a[3]), "r"(b[0]), "r"(b[1]));
}

template<bool TRANSB>
__global__ __launch_bounds__(256) void tgemm_kernel(
    int M, int N, int K,
    const float* __restrict__ A, int lda, long long sAb, long long sAh,
    const float* __restrict__ B, int ldb, long long sBb, long long sBh,
    float* __restrict__ C, int ldc, long long sCb, long long sCh,
    int nh, float alpha, int epi,
    const float* __restrict__ bias,
    const float* __restrict__ resid, int ldr)
{
    const int z = blockIdx.z;
    const int bb = z / nh, hh = z % nh;
    A += (size_t)bb * sAb + (size_t)hh * sAh;
    B += (size_t)bb * sBb + (size_t)hh * sBh;
    C += (size_t)bb * sCb + (size_t)hh * sCh;

    // A tile: [128 m][20] (k contiguous, stride 20)
    // B tile: TRANSB ? [128 n][20] : [16 k][136 n]
    __shared__ unsigned As[128 * 20];
    __shared__ unsigned Bs[128 * 20];

    const int tid  = threadIdx.x;
    const int m0   = blockIdx.y * 128;
    const int n0   = blockIdx.x * 128;
    const int w    = tid >> 5, lane = tid & 31;
    const int lr   = lane >> 2, lc = lane & 3;
    const int wm   = (w & 1) * 64;      // warp m offset in tile
    const int wn   = (w >> 1) * 32;     // warp n offset in tile

    float acc[16][4];
    #pragma unroll
    for (int i = 0; i < 16; i++)
        #pragma unroll
        for (int j = 0; j < 4; j++) acc[i][j] = 0.f;

    // global load mapping
    const int arow = tid >> 2;           // 0..63
    const int acol = (tid & 3) * 4;      // 0,4,8,12
    const int brow = tid >> 5;           // 0..7   (non-trans B)
    const int bcol = (tid & 31) * 4;     // 0..124 (non-trans B)

    float4 ra[2], rb[2];

    // prefetch tile 0
    {
        #pragma unroll
        for (int i = 0; i < 2; i++) {
            int m = m0 + arow + i * 64;
            ra[i] = (m < M) ? *(const float4*)(A + (size_t)m * lda + acol)
                            : make_float4(0.f, 0.f, 0.f, 0.f);
        }
        if (TRANSB) {
            #pragma unroll
            for (int i = 0; i < 2; i++) {
                int n = n0 + arow + i * 64;
                rb[i] = (n < N) ? *(const float4*)(B + (size_t)n * ldb + acol)
                                : make_float4(0.f, 0.f, 0.f, 0.f);
            }
        } else {
            #pragma unroll
            for (int i = 0; i < 2; i++) {
                int n = n0 + bcol;
                rb[i] = (n < N) ? *(const float4*)(B + (size_t)(brow + i * 8) * ldb + n)
                                : make_float4(0.f, 0.f, 0.f, 0.f);
            }
        }
    }

    for (int k0 = 0; k0 < K; k0 += 16) {
        // commit prefetched tile to smem
        #pragma unroll
        for (int i = 0; i < 2; i++)
            *(uint4*)&As[(arow + i * 64) * 20 + acol] = cvt4(ra[i]);
        if (TRANSB) {
            #pragma unroll
            for (int i = 0; i < 2; i++)
                *(uint4*)&Bs[(arow + i * 64) * 20 + acol] = cvt4(rb[i]);
        } else {
            #pragma unroll
            for (int i = 0; i < 2; i++)
                *(uint4*)&Bs[(brow + i * 8) * 136 + bcol] = cvt4(rb[i]);
        }
        __syncthreads();

        // prefetch next tile
        if (k0 + 16 < K) {
            const int kn = k0 + 16;
            #pragma unroll
            for (int i = 0; i < 2; i++) {
                int m = m0 + arow + i * 64;
                ra[i] = (m < M) ? *(const float4*)(A + (size_t)m * lda + kn + acol)
                                : make_float4(0.f, 0.f, 0.f, 0.f);
            }
            if (TRANSB) {
                #pragma unroll
                for (int i = 0; i < 2; i++) {
                    int n = n0 + arow + i * 64;
                    rb[i] = (n < N) ? *(const float4*)(B + (size_t)n * ldb + kn + acol)
                                    : make_float4(0.f, 0.f, 0.f, 0.f);
                }
            } else {
                #pragma unroll
                for (int i = 0; i < 2; i++) {
                    int n = n0 + bcol;
                    rb[i] = (n < N) ? *(const float4*)(B + (size_t)(kn + brow + i * 8) * ldb + n)
                                    : make_float4(0.f, 0.f, 0.f, 0.f);
                }
            }
        }

        // compute 16 k in two k8 steps
        #pragma unroll
        for (int kk = 0; kk < 16; kk += 8) {
            unsigned af[4][4], bf[4][2];
            #pragma unroll
            for (int im = 0; im < 4; im++) {
                const int mb = wm + im * 16;
                af[im][0] = As[(mb + lr) * 20 + kk + lc];
                af[im][1] = As[(mb + 8 + lr) * 20 + kk + lc];
                af[im][2] = As[(mb + lr) * 20 + kk + 4 + lc];
                af[im][3] = As[(mb + 8 + lr) * 20 + kk + 4 + lc];
            }
            #pragma unroll
            for (int in = 0; in < 4; in++) {
                const int nb = wn + in * 8;
                if (TRANSB) {
                    bf[in][0] = Bs[(nb + lr) * 20 + kk + lc];
                    bf[in][1] = Bs[(nb + lr) * 20 + kk + 4 + lc];
                } else {
                    bf[in][0] = Bs[(kk + lc) * 136 + nb + lr];
                    bf[in][1] = Bs[(kk + 4 + lc) * 136 + nb + lr];
                }
            }
            #pragma unroll
            for (int im = 0; im < 4; im++)
                #pragma unroll
                for (int in = 0; in < 4; in++)
                    mma_tf32(acc[im * 4 + in], af[im], bf[in]);
        }
        __syncthreads();
    }

    // ---------------- epilogue ----------------
    #pragma unroll
    for (int im = 0; im < 4; im++) {
        const int r0 = m0 + wm + im * 16 + lr;
        const int r1 = r0 + 8;
        #pragma unroll
        for (int in = 0; in < 4; in++) {
            const int cb = n0 + wn + in * 8 + 2 * lc;
            if (cb >= N) continue;
            const float* ac = acc[im * 4 + in];
            float b0 = 0.f, b1 = 0.f;
            if (epi != 0) { b0 = bias[cb]; b1 = bias[cb + 1]; }
            // row r0
            if (r0 < M) {
                float v0 = alpha * ac[0], v1 = alpha * ac[1];
                if (epi == 1) { v0 = gelu_exact(v0 + b0); v1 = gelu_exact(v1 + b1); }
                else if (epi == 2) {
                    const float2 rv = *(const float2*)(resid + (size_t)r0 * ldr + cb);
                    v0 += b0 + rv.x; v1 += b1 + rv.y;
                }
                *(float2*)(C + (size_t)r0 * ldc + cb) = make_float2(v0, v1);
            }
            // row r1
            if (r1 < M) {
                float v0 = alpha * ac[2], v1 = alpha * ac[3];
                if (epi == 1) { v0 = gelu_exact(v0 + b0); v1 = gelu_exact(v1 + b1); }
                else if (epi == 2) {
                    const float2 rv = *(const float2*)(resid + (size_t)r1 * ldr + cb);
                    v0 += b0 + rv.x; v1 += b1 + rv.y;
                }
                *(float2*)(C + (size_t)r1 * ldc + cb) = make_float2(v0, v1);
            }
        }
    }
}

// ---------------- host launch ----------------
static inline dim3 gemm_grid(int M, int N, int Z)
{
    return dim3((N + 127) / 128, (M + 127) / 128, Z);
}

extern "C" void kernel_launch(void* const* d_in, const int* in_sizes, int n_in,
                              void* d_out, int out_size)
{
    const float* X      = (const float*)d_in[0];
    const float* WQ     = (const float*)d_in[1];
    const float* WK     = (const float*)d_in[2];
    const float* WV     = (const float*)d_in[3];
    const float* WO     = (const float*)d_in[4];
    const float* attn_g = (const float*)d_in[5];
    const float* attn_b = (const float*)d_in[6];
    const float* ff_g   = (const float*)d_in[7];
    const float* ff_b   = (const float*)d_in[8];
    const float* fW1    = (const float*)d_in[9];
    const float* fb1    = (const float*)d_in[10];
    const float* fW2    = (const float*)d_in[11];
    const float* fb2    = (const float*)d_in[12];
    float* out0 = (float*)d_out;

    float *nX, *QKV, *nv, *seq, *preff, *hidden, *Wt, *Sfb;
    cudaGetSymbolAddress((void**)&nX,     g_nX);
    cudaGetSymbolAddress((void**)&QKV,    g_QKV);
    cudaGetSymbolAddress((void**)&nv,     g_nv);
    cudaGetSymbolAddress((void**)&seq,    g_seq);
    cudaGetSymbolAddress((void**)&preff,  g_preff);
    cudaGetSymbolAddress((void**)&hidden, g_hidden);
    cudaGetSymbolAddress((void**)&Wt,     g_Wt);
    cudaGetSymbolAddress((void**)&Sfb,    g_Sfb);

    const long long xel     = (long long)BT * DIM;                 // 8,388,608
    const long long attn_el = (long long)BB * NH * TT * TT;        // 268,435,456
    float* attn = ((long long)out_size >= xel + attn_el) ? (out0 + xel) : Sfb;

    // 1) nX = LN(X)
    ln_kernel<<<BT, 256>>>(X, attn_g, attn_b, nullptr, nX);

    // 2) permute weights (H,D,P) -> columns of (D, 3D)
    wtrans_kernel<<<(DIM * DIM + 255) / 256, 256>>>(WQ, Wt, 0);
    wtrans_kernel<<<(DIM * DIM + 255) / 256, 256>>>(WK, Wt, DIM);
    wtrans_kernel<<<(DIM * DIM + 255) / 256, 256>>>(WV, Wt, 2 * DIM);

    // 3) QKV = nX @ Wt   (8192 x 3072 x 1024)
    tgemm_kernel<false><<<gemm_grid(BT, D3, 1), 256>>>(
        BT, D3, DIM, nX, DIM, 0, 0, Wt, D3, 0, 0,
        QKV, D3, 0, 0, 1, 1.0f, 0, nullptr, nullptr, 0);

    // 4) scores: S[b,h,q,k] = (1/8) * sum_p K[b,q,h,p] * Q[b,k,h,p]   (NT, batched)
    tgemm_kernel<true><<<gemm_grid(TT, TT, BB * NH), 256>>>(
        TT, TT, HP,
        QKV + DIM, D3, (long long)TT * D3, HP,      // K proj
        QKV,       D3, (long long)TT * D3, HP,      // Q proj
        attn, TT, (long long)NH * TT * TT, (long long)TT * TT,
        NH, 0.125f, 0, nullptr, nullptr, 0);

    // 5) softmax over k, in place
    softmax_kernel<<<BB * NH * TT, 256>>>(attn);

    // 6) AV: nv[b,q,h,p] = sum_k attn[b,h,q,k] * V[b,k,h,p]
    tgemm_kernel<false><<<gemm_grid(TT, HP, BB * NH), 256>>>(
        TT, HP, TT,
        attn, TT, (long long)NH * TT * TT, (long long)TT * TT,
        QKV + 2 * DIM, D3, (long long)TT * D3, HP,  // V proj
        nv, DIM, (long long)TT * DIM, HP,
        NH, 1.0f, 0, nullptr, nullptr, 0);

    // 7) seq = nv @ WO
    tgemm_kernel<false><<<gemm_grid(BT, DIM, 1), 256>>>(
        BT, DIM, DIM, nv, DIM, 0, 0, WO, DIM, 0, 0,
        seq, DIM, 0, 0, 1, 1.0f, 0, nullptr, nullptr, 0);

    // 8) pre_ff = X + LN(seq)
    ln_kernel<<<BT, 256>>>(seq, ff_g, ff_b, X, preff);

    // 9) hidden = gelu(pre_ff @ fW1 + fb1)
    tgemm_kernel<false><<<gemm_grid(BT, FFD, 1), 256>>>(
        BT, FFD, DIM, preff, DIM, 0, 0, fW1, FFD, 0, 0,
        hidden, FFD, 0, 0, 1, 1.0f, 1, fb1, nullptr, 0);

    // 10) out = hidden @ fW2 + fb2 + pre_ff
    tgemm_kernel<false><<<gemm_grid(BT, DIM, 1), 256>>>(
        BT, DIM, FFD, hidden, FFD, 0, 0, fW2, DIM, 0, 0,
        out0, DIM, 0, 0, 1, 1.0f, 2, fb2, preff, DIM);
}

// round 3
// speedup vs baseline: 3.2224x; 1.2537x over previous
#include <cuda_runtime.h>
#include <math.h>
#include <stdint.h>

#define BB    4
#define TT    2048
#define DIM   1024
#define NH    16
#define HP    64
#define FFD   4096
#define BT    (BB*TT)          // 8192
#define D3    (3*DIM)          // 3072

// ---------------- scratch (static device globals; no runtime allocs) ----------------
__device__ float g_nX[(size_t)BT*DIM];
__device__ float g_QKV[(size_t)BT*D3];
__device__ float g_nv[(size_t)BT*DIM];
__device__ float g_seq[(size_t)BT*DIM];
__device__ float g_preff[(size_t)BT*DIM];
__device__ float g_hidden[(size_t)BT*FFD];
__device__ float g_Wt[(size_t)DIM*D3];             // permuted WQ|WK|WV  [D][3D]
__device__ float g_Sfb[(size_t)BB*NH*TT*TT];       // attn fallback if d_out lacks room

// ---------------- layernorm (optionally + residual) ----------------
__global__ void ln_kernel(const float* __restrict__ x,
                          const float* __restrict__ g,
                          const float* __restrict__ b,
                          const float* __restrict__ resid,
                          float* __restrict__ out)
{
    const size_t row = blockIdx.x;
    const float4* xr = (const float4*)(x + row * (size_t)DIM);
    const int tid = threadIdx.x;                 // 256 threads, 1 float4 each
    float4 xv = xr[tid];

    float s  = xv.x + xv.y + xv.z + xv.w;
    float ss = xv.x*xv.x + xv.y*xv.y + xv.z*xv.z + xv.w*xv.w;

    #pragma unroll
    for (int o = 16; o > 0; o >>= 1) {
        s  += __shfl_xor_sync(0xffffffffu, s,  o);
        ss += __shfl_xor_sync(0xffffffffu, ss, o);
    }
    __shared__ float rs[8], rss[8];
    int wid = tid >> 5, lane = tid & 31;
    if (lane == 0) { rs[wid] = s; rss[wid] = ss; }
    __syncthreads();
    __shared__ float s_mean, s_rstd;
    if (tid == 0) {
        float ts = 0.f, tss = 0.f;
        #pragma unroll
        for (int i = 0; i < 8; i++) { ts += rs[i]; tss += rss[i]; }
        float mean = ts * (1.0f / DIM);
        float var  = tss * (1.0f / DIM) - mean * mean;
        s_mean = mean;
        s_rstd = rsqrtf(var + 1e-5f);
    }
    __syncthreads();
    const float mean = s_mean, rstd = s_rstd;

    const float4 gv = ((const float4*)g)[tid];
    const float4 bv = ((const float4*)b)[tid];
    float4 o4;
    o4.x = (xv.x - mean) * rstd * gv.x + bv.x;
    o4.y = (xv.y - mean) * rstd * gv.y + bv.y;
    o4.z = (xv.z - mean) * rstd * gv.z + bv.z;
    o4.w = (xv.w - mean) * rstd * gv.w + bv.w;
    if (resid) {
        const float4 rv = ((const float4*)(resid + row * (size_t)DIM))[tid];
        o4.x += rv.x; o4.y += rv.y; o4.z += rv.z; o4.w += rv.w;
    }
    ((float4*)(out + row * (size_t)DIM))[tid] = o4;
}

// ---------------- permute (H,D,P) -> column block of (D, 3D) ----------------
__global__ void wtrans_kernel(const float* __restrict__ w, float* __restrict__ o, int coloff)
{
    int idx = blockIdx.x * blockDim.x + threadIdx.x;     // over DIM*DIM = 1M
    if (idx >= DIM * DIM) return;
    int p = idx & 63;
    int d = (idx >> 6) & 1023;
    int h = idx >> 16;
    o[(size_t)d * D3 + coloff + h * HP + p] = w[idx];
}

// ---------------- in-place row softmax over 2048 ----------------
__global__ void softmax_kernel(float* __restrict__ a)
{
    const size_t row = blockIdx.x;
    float4* p4 = (float4*)(a + row * (size_t)TT);
    const int tid = threadIdx.x;                  // 256 threads * 2 float4 = 2048
    float4 v0 = p4[tid], v1 = p4[tid + 256];

    float mx = fmaxf(fmaxf(fmaxf(v0.x, v0.y), fmaxf(v0.z, v0.w)),
                     fmaxf(fmaxf(v1.x, v1.y), fmaxf(v1.z, v1.w)));
    #pragma unroll
    for (int o = 16; o > 0; o >>= 1) mx = fmaxf(mx, __shfl_xor_sync(0xffffffffu, mx, o));
    __shared__ float red[8];
    int wid = tid >> 5, lane = tid & 31;
    if (lane == 0) red[wid] = mx;
    __syncthreads();
    __shared__ float s_b;
    if (tid == 0) {
        float m = red[0];
        #pragma unroll
        for (int i = 1; i < 8; i++) m = fmaxf(m, red[i]);
        s_b = m;
    }
    __syncthreads();
    mx = s_b;

    v0.x = expf(v0.x - mx); v0.y = expf(v0.y - mx); v0.z = expf(v0.z - mx); v0.w = expf(v0.w - mx);
    v1.x = expf(v1.x - mx); v1.y = expf(v1.y - mx); v1.z = expf(v1.z - mx); v1.w = expf(v1.w - mx);
    float s = v0.x + v0.y + v0.z + v0.w + v1.x + v1.y + v1.z + v1.w;
    #pragma unroll
    for (int o = 16; o > 0; o >>= 1) s += __shfl_xor_sync(0xffffffffu, s, o);
    if (lane == 0) red[wid] = s;
    __syncthreads();
    if (tid == 0) {
        float t = 0.f;
        #pragma unroll
        for (int i = 0; i < 8; i++) t += red[i];
        s_b = 1.0f / t;
    }
    __syncthreads();
    const float inv = s_b;
    v0.x *= inv; v0.y *= inv; v0.z *= inv; v0.w *= inv;
    v1.x *= inv; v1.y *= inv; v1.z *= inv; v1.w *= inv;
    p4[tid] = v0; p4[tid + 256] = v1;
}

// ---------------- TF32 tensor-core batched GEMM, cp.async 3-stage ----------------
// C[m,n] = alpha * sum_k A[m,k] * (TRANSB ? B[n,k] : B[k,n])   (+ epilogue)
// epi: 0 none, 1 gelu(x + bias[n]), 2 x + bias[n] + resid[m*ldr+n]
// tile 128 x BN x 16, 256 thr. REQUIRES: M%128==0, N%BN==0, K%16==0.

__device__ __forceinline__ float gelu_exact(float x)
{
    return 0.5f * x * (1.0f + erff(x * 0.70710678118654752440f));
}

__device__ __forceinline__ unsigned f2tf(float x)
{
    unsigned r;
    asm("cvt.rna.tf32.f32 %0, %1;" : "=r"(r) : "f"(x));
    return r;
}

__device__ __forceinline__ void cpa16(void* dst, const void* src)
{
    uint32_t d = (uint32_t)__cvta_generic_to_shared(dst);
    asm volatile("cp.async.cg.shared.global [%0], [%1], 16;" :: "r"(d), "l"(src));
}

__device__ __forceinline__ void cpa_commit() { asm volatile("cp.async.commit_group;"); }

template<int N>
__device__ __forceinline__ void cpa_wait() { asm volatile("cp.async.wait_group %0;" :: "n"(N)); }

__device__ __forceinline__ void mma_tf32(float c[4], const unsigned a[4], const unsigned b[2])
{
    asm volatile(
        "mma.sync.aligned.m16n8k8.row.col.f32.tf32.tf32.f32 "
        "{%0,%1,%2,%3}, {%4,%5,%6,%7}, {%8,%9}, {%0,%1,%2,%3};"
        : "+f"(c[0]), "+f"(c[1]), "+f"(c[2]), "+f"(c[3])
        : "r"(a[0]), "r"(a[1]), "r"(a[2]), "r"(a[3]), "r"(b[0]), "r"(b[1]));
}

template<int BN, bool TRANSB>
__global__ __launch_bounds__(256, 2) void tgemm_kernel(
    int M, int N, int K,
    const float* __restrict__ A, int lda, long long sAb, long long sAh,
    const float* __restrict__ B, int ldb, long long sBb, long long sBh,
    float* __restrict__ C, int ldc, long long sCb, long long sCh,
    int nh, float alpha, int epi,
    const float* __restrict__ bias,
    const float* __restrict__ resid, int ldr)
{
    constexpr int STAGES  = 3;
    constexpr int A_STAGE = 128 * 20;                                     // floats
    constexpr int B_LD    = TRANSB ? 20 : (BN + 8);
    constexpr int B_STAGE = TRANSB ? (BN * 20) : (16 * (BN + 8));         // floats
    constexpr int WARPS_M = (BN == 128) ? 2 : 4;
    constexpr int WARPS_N = 8 / WARPS_M;
    constexpr int WM      = 128 / WARPS_M;       // 64 or 32
    constexpr int WN      = BN / WARPS_N;        // 32
    constexpr int IM      = WM / 16;             // 4 or 2
    constexpr int IN      = WN / 8;              // 4

    extern __shared__ float smem[];
    float* Asm = smem;
    float* Bsm = smem + STAGES * A_STAGE;

    const int z = blockIdx.z;
    const int bb = z / nh, hh = z % nh;
    A += (size_t)bb * sAb + (size_t)hh * sAh;
    B += (size_t)bb * sBb + (size_t)hh * sBh;
    C += (size_t)bb * sCb + (size_t)hh * sCh;

    const int tid  = threadIdx.x;
    const int m0   = blockIdx.y * 128;
    const int n0   = blockIdx.x * BN;
    const int w    = tid >> 5, lane = tid & 31;
    const int lr   = lane >> 2, lc = lane & 3;
    const int wm   = (w % WARPS_M) * WM;
    const int wn   = (w / WARPS_M) * WN;

    // global->smem load mappings (no bounds checks: shapes are exact multiples)
    const int arow = tid >> 2;           // 0..63
    const int acol = (tid & 3) * 4;      // 0,4,8,12
    const int brow = tid >> 5;           // 0..7     (notrans, BN=128)
    const int bcol = (tid & 31) * 4;     // 0..124
    const int crow = tid >> 4;           // 0..15    (notrans, BN=64)
    const int ccol = (tid & 15) * 4;     // 0..60

    float acc[IM][IN][4];
    #pragma unroll
    for (int i = 0; i < IM; i++)
        #pragma unroll
        for (int j = 0; j < IN; j++)
            #pragma unroll
            for (int q = 0; q < 4; q++) acc[i][j][q] = 0.f;

    auto load_stage = [&](int st, int k0) {
        float* as = Asm + st * A_STAGE;
        #pragma unroll
        for (int i = 0; i < 2; i++) {
            int m = arow + i * 64;
            cpa16(&as[m * 20 + acol], A + (size_t)(m0 + m) * lda + k0 + acol);
        }
        float* bs = Bsm + st * B_STAGE;
        if (TRANSB) {
            #pragma unroll
            for (int i = 0; i < 2; i++) {
                int n = arow + i * 64;
                cpa16(&bs[n * 20 + acol], B + (size_t)(n0 + n) * ldb + k0 + acol);
            }
        } else if (BN == 128) {
            #pragma unroll
            for (int i = 0; i < 2; i++) {
                int kk = brow + i * 8;
                cpa16(&bs[kk * B_LD + bcol], B + (size_t)(k0 + kk) * ldb + n0 + bcol);
            }
        } else {
            cpa16(&bs[crow * B_LD + ccol], B + (size_t)(k0 + crow) * ldb + n0 + ccol);
        }
    };

    const int kiters = K >> 4;

    // prologue: stages 0..STAGES-2
    #pragma unroll
    for (int s = 0; s < STAGES - 1; s++) { load_stage(s, s * 16); cpa_commit(); }

    for (int it = 0; it < kiters; it++) {
        cpa_wait<STAGES - 2>();
        __syncthreads();

        const int nxt = it + STAGES - 1;
        if (nxt < kiters) load_stage(nxt % STAGES, nxt * 16);
        cpa_commit();

        const float* as = Asm + (it % STAGES) * A_STAGE;
        const float* bs = Bsm + (it % STAGES) * B_STAGE;

        #pragma unroll
        for (int kk = 0; kk < 16; kk += 8) {
            unsigned af[IM][4], bf[IN][2];
            #pragma unroll
            for (int im = 0; im < IM; im++) {
                const int mb = wm + im * 16;
                af[im][0] = f2tf(as[(mb + lr) * 20 + kk + lc]);
                af[im][1] = f2tf(as[(mb + 8 + lr) * 20 + kk + lc]);
                af[im][2] = f2tf(as[(mb + lr) * 20 + kk + 4 + lc]);
                af[im][3] = f2tf(as[(mb + 8 + lr) * 20 + kk + 4 + lc]);
            }
            #pragma unroll
            for (int in = 0; in < IN; in++) {
                const int nb = wn + in * 8;
                if (TRANSB) {
                    bf[in][0] = f2tf(bs[(nb + lr) * 20 + kk + lc]);
                    bf[in][1] = f2tf(bs[(nb + lr) * 20 + kk + 4 + lc]);
                } else {
                    bf[in][0] = f2tf(bs[(kk + lc) * B_LD + nb + lr]);
                    bf[in][1] = f2tf(bs[(kk + 4 + lc) * B_LD + nb + lr]);
                }
            }
            #pragma unroll
            for (int im = 0; im < IM; im++)
                #pragma unroll
                for (int in = 0; in < IN; in++)
                    mma_tf32(acc[im][in], af[im], bf[in]);
        }
    }

    // ---------------- epilogue ----------------
    #pragma unroll
    for (int im = 0; im < IM; im++) {
        const int r0 = m0 + wm + im * 16 + lr;
        const int r1 = r0 + 8;
        #pragma unroll
        for (int in = 0; in < IN; in++) {
            const int cb = n0 + wn + in * 8 + 2 * lc;
            const float* ac = acc[im][in];
            float b0 = 0.f, b1 = 0.f;
            if (epi != 0) { b0 = bias[cb]; b1 = bias[cb + 1]; }
            {
                float v0 = alpha * ac[0], v1 = alpha * ac[1];
                if (epi == 1) { v0 = gelu_exact(v0 + b0); v1 = gelu_exact(v1 + b1); }
                else if (epi == 2) {
                    const float2 rv = *(const float2*)(resid + (size_t)r0 * ldr + cb);
                    v0 += b0 + rv.x; v1 += b1 + rv.y;
                }
                *(float2*)(C + (size_t)r0 * ldc + cb) = make_float2(v0, v1);
            }
            {
                float v0 = alpha * ac[2], v1 = alpha * ac[3];
                if (epi == 1) { v0 = gelu_exact(v0 + b0); v1 = gelu_exact(v1 + b1); }
                else if (epi == 2) {
                    const float2 rv = *(const float2*)(resid + (size_t)r1 * ldr + cb);
                    v0 += b0 + rv.x; v1 += b1 + rv.y;
                }
                *(float2*)(C + (size_t)r1 * ldc + cb) = make_float2(v0, v1);
            }
        }
    }
}

// smem sizes (bytes) for each instantiation
#define SMEM_NT128 (3 * (128*20 + 16*136) * 4)   // 56832
#define SMEM_T128  (3 * (128*20 + 128*20) * 4)   // 61440
#define SMEM_NT64  (3 * (128*20 + 16*72)  * 4)   // 44544

// ---------------- host launch ----------------
static inline dim3 gemm_grid(int M, int N, int BN, int Z)
{
    return dim3(N / BN, M / 128, Z);
}

extern "C" void kernel_launch(void* const* d_in, const int* in_sizes, int n_in,
                              void* d_out, int out_size)
{
    const float* X      = (const float*)d_in[0];
    const float* WQ     = (const float*)d_in[1];
    const float* WK     = (const float*)d_in[2];
    const float* WV     = (const float*)d_in[3];
    const float* WO     = (const float*)d_in[4];
    const float* attn_g = (const float*)d_in[5];
    const float* attn_b = (const float*)d_in[6];
    const float* ff_g   = (const float*)d_in[7];
    const float* ff_b   = (const float*)d_in[8];
    const float* fW1    = (const float*)d_in[9];
    const float* fb1    = (const float*)d_in[10];
    const float* fW2    = (const float*)d_in[11];
    const float* fb2    = (const float*)d_in[12];
    float* out0 = (float*)d_out;

    float *nX, *QKV, *nv, *seq, *preff, *hidden, *Wt, *Sfb;
    cudaGetSymbolAddress((void**)&nX,     g_nX);
    cudaGetSymbolAddress((void**)&QKV,    g_QKV);
    cudaGetSymbolAddress((void**)&nv,     g_nv);
    cudaGetSymbolAddress((void**)&seq,    g_seq);
    cudaGetSymbolAddress((void**)&preff,  g_preff);
    cudaGetSymbolAddress((void**)&hidden, g_hidden);
    cudaGetSymbolAddress((void**)&Wt,     g_Wt);
    cudaGetSymbolAddress((void**)&Sfb,    g_Sfb);

    cudaFuncSetAttribute(tgemm_kernel<128, false>,
                         cudaFuncAttributeMaxDynamicSharedMemorySize, SMEM_NT128);
    cudaFuncSetAttribute(tgemm_kernel<128, true>,
                         cudaFuncAttributeMaxDynamicSharedMemorySize, SMEM_T128);
    cudaFuncSetAttribute(tgemm_kernel<64, false>,
                         cudaFuncAttributeMaxDynamicSharedMemorySize, SMEM_NT64);

    const long long xel     = (long long)BT * DIM;                 // 8,388,608
    const long long attn_el = (long long)BB * NH * TT * TT;        // 268,435,456
    float* attn = ((long long)out_size >= xel + attn_el) ? (out0 + xel) : Sfb;

    // 1) nX = LN(X)
    ln_kernel<<<BT, 256>>>(X, attn_g, attn_b, nullptr, nX);

    // 2) permute weights (H,D,P) -> columns of (D, 3D)
    wtrans_kernel<<<(DIM * DIM + 255) / 256, 256>>>(WQ, Wt, 0);
    wtrans_kernel<<<(DIM * DIM + 255) / 256, 256>>>(WK, Wt, DIM);
    wtrans_kernel<<<(DIM * DIM + 255) / 256, 256>>>(WV, Wt, 2 * DIM);

    // 3) QKV = nX @ Wt   (8192 x 3072 x 1024)
    tgemm_kernel<128, false><<<gemm_grid(BT, D3, 128, 1), 256, SMEM_NT128>>>(
        BT, D3, DIM, nX, DIM, 0, 0, Wt, D3, 0, 0,
        QKV, D3, 0, 0, 1, 1.0f, 0, nullptr, nullptr, 0);

    // 4) scores: S[b,h,q,k] = (1/8) * sum_p K[b,q,h,p] * Q[b,k,h,p]   (NT, batched)
    tgemm_kernel<128, true><<<gemm_grid(TT, TT, 128, BB * NH), 256, SMEM_T128>>>(
        TT, TT, HP,
        QKV + DIM, D3, (long long)TT * D3, HP,      // K proj
        QKV,       D3, (long long)TT * D3, HP,      // Q proj
        attn, TT, (long long)NH * TT * TT, (long long)TT * TT,
        NH, 0.125f, 0, nullptr, nullptr, 0);

    // 5) softmax over k, in place
    softmax_kernel<<<BB * NH * TT, 256>>>(attn);

    // 6) AV: nv[b,q,h,p] = sum_k attn[b,h,q,k] * V[b,k,h,p]   (BN=64, exact fit)
    tgemm_kernel<64, false><<<gemm_grid(TT, HP, 64, BB * NH), 256, SMEM_NT64>>>(
        TT, HP, TT,
        attn, TT, (long long)NH * TT * TT, (long long)TT * TT,
        QKV + 2 * DIM, D3, (long long)TT * D3, HP,  // V proj
        nv, DIM, (long long)TT * DIM, HP,
        NH, 1.0f, 0, nullptr, nullptr, 0);

    // 7) seq = nv @ WO
    tgemm_kernel<128, false><<<gemm_grid(BT, DIM, 128, 1), 256, SMEM_NT128>>>(
        BT, DIM, DIM, nv, DIM, 0, 0, WO, DIM, 0, 0,
        seq, DIM, 0, 0, 1, 1.0f, 0, nullptr, nullptr, 0);

    // 8) pre_ff = X + LN(seq)
    ln_kernel<<<BT, 256>>>(seq, ff_g, ff_b, X, preff);

    // 9) hidden = gelu(pre_ff @ fW1 + fb1)
    tgemm_kernel<128, false><<<gemm_grid(BT, FFD, 128, 1), 256, SMEM_NT128>>>(
        BT, FFD, DIM, preff, DIM, 0, 0, fW1, FFD, 0, 0,
        hidden, FFD, 0, 0, 1, 1.0f, 1, fb1, nullptr, 0);

    // 10) out = hidden @ fW2 + fb2 + pre_ff
    tgemm_kernel<128, false><<<gemm_grid(BT, DIM, 128, 1), 256, SMEM_NT128>>>(
        BT, DIM, FFD, hidden, FFD, 0, 0, fW2, DIM, 0, 0,
        out0, DIM, 0, 0, 1, 1.0f, 2, fb2, preff, DIM);
}

// round 4
// speedup vs baseline: 3.2533x; 1.0096x over previous
#include <cuda_runtime.h>
#include <math.h>
#include <stdint.h>

#define BB    4
#define TT    2048
#define DIM   1024
#define NH    16
#define HP    64
#define FFD   4096
#define BT    (BB*TT)          // 8192
#define D3    (3*DIM)          // 3072
#define NZ    (BB*NH)          // 64 batch-heads
#define ROWS_ALL (NZ*TT)       // 131072
#define KTILES (TT/128)        // 16

// ---------------- scratch ----------------
__device__ float g_nX[(size_t)BT*DIM];
__device__ float g_QKV[(size_t)BT*D3];
__device__ float g_nv[(size_t)BT*DIM];
__device__ float g_seq[(size_t)BT*DIM];
__device__ float g_preff[(size_t)BT*DIM];
__device__ float g_preff_r[(size_t)BT*DIM];
__device__ float g_hidden[(size_t)BT*FFD];
__device__ float g_Wt[(size_t)DIM*D3];
__device__ float g_WOr[(size_t)DIM*DIM];
__device__ float g_fW1r[(size_t)DIM*FFD];
__device__ float g_fW2r[(size_t)FFD*DIM];
__device__ float g_part[(size_t)ROWS_ALL*KTILES];
__device__ float g_inv[(size_t)ROWS_ALL];
__device__ float g_Sfb[(size_t)NZ*TT*TT];

// ---------------- helpers ----------------
__device__ __forceinline__ unsigned f2tf(float x)
{
    unsigned r;
    asm("cvt.rna.tf32.f32 %0, %1;" : "=r"(r) : "f"(x));
    return r;
}
__device__ __forceinline__ float roundtf(float x) { return __uint_as_float(f2tf(x)); }

__device__ __forceinline__ float gelu_exact(float x)
{
    return 0.5f * x * (1.0f + erff(x * 0.70710678118654752440f));
}

__device__ __forceinline__ void cpa16(void* dst, const void* src)
{
    uint32_t d = (uint32_t)__cvta_generic_to_shared(dst);
    asm volatile("cp.async.cg.shared.global [%0], [%1], 16;" :: "r"(d), "l"(src));
}
__device__ __forceinline__ void cpa_commit() { asm volatile("cp.async.commit_group;"); }
template<int N>
__device__ __forceinline__ void cpa_wait() { asm volatile("cp.async.wait_group %0;" :: "n"(N)); }

__device__ __forceinline__ void mma_tf32(float c[4], const unsigned a[4], const unsigned b[2])
{
    asm volatile(
        "mma.sync.aligned.m16n8k8.row.col.f32.tf32.tf32.f32 "
        "{%0,%1,%2,%3}, {%4,%5,%6,%7}, {%8,%9}, {%0,%1,%2,%3};"
        : "+f"(c[0]), "+f"(c[1]), "+f"(c[2]), "+f"(c[3])
        : "r"(a[0]), "r"(a[1]), "r"(a[2]), "r"(a[3]), "r"(b[0]), "r"(b[1]));
}

// ---------------- layernorm: out (exact or rounded) and optional rounded copy ----------------
__global__ void ln_kernel(const float* __restrict__ x,
                          const float* __restrict__ g,
                          const float* __restrict__ b,
                          const float* __restrict__ resid,
                          float* __restrict__ out,
                          float* __restrict__ out_r,
                          int round_main)
{
    const size_t row = blockIdx.x;
    const float4* xr = (const float4*)(x + row * (size_t)DIM);
    const int tid = threadIdx.x;                 // 256 threads, 1 float4 each
    float4 xv = xr[tid];

    float s  = xv.x + xv.y + xv.z + xv.w;
    float ss = xv.x*xv.x + xv.y*xv.y + xv.z*xv.z + xv.w*xv.w;

    #pragma unroll
    for (int o = 16; o > 0; o >>= 1) {
        s  += __shfl_xor_sync(0xffffffffu, s,  o);
        ss += __shfl_xor_sync(0xffffffffu, ss, o);
    }
    __shared__ float rs[8], rss[8];
    int wid = tid >> 5, lane = tid & 31;
    if (lane == 0) { rs[wid] = s; rss[wid] = ss; }
    __syncthreads();
    __shared__ float s_mean, s_rstd;
    if (tid == 0) {
        float ts = 0.f, tss = 0.f;
        #pragma unroll
        for (int i = 0; i < 8; i++) { ts += rs[i]; tss += rss[i]; }
        float mean = ts * (1.0f / DIM);
        float var  = tss * (1.0f / DIM) - mean * mean;
        s_mean = mean;
        s_rstd = rsqrtf(var + 1e-5f);
    }
    __syncthreads();
    const float mean = s_mean, rstd = s_rstd;

    const float4 gv = ((const float4*)g)[tid];
    const float4 bv = ((const float4*)b)[tid];
    float4 o4;
    o4.x = (xv.x - mean) * rstd * gv.x + bv.x;
    o4.y = (xv.y - mean) * rstd * gv.y + bv.y;
    o4.z = (xv.z - mean) * rstd * gv.z + bv.z;
    o4.w = (xv.w - mean) * rstd * gv.w + bv.w;
    if (resid) {
        const float4 rv = ((const float4*)(resid + row * (size_t)DIM))[tid];
        o4.x += rv.x; o4.y += rv.y; o4.z += rv.z; o4.w += rv.w;
    }
    float4 om = o4;
    if (round_main) {
        om.x = roundtf(o4.x); om.y = roundtf(o4.y);
        om.z = roundtf(o4.z); om.w = roundtf(o4.w);
    }
    ((float4*)(out + row * (size_t)DIM))[tid] = om;
    if (out_r) {
        float4 orr;
        orr.x = roundtf(o4.x); orr.y = roundtf(o4.y);
        orr.z = roundtf(o4.z); orr.w = roundtf(o4.w);
        ((float4*)(out_r + row * (size_t)DIM))[tid] = orr;
    }
}

// ---------------- permute (H,D,P) -> column block of (D, 3D), tf32-rounded ----------------
__global__ void wtrans_kernel(const float* __restrict__ w, float* __restrict__ o, int coloff)
{
    int idx = blockIdx.x * blockDim.x + threadIdx.x;
    if (idx >= DIM * DIM) return;
    int p = idx & 63;
    int d = (idx >> 6) & 1023;
    int h = idx >> 16;
    o[(size_t)d * D3 + coloff + h * HP + p] = roundtf(w[idx]);
}

// ---------------- elementwise tf32 round (weights) ----------------
__global__ void round_kernel(const float* __restrict__ src, float* __restrict__ dst, int n4)
{
    int idx = blockIdx.x * blockDim.x + threadIdx.x;
    if (idx >= n4) return;
    float4 v = ((const float4*)src)[idx];
    v.x = roundtf(v.x); v.y = roundtf(v.y); v.z = roundtf(v.z); v.w = roundtf(v.w);
    ((float4*)dst)[idx] = v;
}

// ---------------- rowsum -> inverse ----------------
__global__ void rowinv_kernel(const float* __restrict__ part, float* __restrict__ inv)
{
    int idx = blockIdx.x * blockDim.x + threadIdx.x;
    if (idx >= ROWS_ALL) return;
    const float4* p = (const float4*)(part + (size_t)idx * KTILES);
    float s = 0.f;
    #pragma unroll
    for (int i = 0; i < KTILES / 4; i++) {
        float4 v = p[i];
        s += v.x + v.y + v.z + v.w;
    }
    inv[idx] = 1.0f / s;
}

// ================= dense GEMM (NT, 128x128x16, 3-stage, pre-rounded inputs) =================
// C[m,n] = sum_k A[m,k]*B[k,n]  (+ epilogue)   epi: 0 none, 1 gelu+bias, 2 bias+resid
#define DG_ASTAGE (128*20)
#define DG_BSTAGE (16*136)
#define SMEM_DENSE (3 * (DG_ASTAGE + DG_BSTAGE) * 4)

__global__ __launch_bounds__(256, 2) void dense_gemm(
    int M, int N, int K,
    const float* __restrict__ A, int lda,
    const float* __restrict__ B, int ldb,
    float* __restrict__ C, int ldc,
    int epi, const float* __restrict__ bias,
    const float* __restrict__ resid, int ldr, int round_out)
{
    extern __shared__ float smem[];
    float* Asm = smem;
    float* Bsm = smem + 3 * DG_ASTAGE;

    const int tid  = threadIdx.x;
    const int m0   = blockIdx.y * 128;
    const int n0   = blockIdx.x * 128;
    const int w    = tid >> 5, lane = tid & 31;
    const int lr   = lane >> 2, lc = lane & 3;
    const int wm   = (w & 1) * 64;       // WARPS_M=2
    const int wn   = (w >> 1) * 32;      // WARPS_N=4

    const int arow = tid >> 2;
    const int acol = (tid & 3) * 4;
    const int brow = tid >> 5;
    const int bcol = (tid & 31) * 4;

    float acc[4][4][4];
    #pragma unroll
    for (int i = 0; i < 4; i++)
        #pragma unroll
        for (int j = 0; j < 4; j++)
            #pragma unroll
            for (int q = 0; q < 4; q++) acc[i][j][q] = 0.f;

    auto load_stage = [&](int st, int k0) {
        float* as = Asm + st * DG_ASTAGE;
        #pragma unroll
        for (int i = 0; i < 2; i++) {
            int m = arow + i * 64;
            cpa16(&as[m * 20 + acol], A + (size_t)(m0 + m) * lda + k0 + acol);
        }
        float* bs = Bsm + st * DG_BSTAGE;
        #pragma unroll
        for (int i = 0; i < 2; i++) {
            int kk = brow + i * 8;
            cpa16(&bs[kk * 136 + bcol], B + (size_t)(k0 + kk) * ldb + n0 + bcol);
        }
    };

    const int kiters = K >> 4;
    #pragma unroll
    for (int s = 0; s < 2; s++) { load_stage(s, s * 16); cpa_commit(); }

    for (int it = 0; it < kiters; it++) {
        cpa_wait<1>();
        __syncthreads();

        const int nxt = it + 2;
        if (nxt < kiters) load_stage(nxt % 3, nxt * 16);
        cpa_commit();

        const float* as = Asm + (it % 3) * DG_ASTAGE;
        const float* bs = Bsm + (it % 3) * DG_BSTAGE;

        #pragma unroll
        for (int kk = 0; kk < 16; kk += 8) {
            unsigned af[4][4], bf[4][2];
            #pragma unroll
            for (int im = 0; im < 4; im++) {
                const int mb = wm + im * 16;
                af[im][0] = __float_as_uint(as[(mb + lr) * 20 + kk + lc]);
                af[im][1] = __float_as_uint(as[(mb + 8 + lr) * 20 + kk + lc]);
                af[im][2] = __float_as_uint(as[(mb + lr) * 20 + kk + 4 + lc]);
                af[im][3] = __float_as_uint(as[(mb + 8 + lr) * 20 + kk + 4 + lc]);
            }
            #pragma unroll
            for (int in = 0; in < 4; in++) {
                const int nb = wn + in * 8;
                bf[in][0] = __float_as_uint(bs[(kk + lc) * 136 + nb + lr]);
                bf[in][1] = __float_as_uint(bs[(kk + 4 + lc) * 136 + nb + lr]);
            }
            #pragma unroll
            for (int im = 0; im < 4; im++)
                #pragma unroll
                for (int in = 0; in < 4; in++)
                    mma_tf32(acc[im][in], af[im], bf[in]);
        }
    }

    #pragma unroll
    for (int im = 0; im < 4; im++) {
        const int r0 = m0 + wm + im * 16 + lr;
        const int r1 = r0 + 8;
        #pragma unroll
        for (int in = 0; in < 4; in++) {
            const int cb = n0 + wn + in * 8 + 2 * lc;
            const float* ac = acc[im][in];
            float b0 = 0.f, b1 = 0.f;
            if (epi != 0) { b0 = bias[cb]; b1 = bias[cb + 1]; }
            float v0 = ac[0], v1 = ac[1];
            if (epi == 1) { v0 = gelu_exact(v0 + b0); v1 = gelu_exact(v1 + b1); }
            else if (epi == 2) {
                const float2 rv = *(const float2*)(resid + (size_t)r0 * ldr + cb);
                v0 += b0 + rv.x; v1 += b1 + rv.y;
            }
            if (round_out) { v0 = roundtf(v0); v1 = roundtf(v1); }
            *(float2*)(C + (size_t)r0 * ldc + cb) = make_float2(v0, v1);

            float v2 = ac[2], v3 = ac[3];
            if (epi == 1) { v2 = gelu_exact(v2 + b0); v3 = gelu_exact(v3 + b1); }
            else if (epi == 2) {
                const float2 rv = *(const float2*)(resid + (size_t)r1 * ldr + cb);
                v2 += b0 + rv.x; v3 += b1 + rv.y;
            }
            if (round_out) { v2 = roundtf(v2); v3 = roundtf(v3); }
            *(float2*)(C + (size_t)r1 * ldc + cb) = make_float2(v2, v3);
        }
    }
}

// ================= scores kernel: p_un = exp(K.Q^T / 8), partial row sums =================
// A = K-proj rows (q), B = Q-proj rows (k), both pre-rounded. K-dim = HP = 64.
#define SC_ASTAGE (128*20)
#define SC_BSTAGE (128*20)
#define SMEM_SCORES (3 * (SC_ASTAGE + SC_BSTAGE) * 4)

__global__ __launch_bounds__(256, 2) void scores_kernel(
    const float* __restrict__ QKV, float* __restrict__ attn, float* __restrict__ part)
{
    extern __shared__ float smem[];
    float* Asm = smem;
    float* Bsm = smem + 3 * SC_ASTAGE;
    __shared__ float s_part[4][128];

    const int z  = blockIdx.z;
    const int bb = z >> 4, hh = z & 15;
    const float* A = QKV + DIM + (size_t)bb * TT * D3 + hh * HP;   // K proj
    const float* B = QKV +        (size_t)bb * TT * D3 + hh * HP;  // Q proj
    float* C = attn + (size_t)z * TT * TT;

    const int tid  = threadIdx.x;
    const int m0   = blockIdx.y * 128;
    const int n0   = blockIdx.x * 128;
    const int w    = tid >> 5, lane = tid & 31;
    const int lr   = lane >> 2, lc = lane & 3;
    const int wm   = (w & 1) * 64;
    const int wn   = (w >> 1) * 32;
    const int wni  = w >> 1;

    const int arow = tid >> 2;
    const int acol = (tid & 3) * 4;

    float acc[4][4][4];
    #pragma unroll
    for (int i = 0; i < 4; i++)
        #pragma unroll
        for (int j = 0; j < 4; j++)
            #pragma unroll
            for (int q = 0; q < 4; q++) acc[i][j][q] = 0.f;

    auto load_stage = [&](int st, int k0) {
        float* as = Asm + st * SC_ASTAGE;
        float* bs = Bsm + st * SC_BSTAGE;
        #pragma unroll
        for (int i = 0; i < 2; i++) {
            int r = arow + i * 64;
            cpa16(&as[r * 20 + acol], A + (size_t)(m0 + r) * D3 + k0 + acol);
            cpa16(&bs[r * 20 + acol], B + (size_t)(n0 + r) * D3 + k0 + acol);
        }
    };

    const int kiters = HP >> 4;   // 4
    #pragma unroll
    for (int s = 0; s < 2; s++) { load_stage(s, s * 16); cpa_commit(); }

    for (int it = 0; it < kiters; it++) {
        cpa_wait<1>();
        __syncthreads();
        const int nxt = it + 2;
        if (nxt < kiters) load_stage(nxt % 3, nxt * 16);
        cpa_commit();

        const float* as = Asm + (it % 3) * SC_ASTAGE;
        const float* bs = Bsm + (it % 3) * SC_BSTAGE;

        #pragma unroll
        for (int kk = 0; kk < 16; kk += 8) {
            unsigned af[4][4], bf[4][2];
            #pragma unroll
            for (int im = 0; im < 4; im++) {
                const int mb = wm + im * 16;
                af[im][0] = __float_as_uint(as[(mb + lr) * 20 + kk + lc]);
                af[im][1] = __float_as_uint(as[(mb + 8 + lr) * 20 + kk + lc]);
                af[im][2] = __float_as_uint(as[(mb + lr) * 20 + kk + 4 + lc]);
                af[im][3] = __float_as_uint(as[(mb + 8 + lr) * 20 + kk + 4 + lc]);
            }
            #pragma unroll
            for (int in = 0; in < 4; in++) {
                const int nb = wn + in * 8;
                bf[in][0] = __float_as_uint(bs[(nb + lr) * 20 + kk + lc]);
                bf[in][1] = __float_as_uint(bs[(nb + lr) * 20 + kk + 4 + lc]);
            }
            #pragma unroll
            for (int im = 0; im < 4; im++)
                #pragma unroll
                for (int in = 0; in < 4; in++)
                    mma_tf32(acc[im][in], af[im], bf[in]);
        }
    }

    // epilogue: exp, store, deterministic partial row sums
    #pragma unroll
    for (int im = 0; im < 4; im++) {
        const int r0 = m0 + wm + im * 16 + lr;
        const int r1 = r0 + 8;
        float sum0 = 0.f, sum1 = 0.f;
        #pragma unroll
        for (int in = 0; in < 4; in++) {
            const int cb = n0 + wn + in * 8 + 2 * lc;
            float* ac = acc[im][in];
            float e0 = __expf(0.125f * ac[0]);
            float e1 = __expf(0.125f * ac[1]);
            float e2 = __expf(0.125f * ac[2]);
            float e3 = __expf(0.125f * ac[3]);
            sum0 += e0 + e1;
            sum1 += e2 + e3;
            *(float2*)(C + (size_t)r0 * TT + cb) = make_float2(e0, e1);
            *(float2*)(C + (size_t)r1 * TT + cb) = make_float2(e2, e3);
        }
        // reduce over lc (4 lanes)
        sum0 += __shfl_xor_sync(0xffffffffu, sum0, 1);
        sum0 += __shfl_xor_sync(0xffffffffu, sum0, 2);
        sum1 += __shfl_xor_sync(0xffffffffu, sum1, 1);
        sum1 += __shfl_xor_sync(0xffffffffu, sum1, 2);
        if (lc == 0) {
            s_part[wni][wm + im * 16 + lr]     = sum0;
            s_part[wni][wm + im * 16 + 8 + lr] = sum1;
        }
    }
    __syncthreads();
    if (tid < 128) {
        float t = s_part[0][tid] + s_part[1][tid] + s_part[2][tid] + s_part[3][tid];
        part[((size_t)z * TT + m0 + tid) * KTILES + blockIdx.x] = t;
    }
}

// ================= AV kernel: nv = (p_un @ V) * inv, write back p_norm =================
// tile 128 x 64 x 16. grid (qtile=16, z=64).
#define AV_ASTAGE (128*20)
#define AV_BSTAGE (16*72)
#define SMEM_AV (3 * (AV_ASTAGE + AV_BSTAGE) * 4)

__global__ __launch_bounds__(256, 2) void av_kernel(
    float* __restrict__ attn, const float* __restrict__ QKV,
    const float* __restrict__ inv, float* __restrict__ nv)
{
    extern __shared__ float smem[];
    float* Asm = smem;
    float* Bsm = smem + 3 * AV_ASTAGE;

    const int z  = blockIdx.y;
    const int bb = z >> 4, hh = z & 15;
    float* Aat = attn + (size_t)z * TT * TT;
    const float* B = QKV + 2 * DIM + (size_t)bb * TT * D3 + hh * HP;   // V proj
    float* C = nv + (size_t)bb * TT * DIM + hh * HP;

    const int tid  = threadIdx.x;
    const int m0   = blockIdx.x * 128;
    const int w    = tid >> 5, lane = tid & 31;
    const int lr   = lane >> 2, lc = lane & 3;
    const int wm   = (w & 3) * 32;       // WARPS_M=4, WM=32, IM=2
    const int wn   = (w >> 2) * 32;      // WARPS_N=2, WN=32, IN=4

    const int arow = tid >> 2;
    const int acol = (tid & 3) * 4;
    const int crow = tid >> 4;           // 0..15
    const int ccol = (tid & 15) * 4;     // 0..60

    const float invA0 = inv[(size_t)z * TT + m0 + arow];
    const float invA1 = inv[(size_t)z * TT + m0 + arow + 64];

    float acc[2][4][4];
    #pragma unroll
    for (int i = 0; i < 2; i++)
        #pragma unroll
        for (int j = 0; j < 4; j++)
            #pragma unroll
            for (int q = 0; q < 4; q++) acc[i][j][q] = 0.f;

    auto load_stage = [&](int st, int k0) {
        float* as = Asm + st * AV_ASTAGE;
        #pragma unroll
        for (int i = 0; i < 2; i++) {
            int m = arow + i * 64;
            cpa16(&as[m * 20 + acol], Aat + (size_t)(m0 + m) * TT + k0 + acol);
        }
        float* bs = Bsm + st * AV_BSTAGE;
        cpa16(&bs[crow * 72 + ccol], B + (size_t)(k0 + crow) * D3 + ccol);
    };

    const int kiters = TT >> 4;   // 128
    #pragma unroll
    for (int s = 0; s < 2; s++) { load_stage(s, s * 16); cpa_commit(); }

    for (int it = 0; it < kiters; it++) {
        cpa_wait<1>();
        __syncthreads();
        const int nxt = it + 2;
        if (nxt < kiters) load_stage(nxt % 3, nxt * 16);
        cpa_commit();

        const float* as = Asm + (it % 3) * AV_ASTAGE;
        const float* bs = Bsm + (it % 3) * AV_BSTAGE;

        #pragma unroll
        for (int kk = 0; kk < 16; kk += 8) {
            unsigned af[2][4], bf[4][2];
            #pragma unroll
            for (int im = 0; im < 2; im++) {
                const int mb = wm + im * 16;
                af[im][0] = f2tf(as[(mb + lr) * 20 + kk + lc]);
                af[im][1] = f2tf(as[(mb + 8 + lr) * 20 + kk + lc]);
                af[im][2] = f2tf(as[(mb + lr) * 20 + kk + 4 + lc]);
                af[im][3] = f2tf(as[(mb + 8 + lr) * 20 + kk + 4 + lc]);
            }
            #pragma unroll
            for (int in = 0; in < 4; in++) {
                const int nb = wn + in * 8;
                bf[in][0] = __float_as_uint(bs[(kk + lc) * 72 + nb + lr]);
                bf[in][1] = __float_as_uint(bs[(kk + 4 + lc) * 72 + nb + lr]);
            }
            #pragma unroll
            for (int im = 0; im < 2; im++)
                #pragma unroll
                for (int in = 0; in < 4; in++)
                    mma_tf32(acc[im][in], af[im], bf[in]);
        }

        // write back normalized probs from this A stage (in-place; only this CTA reads this strip)
        {
            const int k0 = it * 16;
            #pragma unroll
            for (int i = 0; i < 2; i++) {
                const int m = arow + i * 64;
                const float sc = i ? invA1 : invA0;
                float4 v;
                v.x = as[m * 20 + acol + 0] * sc;
                v.y = as[m * 20 + acol + 1] * sc;
                v.z = as[m * 20 + acol + 2] * sc;
                v.w = as[m * 20 + acol + 3] * sc;
                *(float4*)(Aat + (size_t)(m0 + m) * TT + k0 + acol) = v;
            }
        }
    }

    // epilogue: nv = acc * inv[row], rounded (feeds WO GEMM)
    #pragma unroll
    for (int im = 0; im < 2; im++) {
        const int r0 = m0 + wm + im * 16 + lr;
        const int r1 = r0 + 8;
        const float i0 = inv[(size_t)z * TT + r0];
        const float i1 = inv[(size_t)z * TT + r1];
        #pragma unroll
        for (int in = 0; in < 4; in++) {
            const int cb = wn + in * 8 + 2 * lc;
            const float* ac = acc[im][in];
            *(float2*)(C + (size_t)r0 * DIM + cb) =
                make_float2(roundtf(ac[0] * i0), roundtf(ac[1] * i0));
            *(float2*)(C + (size_t)r1 * DIM + cb) =
                make_float2(roundtf(ac[2] * i1), roundtf(ac[3] * i1));
        }
    }
}

// ---------------- host launch ----------------
extern "C" void kernel_launch(void* const* d_in, const int* in_sizes, int n_in,
                              void* d_out, int out_size)
{
    const float* X      = (const float*)d_in[0];
    const float* WQ     = (const float*)d_in[1];
    const float* WK     = (const float*)d_in[2];
    const float* WV     = (const float*)d_in[3];
    const float* WO     = (const float*)d_in[4];
    const float* attn_g = (const float*)d_in[5];
    const float* attn_b = (const float*)d_in[6];
    const float* ff_g   = (const float*)d_in[7];
    const float* ff_b   = (const float*)d_in[8];
    const float* fW1    = (const float*)d_in[9];
    const float* fb1    = (const float*)d_in[10];
    const float* fW2    = (const float*)d_in[11];
    const float* fb2    = (const float*)d_in[12];
    float* out0 = (float*)d_out;

    float *nX, *QKV, *nv, *seq, *preff, *preff_r, *hidden, *Wt, *WOr, *fW1r, *fW2r, *part, *inv, *Sfb;
    cudaGetSymbolAddress((void**)&nX,      g_nX);
    cudaGetSymbolAddress((void**)&QKV,     g_QKV);
    cudaGetSymbolAddress((void**)&nv,      g_nv);
    cudaGetSymbolAddress((void**)&seq,     g_seq);
    cudaGetSymbolAddress((void**)&preff,   g_preff);
    cudaGetSymbolAddress((void**)&preff_r, g_preff_r);
    cudaGetSymbolAddress((void**)&hidden,  g_hidden);
    cudaGetSymbolAddress((void**)&Wt,      g_Wt);
    cudaGetSymbolAddress((void**)&WOr,     g_WOr);
    cudaGetSymbolAddress((void**)&fW1r,    g_fW1r);
    cudaGetSymbolAddress((void**)&fW2r,    g_fW2r);
    cudaGetSymbolAddress((void**)&part,    g_part);
    cudaGetSymbolAddress((void**)&inv,     g_inv);
    cudaGetSymbolAddress((void**)&Sfb,     g_Sfb);

    cudaFuncSetAttribute(dense_gemm, cudaFuncAttributeMaxDynamicSharedMemorySize, SMEM_DENSE);
    cudaFuncSetAttribute(scores_kernel, cudaFuncAttributeMaxDynamicSharedMemorySize, SMEM_SCORES);
    cudaFuncSetAttribute(av_kernel, cudaFuncAttributeMaxDynamicSharedMemorySize, SMEM_AV);

    const long long xel     = (long long)BT * DIM;
    const long long attn_el = (long long)NZ * TT * TT;
    float* attn = ((long long)out_size >= xel + attn_el) ? (out0 + xel) : Sfb;

    // 1) nX = round(LN(X))
    ln_kernel<<<BT, 256>>>(X, attn_g, attn_b, nullptr, nX, nullptr, 1);

    // 2) weights: permute+round QKV weights; round WO/fW1/fW2
    wtrans_kernel<<<(DIM * DIM + 255) / 256, 256>>>(WQ, Wt, 0);
    wtrans_kernel<<<(DIM * DIM + 255) / 256, 256>>>(WK, Wt, DIM);
    wtrans_kernel<<<(DIM * DIM + 255) / 256, 256>>>(WV, Wt, 2 * DIM);
    round_kernel<<<(DIM * DIM / 4 + 255) / 256, 256>>>(WO, WOr, DIM * DIM / 4);
    round_kernel<<<(DIM * FFD / 4 + 255) / 256, 256>>>(fW1, fW1r, DIM * FFD / 4);
    round_kernel<<<(FFD * DIM / 4 + 255) / 256, 256>>>(fW2, fW2r, FFD * DIM / 4);

    // 3) QKV = nX @ Wt (rounded out)
    dense_gemm<<<dim3(D3 / 128, BT / 128), 256, SMEM_DENSE>>>(
        BT, D3, DIM, nX, DIM, Wt, D3, QKV, D3, 0, nullptr, nullptr, 0, 1);

    // 4) p_un = exp(scores), partial sums
    scores_kernel<<<dim3(KTILES, TT / 128, NZ), 256, SMEM_SCORES>>>(QKV, attn, part);

    // 5) inv = 1 / rowsum
    rowinv_kernel<<<(ROWS_ALL + 255) / 256, 256>>>(part, inv);

    // 6) AV + normalize probs in place + rounded nv
    av_kernel<<<dim3(TT / 128, NZ), 256, SMEM_AV>>>(attn, QKV, inv, nv);

    // 7) seq = nv @ WO_r
    dense_gemm<<<dim3(DIM / 128, BT / 128), 256, SMEM_DENSE>>>(
        BT, DIM, DIM, nv, DIM, WOr, DIM, seq, DIM, 0, nullptr, nullptr, 0, 0);

    // 8) pre_ff = X + LN(seq)  (exact) + rounded copy
    ln_kernel<<<BT, 256>>>(seq, ff_g, ff_b, X, preff, preff_r, 0);

    // 9) hidden = round(gelu(preff_r @ fW1_r + fb1))
    dense_gemm<<<dim3(FFD / 128, BT / 128), 256, SMEM_DENSE>>>(
        BT, FFD, DIM, preff_r, DIM, fW1r, FFD, hidden, FFD, 1, fb1, nullptr, 0, 1);

    // 10) out = hidden @ fW2_r + fb2 + preff
    dense_gemm<<<dim3(DIM / 128, BT / 128), 256, SMEM_DENSE>>>(
        BT, DIM, FFD, hidden, FFD, fW2r, DIM, out0, DIM, 2, fb2, preff, DIM, 0);
}

// round 6
// speedup vs baseline: 4.6624x; 1.4331x over previous
#include <cuda_runtime.h>
#include <cuda_fp16.h>
#include <math.h>
#include <stdint.h>

#define BB    4
#define TT    2048
#define DIM   1024
#define NH    16
#define HP    64
#define FFD   4096
#define BT    (BB*TT)          // 8192
#define D3    (3*DIM)          // 3072
#define NZ    (BB*NH)          // 64 batch-heads
#define ROWS_ALL (NZ*TT)       // 131072
#define KTILES (TT/128)        // 16

// ---------------- scratch ----------------
__device__ __half g_nXh[(size_t)BT*DIM];
__device__ __half g_QKVh[(size_t)BT*D3];
__device__ __half g_nvh[(size_t)BT*DIM];
__device__ float  g_seq[(size_t)BT*DIM];
__device__ float  g_preff[(size_t)BT*DIM];
__device__ __half g_preffh[(size_t)BT*DIM];
__device__ __half g_hiddenh[(size_t)BT*FFD];
__device__ __half g_Wth[(size_t)D3*DIM];         // QKV weights permuted+transposed [3D][D]
__device__ __half g_WOh[(size_t)DIM*DIM];        // WO^T [D][D]
__device__ __half g_fW1h[(size_t)FFD*DIM];       // fW1^T [FF][D]
__device__ __half g_fW2h[(size_t)DIM*FFD];       // fW2^T [D][FF]
__device__ float  g_part[(size_t)ROWS_ALL*KTILES];
__device__ float  g_inv[(size_t)ROWS_ALL];
__device__ float  g_Sfb[(size_t)NZ*TT*TT];

// ---------------- helpers ----------------
__device__ __forceinline__ float gelu_exact(float x)
{
    return 0.5f * x * (1.0f + erff(x * 0.70710678118654752440f));
}

__device__ __forceinline__ uint32_t smem_u32(const void* p)
{
    return (uint32_t)__cvta_generic_to_shared(p);
}
__device__ __forceinline__ void cpa16(uint32_t dst, const void* src)
{
    asm volatile("cp.async.cg.shared.global [%0], [%1], 16;" :: "r"(dst), "l"(src));
}
__device__ __forceinline__ void cpa_commit() { asm volatile("cp.async.commit_group;"); }
template<int N>
__device__ __forceinline__ void cpa_wait() { asm volatile("cp.async.wait_group %0;" :: "n"(N)); }

__device__ __forceinline__ void ldm_x4(uint32_t r[4], uint32_t addr)
{
    asm volatile("ldmatrix.sync.aligned.m8n8.x4.shared.b16 {%0,%1,%2,%3}, [%4];"
                 : "=r"(r[0]), "=r"(r[1]), "=r"(r[2]), "=r"(r[3]) : "r"(addr));
}
__device__ __forceinline__ void ldm_x4_t(uint32_t r[4], uint32_t addr)
{
    asm volatile("ldmatrix.sync.aligned.m8n8.x4.trans.shared.b16 {%0,%1,%2,%3}, [%4];"
                 : "=r"(r[0]), "=r"(r[1]), "=r"(r[2]), "=r"(r[3]) : "r"(addr));
}

__device__ __forceinline__ void mma_f16(float c[4], const uint32_t a[4], uint32_t b0, uint32_t b1)
{
    asm volatile(
        "mma.sync.aligned.m16n8k16.row.col.f32.f16.f16.f32 "
        "{%0,%1,%2,%3}, {%4,%5,%6,%7}, {%8,%9}, {%0,%1,%2,%3};"
        : "+f"(c[0]), "+f"(c[1]), "+f"(c[2]), "+f"(c[3])
        : "r"(a[0]), "r"(a[1]), "r"(a[2]), "r"(a[3]), "r"(b0), "r"(b1));
}

// pack two f32 -> f16x2 reg (lo in bits 0-15, hi in 16-31)
__device__ __forceinline__ uint32_t pack_h2(float lo, float hi)
{
    uint32_t r;
    asm("cvt.rn.f16x2.f32 %0, %1, %2;" : "=r"(r) : "f"(hi), "f"(lo));
    return r;
}

// ---------------- layernorm: optional fp32 out, optional half out ----------------
__global__ void ln_kernel(const float* __restrict__ x,
                          const float* __restrict__ g,
                          const float* __restrict__ b,
                          const float* __restrict__ resid,
                          float* __restrict__ outf,
                          __half* __restrict__ outh)
{
    const size_t row = blockIdx.x;
    const float4* xr = (const float4*)(x + row * (size_t)DIM);
    const int tid = threadIdx.x;
    float4 xv = xr[tid];

    float s  = xv.x + xv.y + xv.z + xv.w;
    float ss = xv.x*xv.x + xv.y*xv.y + xv.z*xv.z + xv.w*xv.w;

    #pragma unroll
    for (int o = 16; o > 0; o >>= 1) {
        s  += __shfl_xor_sync(0xffffffffu, s,  o);
        ss += __shfl_xor_sync(0xffffffffu, ss, o);
    }
    __shared__ float rs[8], rss[8];
    int wid = tid >> 5, lane = tid & 31;
    if (lane == 0) { rs[wid] = s; rss[wid] = ss; }
    __syncthreads();
    __shared__ float s_mean, s_rstd;
    if (tid == 0) {
        float ts = 0.f, tss = 0.f;
        #pragma unroll
        for (int i = 0; i < 8; i++) { ts += rs[i]; tss += rss[i]; }
        float mean = ts * (1.0f / DIM);
        float var  = tss * (1.0f / DIM) - mean * mean;
        s_mean = mean;
        s_rstd = rsqrtf(var + 1e-5f);
    }
    __syncthreads();
    const float mean = s_mean, rstd = s_rstd;

    const float4 gv = ((const float4*)g)[tid];
    const float4 bv = ((const float4*)b)[tid];
    float4 o4;
    o4.x = (xv.x - mean) * rstd * gv.x + bv.x;
    o4.y = (xv.y - mean) * rstd * gv.y + bv.y;
    o4.z = (xv.z - mean) * rstd * gv.z + bv.z;
    o4.w = (xv.w - mean) * rstd * gv.w + bv.w;
    if (resid) {
        const float4 rv = ((const float4*)(resid + row * (size_t)DIM))[tid];
        o4.x += rv.x; o4.y += rv.y; o4.z += rv.z; o4.w += rv.w;
    }
    if (outf) ((float4*)(outf + row * (size_t)DIM))[tid] = o4;
    if (outh) {
        __half2* oh = (__half2*)(outh + row * (size_t)DIM);
        oh[tid * 2 + 0] = __floats2half2_rn(o4.x, o4.y);
        oh[tid * 2 + 1] = __floats2half2_rn(o4.z, o4.w);
    }
}

// ---------------- permute (H,D,P) -> rows of [3D][D], half ----------------
__global__ void wtrans_kernel(const float* __restrict__ w, __half* __restrict__ o, int rowoff)
{
    int idx = blockIdx.x * blockDim.x + threadIdx.x;
    if (idx >= DIM * DIM) return;
    int p = idx & 63;
    int d = (idx >> 6) & 1023;
    int h = idx >> 16;
    o[(size_t)(rowoff + h * HP + p) * DIM + d] = __float2half(w[idx]);
}

// ---------------- tiled transpose: dst_h[c][r] = half(src[r][c]) ----------------
__global__ void transp_kernel(const float* __restrict__ src, __half* __restrict__ dst, int R, int C)
{
    __shared__ float t[32][33];
    int c0 = blockIdx.x * 32, r0 = blockIdx.y * 32;
    #pragma unroll
    for (int j = 0; j < 32; j += 8)
        t[threadIdx.y + j][threadIdx.x] = src[(size_t)(r0 + threadIdx.y + j) * C + c0 + threadIdx.x];
    __syncthreads();
    #pragma unroll
    for (int j = 0; j < 32; j += 8)
        dst[(size_t)(c0 + threadIdx.y + j) * R + r0 + threadIdx.x] = __float2half(t[threadIdx.x][threadIdx.y + j]);
}

// ---------------- rowsum -> inverse ----------------
__global__ void rowinv_kernel(const float* __restrict__ part, float* __restrict__ inv)
{
    int idx = blockIdx.x * blockDim.x + threadIdx.x;
    if (idx >= ROWS_ALL) return;
    const float4* p = (const float4*)(part + (size_t)idx * KTILES);
    float s = 0.f;
    #pragma unroll
    for (int i = 0; i < KTILES / 4; i++) {
        float4 v = p[i];
        s += v.x + v.y + v.z + v.w;
    }
    inv[idx] = 1.0f / s;
}

// ================= fp16 dense GEMM (NT): C[m,n] = sum_k A[m,k]*Bt[n,k] =================
// 128x128x32 tile, 3-stage cp.async, ldmatrix + m16n8k16. 8 warps (2x4), warp 64x32.
// epi: 0 none, 1 gelu(x+bias), 2 x+bias+resid. out_half: C is __half else float.
#define HG_LD     40                      // halves per row (32 data + 8 pad)
#define HG_STAGE  (128*HG_LD)             // halves per operand stage
#define HG_SMEM   (3 * 2 * HG_STAGE * 2)  // bytes = 61440

__global__ __launch_bounds__(256, 2) void hgemm(
    int M, int N, int K,
    const __half* __restrict__ A, int lda,
    const __half* __restrict__ Bt, int ldb,
    void* __restrict__ Cv, int ldc,
    int epi, const float* __restrict__ bias,
    const float* __restrict__ resid, int ldr, int out_half)
{
    extern __shared__ __half hsm[];
    __half* Asm = hsm;
    __half* Bsm = hsm + 3 * HG_STAGE;

    const int tid  = threadIdx.x;
    const int m0   = blockIdx.y * 128;
    const int n0   = blockIdx.x * 128;
    const int w    = tid >> 5, lane = tid & 31;
    const int lr   = lane >> 2, lc = lane & 3;
    const int wm   = (w & 1) * 64;
    const int wn   = (w >> 1) * 32;

    // global load mapping: row = tid>>1, 2 chunks of 8 halves at cols (tid&1)*16 + {0,8}
    const int lrow = tid >> 1;
    const int lcol = (tid & 1) * 16;

    // ldmatrix lane addressing
    const int sel   = lane >> 3;          // 0..3
    const int off8  = (sel & 1) * 8;      // row offset within 16
    const int koff8 = (sel >> 1) * 8;     // k offset within 16
    const int lrow8 = lane & 7;

    float acc[4][4][4];
    #pragma unroll
    for (int i = 0; i < 4; i++)
        #pragma unroll
        for (int j = 0; j < 4; j++)
            #pragma unroll
            for (int q = 0; q < 4; q++) acc[i][j][q] = 0.f;

    auto load_stage = [&](int st, int k0) {
        __half* as = Asm + st * HG_STAGE;
        __half* bs = Bsm + st * HG_STAGE;
        #pragma unroll
        for (int i = 0; i < 2; i++) {
            int c = lcol + i * 8;
            cpa16(smem_u32(as + lrow * HG_LD + c), A  + (size_t)(m0 + lrow) * lda + k0 + c);
            cpa16(smem_u32(bs + lrow * HG_LD + c), Bt + (size_t)(n0 + lrow) * ldb + k0 + c);
        }
    };

    const int kiters = K >> 5;
    load_stage(0, 0);  cpa_commit();
    load_stage(1, 32); cpa_commit();

    for (int it = 0; it < kiters; it++) {
        cpa_wait<1>();
        __syncthreads();

        const int nxt = it + 2;
        if (nxt < kiters) load_stage(nxt % 3, nxt * 32);
        cpa_commit();

        const __half* as = Asm + (it % 3) * HG_STAGE;
        const __half* bs = Bsm + (it % 3) * HG_STAGE;

        #pragma unroll
        for (int kk = 0; kk < 32; kk += 16) {
            uint32_t af[4][4], bf[2][4];
            #pragma unroll
            for (int im = 0; im < 4; im++)
                ldm_x4(af[im], smem_u32(as + (wm + im * 16 + off8 + lrow8) * HG_LD + kk + koff8));
            #pragma unroll
            for (int j = 0; j < 2; j++)
                ldm_x4(bf[j], smem_u32(bs + (wn + j * 16 + off8 + lrow8) * HG_LD + kk + koff8));
            #pragma unroll
            for (int im = 0; im < 4; im++)
                #pragma unroll
                for (int j = 0; j < 2; j++) {
                    mma_f16(acc[im][2 * j + 0], af[im], bf[j][0], bf[j][2]);
                    mma_f16(acc[im][2 * j + 1], af[im], bf[j][1], bf[j][3]);
                }
        }
        __syncthreads();
    }

    // epilogue
    #pragma unroll
    for (int im = 0; im < 4; im++) {
        const int r0 = m0 + wm + im * 16 + lr;
        const int r1 = r0 + 8;
        #pragma unroll
        for (int in = 0; in < 4; in++) {
            const int cb = n0 + wn + in * 8 + 2 * lc;
            const float* ac = acc[im][in];
            float b0 = 0.f, b1 = 0.f;
            if (epi != 0) { b0 = bias[cb]; b1 = bias[cb + 1]; }

            float v0 = ac[0], v1 = ac[1];
            if (epi == 1) { v0 = gelu_exact(v0 + b0); v1 = gelu_exact(v1 + b1); }
            else if (epi == 2) {
                const float2 rv = *(const float2*)(resid + (size_t)r0 * ldr + cb);
                v0 += b0 + rv.x; v1 += b1 + rv.y;
            }
            float v2 = ac[2], v3 = ac[3];
            if (epi == 1) { v2 = gelu_exact(v2 + b0); v3 = gelu_exact(v3 + b1); }
            else if (epi == 2) {
                const float2 rv = *(const float2*)(resid + (size_t)r1 * ldr + cb);
                v2 += b0 + rv.x; v3 += b1 + rv.y;
            }
            if (out_half) {
                __half* C = (__half*)Cv;
                *(__half2*)(C + (size_t)r0 * ldc + cb) = __floats2half2_rn(v0, v1);
                *(__half2*)(C + (size_t)r1 * ldc + cb) = __floats2half2_rn(v2, v3);
            } else {
                float* C = (float*)Cv;
                *(float2*)(C + (size_t)r0 * ldc + cb) = make_float2(v0, v1);
                *(float2*)(C + (size_t)r1 * ldc + cb) = make_float2(v2, v3);
            }
        }
    }
}

// ================= scores: p_un = exp(K.Q^T/8) + partial row sums (fp16 mma) ==========
#define SC_LD 72

__global__ __launch_bounds__(256, 2) void scores_kernel(
    const __half* __restrict__ QKVh, float* __restrict__ attn, float* __restrict__ part)
{
    __shared__ __half sA[128 * SC_LD];
    __shared__ __half sB[128 * SC_LD];
    __shared__ float s_part[4][128];

    const int z  = blockIdx.z;
    const int bb = z >> 4, hh = z & 15;
    const __half* A = QKVh + DIM + (size_t)bb * TT * D3 + hh * HP;   // K proj
    const __half* B = QKVh +        (size_t)bb * TT * D3 + hh * HP;  // Q proj
    float* C = attn + (size_t)z * TT * TT;

    const int tid  = threadIdx.x;
    const int m0   = blockIdx.y * 128;
    const int n0   = blockIdx.x * 128;
    const int w    = tid >> 5, lane = tid & 31;
    const int lr   = lane >> 2, lc = lane & 3;
    const int wm   = (w & 1) * 64;
    const int wn   = (w >> 1) * 32;
    const int wni  = w >> 1;

    const int sel   = lane >> 3;
    const int off8  = (sel & 1) * 8;
    const int koff8 = (sel >> 1) * 8;
    const int lrow8 = lane & 7;

    // load full 128x64 tiles (8 chunks/row; 4 chunks per thread per operand)
    #pragma unroll
    for (int i = 0; i < 4; i++) {
        int g = tid + i * 256;             // 0..1023
        int row = g >> 3, c8 = (g & 7) * 8;
        cpa16(smem_u32(sA + row * SC_LD + c8), A + (size_t)(m0 + row) * D3 + c8);
        cpa16(smem_u32(sB + row * SC_LD + c8), B + (size_t)(n0 + row) * D3 + c8);
    }
    cpa_commit();
    cpa_wait<0>();
    __syncthreads();

    float acc[4][4][4];
    #pragma unroll
    for (int i = 0; i < 4; i++)
        #pragma unroll
        for (int j = 0; j < 4; j++)
            #pragma unroll
            for (int q = 0; q < 4; q++) acc[i][j][q] = 0.f;

    #pragma unroll
    for (int kk = 0; kk < 64; kk += 16) {
        uint32_t af[4][4], bf[2][4];
        #pragma unroll
        for (int im = 0; im < 4; im++)
            ldm_x4(af[im], smem_u32(sA + (wm + im * 16 + off8 + lrow8) * SC_LD + kk + koff8));
        #pragma unroll
        for (int j = 0; j < 2; j++)
            ldm_x4(bf[j], smem_u32(sB + (wn + j * 16 + off8 + lrow8) * SC_LD + kk + koff8));
        #pragma unroll
        for (int im = 0; im < 4; im++)
            #pragma unroll
            for (int j = 0; j < 2; j++) {
                mma_f16(acc[im][2 * j + 0], af[im], bf[j][0], bf[j][2]);
                mma_f16(acc[im][2 * j + 1], af[im], bf[j][1], bf[j][3]);
            }
    }

    // epilogue: exp, store, deterministic partial row sums
    #pragma unroll
    for (int im = 0; im < 4; im++) {
        const int r0 = m0 + wm + im * 16 + lr;
        const int r1 = r0 + 8;
        float sum0 = 0.f, sum1 = 0.f;
        #pragma unroll
        for (int in = 0; in < 4; in++) {
            const int cb = n0 + wn + in * 8 + 2 * lc;
            float* ac = acc[im][in];
            float e0 = __expf(0.125f * ac[0]);
            float e1 = __expf(0.125f * ac[1]);
            float e2 = __expf(0.125f * ac[2]);
            float e3 = __expf(0.125f * ac[3]);
            sum0 += e0 + e1;
            sum1 += e2 + e3;
            *(float2*)(C + (size_t)r0 * TT + cb) = make_float2(e0, e1);
            *(float2*)(C + (size_t)r1 * TT + cb) = make_float2(e2, e3);
        }
        sum0 += __shfl_xor_sync(0xffffffffu, sum0, 1);
        sum0 += __shfl_xor_sync(0xffffffffu, sum0, 2);
        sum1 += __shfl_xor_sync(0xffffffffu, sum1, 1);
        sum1 += __shfl_xor_sync(0xffffffffu, sum1, 2);
        if (lc == 0) {
            s_part[wni][wm + im * 16 + lr]     = sum0;
            s_part[wni][wm + im * 16 + 8 + lr] = sum1;
        }
    }
    __syncthreads();
    if (tid < 128) {
        float t = s_part[0][tid] + s_part[1][tid] + s_part[2][tid] + s_part[3][tid];
        part[((size_t)z * TT + m0 + tid) * KTILES + blockIdx.x] = t;
    }
}

// ================= AV: nv = (p_un @ V) * inv, write back p_norm =================
// tile 128x64x32. A = probs fp32 (cvt->f16 in regs), B = V half via ldmatrix.trans.
#define AV_ALD    36                        // floats per A row (32 + 4 pad)
#define AV_ASTG   (128*AV_ALD)              // floats
#define AV_BLD    72                        // halves per B row (64 + 8 pad)
#define AV_BSTG   (32*AV_BLD)               // halves
#define AV_SMEM   (3 * (AV_ASTG * 4 + AV_BSTG * 2))   // 69120 B

__global__ __launch_bounds__(256, 2) void av_kernel(
    float* __restrict__ attn, const __half* __restrict__ QKVh,
    const float* __restrict__ inv, __half* __restrict__ nvh)
{
    extern __shared__ float avsm[];
    float*  Af = avsm;                                   // 3 * AV_ASTG floats
    __half* Bh = (__half*)(avsm + 3 * AV_ASTG);          // 3 * AV_BSTG halves

    const int z  = blockIdx.y;
    const int bb = z >> 4, hh = z & 15;
    float* Aat = attn + (size_t)z * TT * TT;
    const __half* V = QKVh + 2 * DIM + (size_t)bb * TT * D3 + hh * HP;
    __half* C = nvh + (size_t)bb * TT * DIM + hh * HP;

    const int tid  = threadIdx.x;
    const int m0   = blockIdx.x * 128;
    const int w    = tid >> 5, lane = tid & 31;
    const int lr   = lane >> 2, lc = lane & 3;
    const int wm   = (w & 3) * 32;      // 4 warps in m, warp 32 rows
    const int wn   = (w >> 2) * 32;     // 2 warps in n, warp 32 cols

    const int sel   = lane >> 3;
    const int koff8 = (sel & 1) * 8;
    const int noff8 = (sel >> 1) * 8;
    const int lrow8 = lane & 7;

    // A load mapping: 4 chunks/thread: rows tid>>3 + 32i, col (tid&7)*4 floats
    const int arow = tid >> 3;
    const int ac4  = (tid & 7) * 4;
    // B load: 1 chunk: row tid>>3 (0..31), col (tid&7)*8 halves
    const int brow = tid >> 3;
    const int bc8  = (tid & 7) * 8;

    float inv4[4];
    #pragma unroll
    for (int i = 0; i < 4; i++)
        inv4[i] = inv[(size_t)z * TT + m0 + arow + 32 * i];

    float acc[2][4][4];
    #pragma unroll
    for (int i = 0; i < 2; i++)
        #pragma unroll
        for (int j = 0; j < 4; j++)
            #pragma unroll
            for (int q = 0; q < 4; q++) acc[i][j][q] = 0.f;

    auto load_stage = [&](int st, int k0) {
        float* af = Af + st * AV_ASTG;
        #pragma unroll
        for (int i = 0; i < 4; i++) {
            int row = arow + 32 * i;
            cpa16(smem_u32(af + row * AV_ALD + ac4), Aat + (size_t)(m0 + row) * TT + k0 + ac4);
        }
        __half* bs = Bh + st * AV_BSTG;
        if (tid < 256) {
            cpa16(smem_u32(bs + brow * AV_BLD + bc8), V + (size_t)(k0 + brow) * D3 + bc8);
        }
    };

    const int kiters = TT >> 5;   // 64
    load_stage(0, 0);  cpa_commit();
    load_stage(1, 32); cpa_commit();

    for (int it = 0; it < kiters; it++) {
        cpa_wait<1>();
        __syncthreads();

        const int nxt = it + 2;
        if (nxt < kiters) load_stage(nxt % 3, nxt * 32);
        cpa_commit();

        const float*  af = Af + (it % 3) * AV_ASTG;
        const __half* bs = Bh + (it % 3) * AV_BSTG;

        #pragma unroll
        for (int kk = 0; kk < 32; kk += 16) {
            uint32_t aw[2][4], bw[2][4];
            #pragma unroll
            for (int im = 0; im < 2; im++) {
                const int mb = wm + im * 16;
                #pragma unroll
                for (int r = 0; r < 4; r++) {
                    const int row = mb + (r & 1) * 8 + lr;
                    const int ke  = kk + (r >> 1) * 8 + 2 * lc;
                    const float2 v = *(const float2*)(af + row * AV_ALD + ke);
                    aw[im][r] = pack_h2(v.x, v.y);
                }
            }
            #pragma unroll
            for (int j = 0; j < 2; j++)
                ldm_x4_t(bw[j], smem_u32(bs + (kk + koff8 + lrow8) * AV_BLD + wn + j * 16 + noff8));
            // bw[j]: r0 = b0 of n8 tile 2j, r1 = b1 of tile 2j, r2 = b0 of tile 2j+1, r3 = b1
            #pragma unroll
            for (int im = 0; im < 2; im++)
                #pragma unroll
                for (int j = 0; j < 2; j++) {
                    mma_f16(acc[im][2 * j + 0], aw[im], bw[j][0], bw[j][1]);
                    mma_f16(acc[im][2 * j + 1], aw[im], bw[j][2], bw[j][3]);
                }
        }

        // normalized-prob write-back (CTA owns this 128-row strip)
        {
            const int k0 = it * 32;
            const float* af2 = af;
            #pragma unroll
            for (int i = 0; i < 4; i++) {
                const int row = arow + 32 * i;
                const float sc = inv4[i];
                float4 v = *(const float4*)(af2 + row * AV_ALD + ac4);
                v.x *= sc; v.y *= sc; v.z *= sc; v.w *= sc;
                *(float4*)(Aat + (size_t)(m0 + row) * TT + k0 + ac4) = v;
            }
        }
        __syncthreads();
    }

    // epilogue: nv_h = half(acc * inv[row])
    #pragma unroll
    for (int im = 0; im < 2; im++) {
        const int r0 = m0 + wm + im * 16 + lr;
        const int r1 = r0 + 8;
        const float i0 = inv[(size_t)z * TT + r0];
        const float i1 = inv[(size_t)z * TT + r1];
        #pragma unroll
        for (int in = 0; in < 4; in++) {
            const int cb = wn + in * 8 + 2 * lc;
            const float* ac = acc[im][in];
            *(__half2*)(C + (size_t)r0 * DIM + cb) = __floats2half2_rn(ac[0] * i0, ac[1] * i0);
            *(__half2*)(C + (size_t)r1 * DIM + cb) = __floats2half2_rn(ac[2] * i1, ac[3] * i1);
        }
    }
}

// ---------------- host launch ----------------
extern "C" void kernel_launch(void* const* d_in, const int* in_sizes, int n_in,
                              void* d_out, int out_size)
{
    const float* X      = (const float*)d_in[0];
    const float* WQ     = (const float*)d_in[1];
    const float* WK     = (const float*)d_in[2];
    const float* WV     = (const float*)d_in[3];
    const float* WO     = (const float*)d_in[4];
    const float* attn_g = (const float*)d_in[5];
    const float* attn_b = (const float*)d_in[6];
    const float* ff_g   = (const float*)d_in[7];
    const float* ff_b   = (const float*)d_in[8];
    const float* fW1    = (const float*)d_in[9];
    const float* fb1    = (const float*)d_in[10];
    const float* fW2    = (const float*)d_in[11];
    const float* fb2    = (const float*)d_in[12];
    float* out0 = (float*)d_out;

    __half *nXh, *QKVh, *nvh, *preffh, *hiddenh, *Wth, *WOh, *fW1h, *fW2h;
    float *seq, *preff, *part, *inv, *Sfb;
    cudaGetSymbolAddress((void**)&nXh,     g_nXh);
    cudaGetSymbolAddress((void**)&QKVh,    g_QKVh);
    cudaGetSymbolAddress((void**)&nvh,     g_nvh);
    cudaGetSymbolAddress((void**)&seq,     g_seq);
    cudaGetSymbolAddress((void**)&preff,   g_preff);
    cudaGetSymbolAddress((void**)&preffh,  g_preffh);
    cudaGetSymbolAddress((void**)&hiddenh, g_hiddenh);
    cudaGetSymbolAddress((void**)&Wth,     g_Wth);
    cudaGetSymbolAddress((void**)&WOh,     g_WOh);
    cudaGetSymbolAddress((void**)&fW1h,    g_fW1h);
    cudaGetSymbolAddress((void**)&fW2h,    g_fW2h);
    cudaGetSymbolAddress((void**)&part,    g_part);
    cudaGetSymbolAddress((void**)&inv,     g_inv);
    cudaGetSymbolAddress((void**)&Sfb,     g_Sfb);

    cudaFuncSetAttribute(hgemm, cudaFuncAttributeMaxDynamicSharedMemorySize, HG_SMEM);
    cudaFuncSetAttribute(av_kernel, cudaFuncAttributeMaxDynamicSharedMemorySize, AV_SMEM);

    const long long xel     = (long long)BT * DIM;
    const long long attn_el = (long long)NZ * TT * TT;
    float* attn = ((long long)out_size >= xel + attn_el) ? (out0 + xel) : Sfb;

    // 1) nX_h = half(LN(X))
    ln_kernel<<<BT, 256>>>(X, attn_g, attn_b, nullptr, nullptr, nXh);

    // 2) weights -> half, transposed layouts
    wtrans_kernel<<<(DIM * DIM + 255) / 256, 256>>>(WQ, Wth, 0);
    wtrans_kernel<<<(DIM * DIM + 255) / 256, 256>>>(WK, Wth, DIM);
    wtrans_kernel<<<(DIM * DIM + 255) / 256, 256>>>(WV, Wth, 2 * DIM);
    transp_kernel<<<dim3(DIM / 32, DIM / 32), dim3(32, 8)>>>(WO,  WOh,  DIM, DIM);
    transp_kernel<<<dim3(FFD / 32, DIM / 32), dim3(32, 8)>>>(fW1, fW1h, DIM, FFD);
    transp_kernel<<<dim3(DIM / 32, FFD / 32), dim3(32, 8)>>>(fW2, fW2h, FFD, DIM);

    // 3) QKV_h = nX_h @ Wt^T (half out)
    hgemm<<<dim3(D3 / 128, BT / 128), 256, HG_SMEM>>>(
        BT, D3, DIM, nXh, DIM, Wth, DIM, QKVh, D3, 0, nullptr, nullptr, 0, 1);

    // 4) p_un = exp(scores), partial sums
    scores_kernel<<<dim3(KTILES, TT / 128, NZ), 256>>>(QKVh, attn, part);

    // 5) inv = 1 / rowsum
    rowinv_kernel<<<(ROWS_ALL + 255) / 256, 256>>>(part, inv);

    // 6) AV + normalize probs in place + nv_h
    av_kernel<<<dim3(TT / 128, NZ), 256, AV_SMEM>>>(attn, QKVh, inv, nvh);

    // 7) seq = nv_h @ WO^T (fp32 out)
    hgemm<<<dim3(DIM / 128, BT / 128), 256, HG_SMEM>>>(
        BT, DIM, DIM, nvh, DIM, WOh, DIM, seq, DIM, 0, nullptr, nullptr, 0, 0);

    // 8) pre_ff = X + LN(seq): fp32 + half copies
    ln_kernel<<<BT, 256>>>(seq, ff_g, ff_b, X, preff, preffh);

    // 9) hidden_h = half(gelu(preff_h @ fW1^T + fb1))
    hgemm<<<dim3(FFD / 128, BT / 128), 256, HG_SMEM>>>(
        BT, FFD, DIM, preffh, DIM, fW1h, DIM, hiddenh, FFD, 1, fb1, nullptr, 0, 1);

    // 10) out = hidden_h @ fW2^T + fb2 + preff (fp32)
    hgemm<<<dim3(DIM / 128, BT / 128), 256, HG_SMEM>>>(
        BT, DIM, FFD, hiddenh, FFD, fW2h, FFD, out0, DIM, 2, fb2, preff, DIM, 0);
}

// round 9
// speedup vs baseline: 4.7712x; 1.0233x over previous
#include <cuda_runtime.h>
#include <cuda_fp16.h>
#include <math.h>
#include <stdint.h>

#define BB    4
#define TT    2048
#define DIM   1024
#define NH    16
#define HP    64
#define FFD   4096
#define BT    (BB*TT)          // 8192
#define D3    (3*DIM)          // 3072
#define NZ    (BB*NH)          // 64 batch-heads
#define ROWS_ALL (NZ*TT)       // 131072
#define KTILES (TT/128)        // 16

// ---------------- scratch ----------------
__device__ __half g_nXh[(size_t)BT*DIM];
__device__ __half g_QKVh[(size_t)BT*D3];
__device__ __half g_nvh[(size_t)BT*DIM];
__device__ float  g_seq[(size_t)BT*DIM];
__device__ float  g_preff[(size_t)BT*DIM];
__device__ __half g_preffh[(size_t)BT*DIM];
__device__ __half g_hiddenh[(size_t)BT*FFD];
__device__ __half g_Wth[(size_t)D3*DIM];         // QKV weights permuted+transposed [3D][D]
__device__ __half g_WOh[(size_t)DIM*DIM];        // WO^T [D][D]
__device__ __half g_fW1h[(size_t)FFD*DIM];       // fW1^T [FF][D]
__device__ __half g_fW2h[(size_t)DIM*FFD];       // fW2^T [D][FF]
__device__ __half g_Ph[(size_t)NZ*TT*TT];        // unnormalized probs (fp16)
__device__ float  g_part[(size_t)ROWS_ALL*KTILES];
__device__ float  g_inv[(size_t)ROWS_ALL];
__device__ float  g_Sfb[(size_t)NZ*TT*TT];       // attn fallback if d_out lacks room

// ---------------- helpers ----------------
__device__ __forceinline__ float gelu_exact(float x)
{
    return 0.5f * x * (1.0f + erff(x * 0.70710678118654752440f));
}

__device__ __forceinline__ uint32_t smem_u32(const void* p)
{
    return (uint32_t)__cvta_generic_to_shared(p);
}
__device__ __forceinline__ void cpa16(uint32_t dst, const void* src)
{
    asm volatile("cp.async.cg.shared.global [%0], [%1], 16;" :: "r"(dst), "l"(src));
}
__device__ __forceinline__ void cpa_commit() { asm volatile("cp.async.commit_group;"); }
template<int N>
__device__ __forceinline__ void cpa_wait() { asm volatile("cp.async.wait_group %0;" :: "n"(N)); }

__device__ __forceinline__ void ldm_x4(uint32_t r[4], uint32_t addr)
{
    asm volatile("ldmatrix.sync.aligned.m8n8.x4.shared.b16 {%0,%1,%2,%3}, [%4];"
                 : "=r"(r[0]), "=r"(r[1]), "=r"(r[2]), "=r"(r[3]) : "r"(addr));
}
__device__ __forceinline__ void ldm_x4_t(uint32_t r[4], uint32_t addr)
{
    asm volatile("ldmatrix.sync.aligned.m8n8.x4.trans.shared.b16 {%0,%1,%2,%3}, [%4];"
                 : "=r"(r[0]), "=r"(r[1]), "=r"(r[2]), "=r"(r[3]) : "r"(addr));
}

__device__ __forceinline__ void mma_f16(float c[4], const uint32_t a[4], uint32_t b0, uint32_t b1)
{
    asm volatile(
        "mma.sync.aligned.m16n8k16.row.col.f32.f16.f16.f32 "
        "{%0,%1,%2,%3}, {%4,%5,%6,%7}, {%8,%9}, {%0,%1,%2,%3};"
        : "+f"(c[0]), "+f"(c[1]), "+f"(c[2]), "+f"(c[3])
        : "r"(a[0]), "r"(a[1]), "r"(a[2]), "r"(a[3]), "r"(b0), "r"(b1));
}

// ---------------- layernorm: optional fp32 out, optional half out ----------------
__global__ void ln_kernel(const float* __restrict__ x,
                          const float* __restrict__ g,
                          const float* __restrict__ b,
                          const float* __restrict__ resid,
                          float* __restrict__ outf,
                          __half* __restrict__ outh)
{
    const size_t row = blockIdx.x;
    const float4* xr = (const float4*)(x + row * (size_t)DIM);
    const int tid = threadIdx.x;
    float4 xv = xr[tid];

    float s  = xv.x + xv.y + xv.z + xv.w;
    float ss = xv.x*xv.x + xv.y*xv.y + xv.z*xv.z + xv.w*xv.w;

    #pragma unroll
    for (int o = 16; o > 0; o >>= 1) {
        s  += __shfl_xor_sync(0xffffffffu, s,  o);
        ss += __shfl_xor_sync(0xffffffffu, ss, o);
    }
    __shared__ float rs[8], rss[8];
    int wid = tid >> 5, lane = tid & 31;
    if (lane == 0) { rs[wid] = s; rss[wid] = ss; }
    __syncthreads();
    __shared__ float s_mean, s_rstd;
    if (tid == 0) {
        float ts = 0.f, tss = 0.f;
        #pragma unroll
        for (int i = 0; i < 8; i++) { ts += rs[i]; tss += rss[i]; }
        float mean = ts * (1.0f / DIM);
        float var  = tss * (1.0f / DIM) - mean * mean;
        s_mean = mean;
        s_rstd = rsqrtf(var + 1e-5f);
    }
    __syncthreads();
    const float mean = s_mean, rstd = s_rstd;

    const float4 gv = ((const float4*)g)[tid];
    const float4 bv = ((const float4*)b)[tid];
    float4 o4;
    o4.x = (xv.x - mean) * rstd * gv.x + bv.x;
    o4.y = (xv.y - mean) * rstd * gv.y + bv.y;
    o4.z = (xv.z - mean) * rstd * gv.z + bv.z;
    o4.w = (xv.w - mean) * rstd * gv.w + bv.w;
    if (resid) {
        const float4 rv = ((const float4*)(resid + row * (size_t)DIM))[tid];
        o4.x += rv.x; o4.y += rv.y; o4.z += rv.z; o4.w += rv.w;
    }
    if (outf) ((float4*)(outf + row * (size_t)DIM))[tid] = o4;
    if (outh) {
        __half2* oh = (__half2*)(outh + row * (size_t)DIM);
        oh[tid * 2 + 0] = __floats2half2_rn(o4.x, o4.y);
        oh[tid * 2 + 1] = __floats2half2_rn(o4.z, o4.w);
    }
}

// ---------------- permute (H,D,P) -> rows of [3D][D], half ----------------
__global__ void wtrans_kernel(const float* __restrict__ w, __half* __restrict__ o, int rowoff)
{
    int idx = blockIdx.x * blockDim.x + threadIdx.x;
    if (idx >= DIM * DIM) return;
    int p = idx & 63;
    int d = (idx >> 6) & 1023;
    int h = idx >> 16;
    o[(size_t)(rowoff + h * HP + p) * DIM + d] = __float2half(w[idx]);
}

// ---------------- tiled transpose: dst_h[c][r] = half(src[r][c]) ----------------
__global__ void transp_kernel(const float* __restrict__ src, __half* __restrict__ dst, int R, int C)
{
    __shared__ float t[32][33];
    int c0 = blockIdx.x * 32, r0 = blockIdx.y * 32;
    #pragma unroll
    for (int j = 0; j < 32; j += 8)
        t[threadIdx.y + j][threadIdx.x] = src[(size_t)(r0 + threadIdx.y + j) * C + c0 + threadIdx.x];
    __syncthreads();
    #pragma unroll
    for (int j = 0; j < 32; j += 8)
        dst[(size_t)(c0 + threadIdx.y + j) * R + r0 + threadIdx.x] = __float2half(t[threadIdx.x][threadIdx.y + j]);
}

// ---------------- rowsum -> inverse ----------------
__global__ void rowinv_kernel(const float* __restrict__ part, float* __restrict__ inv)
{
    int idx = blockIdx.x * blockDim.x + threadIdx.x;
    if (idx >= ROWS_ALL) return;
    const float4* p = (const float4*)(part + (size_t)idx * KTILES);
    float s = 0.f;
    #pragma unroll
    for (int i = 0; i < KTILES / 4; i++) {
        float4 v = p[i];
        s += v.x + v.y + v.z + v.w;
    }
    inv[idx] = 1.0f / s;
}

// ================= fp16 dense GEMM (NT): C[m,n] = sum_k A[m,k]*Bt[n,k] =================
// 128x128x32 tile, 3-stage cp.async, ldmatrix + m16n8k16. 8 warps (2x4), warp 64x32.
#define HG_LD     40                      // halves per row (32 data + 8 pad)
#define HG_STAGE  (128*HG_LD)             // halves per operand stage
#define HG_SMEM   (3 * 2 * HG_STAGE * 2)  // bytes = 61440

__global__ __launch_bounds__(256, 2) void hgemm(
    int M, int N, int K,
    const __half* __restrict__ A, int lda,
    const __half* __restrict__ Bt, int ldb,
    void* __restrict__ Cv, int ldc,
    int epi, const float* __restrict__ bias,
    const float* __restrict__ resid, int ldr, int out_half)
{
    extern __shared__ __half hsm[];
    __half* Asm = hsm;
    __half* Bsm = hsm + 3 * HG_STAGE;

    const int tid  = threadIdx.x;
    const int m0   = blockIdx.y * 128;
    const int n0   = blockIdx.x * 128;
    const int w    = tid >> 5, lane = tid & 31;
    const int lr   = lane >> 2, lc = lane & 3;
    const int wm   = (w & 1) * 64;
    const int wn   = (w >> 1) * 32;

    const int lrow = tid >> 1;
    const int lcol = (tid & 1) * 16;

    const int sel   = lane >> 3;
    const int off8  = (sel & 1) * 8;
    const int koff8 = (sel >> 1) * 8;
    const int lrow8 = lane & 7;

    float acc[4][4][4];
    #pragma unroll
    for (int i = 0; i < 4; i++)
        #pragma unroll
        for (int j = 0; j < 4; j++)
            #pragma unroll
            for (int q = 0; q < 4; q++) acc[i][j][q] = 0.f;

    auto load_stage = [&](int st, int k0) {
        __half* as = Asm + st * HG_STAGE;
        __half* bs = Bsm + st * HG_STAGE;
        #pragma unroll
        for (int i = 0; i < 2; i++) {
            int c = lcol + i * 8;
            cpa16(smem_u32(as + lrow * HG_LD + c), A  + (size_t)(m0 + lrow) * lda + k0 + c);
            cpa16(smem_u32(bs + lrow * HG_LD + c), Bt + (size_t)(n0 + lrow) * ldb + k0 + c);
        }
    };

    const int kiters = K >> 5;
    load_stage(0, 0);  cpa_commit();
    load_stage(1, 32); cpa_commit();

    for (int it = 0; it < kiters; it++) {
        cpa_wait<1>();
        __syncthreads();

        const int nxt = it + 2;
        if (nxt < kiters) load_stage(nxt % 3, nxt * 32);
        cpa_commit();

        const __half* as = Asm + (it % 3) * HG_STAGE;
        const __half* bs = Bsm + (it % 3) * HG_STAGE;

        #pragma unroll
        for (int kk = 0; kk < 32; kk += 16) {
            uint32_t af[4][4], bf[2][4];
            #pragma unroll
            for (int im = 0; im < 4; im++)
                ldm_x4(af[im], smem_u32(as + (wm + im * 16 + off8 + lrow8) * HG_LD + kk + koff8));
            #pragma unroll
            for (int j = 0; j < 2; j++)
                ldm_x4(bf[j], smem_u32(bs + (wn + j * 16 + off8 + lrow8) * HG_LD + kk + koff8));
            #pragma unroll
            for (int im = 0; im < 4; im++)
                #pragma unroll
                for (int j = 0; j < 2; j++) {
                    mma_f16(acc[im][2 * j + 0], af[im], bf[j][0], bf[j][2]);
                    mma_f16(acc[im][2 * j + 1], af[im], bf[j][1], bf[j][3]);
                }
        }
    }

    // epilogue
    #pragma unroll
    for (int im = 0; im < 4; im++) {
        const int r0 = m0 + wm + im * 16 + lr;
        const int r1 = r0 + 8;
        #pragma unroll
        for (int in = 0; in < 4; in++) {
            const int cb = n0 + wn + in * 8 + 2 * lc;
            const float* ac = acc[im][in];
            float b0 = 0.f, b1 = 0.f;
            if (epi != 0) { b0 = bias[cb]; b1 = bias[cb + 1]; }

            float v0 = ac[0], v1 = ac[1];
            if (epi == 1) { v0 = gelu_exact(v0 + b0); v1 = gelu_exact(v1 + b1); }
            else if (epi == 2) {
                const float2 rv = *(const float2*)(resid + (size_t)r0 * ldr + cb);
                v0 += b0 + rv.x; v1 += b1 + rv.y;
            }
            float v2 = ac[2], v3 = ac[3];
            if (epi == 1) { v2 = gelu_exact(v2 + b0); v3 = gelu_exact(v3 + b1); }
            else if (epi == 2) {
                const float2 rv = *(const float2*)(resid + (size_t)r1 * ldr + cb);
                v2 += b0 + rv.x; v3 += b1 + rv.y;
            }
            if (out_half) {
                __half* C = (__half*)Cv;
                *(__half2*)(C + (size_t)r0 * ldc + cb) = __floats2half2_rn(v0, v1);
                *(__half2*)(C + (size_t)r1 * ldc + cb) = __floats2half2_rn(v2, v3);
            } else {
                float* C = (float*)Cv;
                *(float2*)(C + (size_t)r0 * ldc + cb) = make_float2(v0, v1);
                *(float2*)(C + (size_t)r1 * ldc + cb) = make_float2(v2, v3);
            }
        }
    }
}

// ================= scores: p_un(h) = exp(K.Q^T/8) + partial row sums ==========
#define SC_LD 72

__global__ __launch_bounds__(256, 2) void scores_kernel(
    const __half* __restrict__ QKVh, __half* __restrict__ Ph, float* __restrict__ part)
{
    __shared__ __half sA[128 * SC_LD];
    __shared__ __half sB[128 * SC_LD];
    __shared__ float s_part[4][128];

    const int z  = blockIdx.z;
    const int bb = z >> 4, hh = z & 15;
    const __half* A = QKVh + DIM + (size_t)bb * TT * D3 + hh * HP;   // K proj
    const __half* B = QKVh +        (size_t)bb * TT * D3 + hh * HP;  // Q proj
    __half* C = Ph + (size_t)z * TT * TT;

    const int tid  = threadIdx.x;
    const int m0   = blockIdx.y * 128;
    const int n0   = blockIdx.x * 128;
    const int w    = tid >> 5, lane = tid & 31;
    const int lr   = lane >> 2, lc = lane & 3;
    const int wm   = (w & 1) * 64;
    const int wn   = (w >> 1) * 32;
    const int wni  = w >> 1;

    const int sel   = lane >> 3;
    const int off8  = (sel & 1) * 8;
    const int koff8 = (sel >> 1) * 8;
    const int lrow8 = lane & 7;

    #pragma unroll
    for (int i = 0; i < 4; i++) {
        int g = tid + i * 256;
        int row = g >> 3, c8 = (g & 7) * 8;
        cpa16(smem_u32(sA + row * SC_LD + c8), A + (size_t)(m0 + row) * D3 + c8);
        cpa16(smem_u32(sB + row * SC_LD + c8), B + (size_t)(n0 + row) * D3 + c8);
    }
    cpa_commit();
    cpa_wait<0>();
    __syncthreads();

    float acc[4][4][4];
    #pragma unroll
    for (int i = 0; i < 4; i++)
        #pragma unroll
        for (int j = 0; j < 4; j++)
            #pragma unroll
            for (int q = 0; q < 4; q++) acc[i][j][q] = 0.f;

    #pragma unroll
    for (int kk = 0; kk < 64; kk += 16) {
        uint32_t af[4][4], bf[2][4];
        #pragma unroll
        for (int im = 0; im < 4; im++)
            ldm_x4(af[im], smem_u32(sA + (wm + im * 16 + off8 + lrow8) * SC_LD + kk + koff8));
        #pragma unroll
        for (int j = 0; j < 2; j++)
            ldm_x4(bf[j], smem_u32(sB + (wn + j * 16 + off8 + lrow8) * SC_LD + kk + koff8));
        #pragma unroll
        for (int im = 0; im < 4; im++)
            #pragma unroll
            for (int j = 0; j < 2; j++) {
                mma_f16(acc[im][2 * j + 0], af[im], bf[j][0], bf[j][2]);
                mma_f16(acc[im][2 * j + 1], af[im], bf[j][1], bf[j][3]);
            }
    }

    // epilogue: exp, half store, deterministic partial row sums
    #pragma unroll
    for (int im = 0; im < 4; im++) {
        const int r0 = m0 + wm + im * 16 + lr;
        const int r1 = r0 + 8;
        float sum0 = 0.f, sum1 = 0.f;
        #pragma unroll
        for (int in = 0; in < 4; in++) {
            const int cb = n0 + wn + in * 8 + 2 * lc;
            float* ac = acc[im][in];
            float e0 = __expf(0.125f * ac[0]);
            float e1 = __expf(0.125f * ac[1]);
            float e2 = __expf(0.125f * ac[2]);
            float e3 = __expf(0.125f * ac[3]);
            sum0 += e0 + e1;
            sum1 += e2 + e3;
            *(__half2*)(C + (size_t)r0 * TT + cb) = __floats2half2_rn(e0, e1);
            *(__half2*)(C + (size_t)r1 * TT + cb) = __floats2half2_rn(e2, e3);
        }
        sum0 += __shfl_xor_sync(0xffffffffu, sum0, 1);
        sum0 += __shfl_xor_sync(0xffffffffu, sum0, 2);
        sum1 += __shfl_xor_sync(0xffffffffu, sum1, 1);
        sum1 += __shfl_xor_sync(0xffffffffu, sum1, 2);
        if (lc == 0) {
            s_part[wni][wm + im * 16 + lr]     = sum0;
            s_part[wni][wm + im * 16 + 8 + lr] = sum1;
        }
    }
    __syncthreads();
    if (tid < 128) {
        float t = s_part[0][tid] + s_part[1][tid] + s_part[2][tid] + s_part[3][tid];
        part[((size_t)z * TT + m0 + tid) * KTILES + blockIdx.x] = t;
    }
}

// ================= AV: nv = (p_un @ V) * inv; p_norm fp32 -> attn out =================
// tile 128x64x32. A = p_un fp16 (ldmatrix), B = V half via ldmatrix.trans.
#define AV_ALD    40                        // halves per A row (32 + 8 pad)
#define AV_ASTG   (128*AV_ALD)              // halves
#define AV_BLD    72                        // halves per B row (64 + 8 pad)
#define AV_BSTG   (32*AV_BLD)               // halves
#define AV_SMEM   (3 * (AV_ASTG + AV_BSTG) * 2)   // 44544 B

__global__ __launch_bounds__(256, 2) void av_kernel(
    const __half* __restrict__ Ph, const __half* __restrict__ QKVh,
    const float* __restrict__ inv, __half* __restrict__ nvh,
    float* __restrict__ attn)
{
    extern __shared__ __half avh[];
    __half* Ah = avh;
    __half* Bh = avh + 3 * AV_ASTG;

    const int z  = blockIdx.y;
    const int bb = z >> 4, hh = z & 15;
    const __half* Pun = Ph + (size_t)z * TT * TT;
    const __half* V = QKVh + 2 * DIM + (size_t)bb * TT * D3 + hh * HP;
    __half* C = nvh + (size_t)bb * TT * DIM + hh * HP;
    float* Pout = attn + (size_t)z * TT * TT;

    const int tid  = threadIdx.x;
    const int m0   = blockIdx.x * 128;
    const int w    = tid >> 5, lane = tid & 31;
    const int lr   = lane >> 2, lc = lane & 3;
    const int wm   = (w & 3) * 32;      // 4 warps in m
    const int wn   = (w >> 2) * 32;     // 2 warps in n

    const int sel   = lane >> 3;
    const int a_r8  = (sel & 1) * 8;    // A ldmatrix row offset
    const int a_k8  = (sel >> 1) * 8;   // A ldmatrix k offset
    const int b_k8  = (sel & 1) * 8;    // B trans k offset
    const int b_n8  = (sel >> 1) * 8;   // B trans n offset
    const int lrow8 = lane & 7;

    // A load: row tid>>1, 2 chunks of 8 halves at (tid&1)*16 + {0,8}
    const int prow = tid >> 1;
    const int pc   = (tid & 1) * 16;
    // B load: row tid>>3 (0..31), chunk (tid&7)*8
    const int brow = tid >> 3;
    const int bc8  = (tid & 7) * 8;

    const float pinv = inv[(size_t)z * TT + m0 + prow];

    float acc[2][4][4];
    #pragma unroll
    for (int i = 0; i < 2; i++)
        #pragma unroll
        for (int j = 0; j < 4; j++)
            #pragma unroll
            for (int q = 0; q < 4; q++) acc[i][j][q] = 0.f;

    auto load_stage = [&](int st, int k0) {
        __half* as = Ah + st * AV_ASTG;
        const __half* src = Pun + (size_t)(m0 + prow) * TT + k0 + pc;
        cpa16(smem_u32(as + prow * AV_ALD + pc),     src);
        cpa16(smem_u32(as + prow * AV_ALD + pc + 8), src + 8);
        __half* bs = Bh + st * AV_BSTG;
        cpa16(smem_u32(bs + brow * AV_BLD + bc8), V + (size_t)(k0 + brow) * D3 + bc8);
    };

    const int kiters = TT >> 5;   // 64
    load_stage(0, 0);  cpa_commit();
    load_stage(1, 32); cpa_commit();

    for (int it = 0; it < kiters; it++) {
        cpa_wait<1>();
        __syncthreads();

        const int nxt = it + 2;
        if (nxt < kiters) load_stage(nxt % 3, nxt * 32);
        cpa_commit();

        const __half* as = Ah + (it % 3) * AV_ASTG;
        const __half* bs = Bh + (it % 3) * AV_BSTG;

        #pragma unroll
        for (int kk = 0; kk < 32; kk += 16) {
            uint32_t af[2][4], bw[2][4];
            #pragma unroll
            for (int im = 0; im < 2; im++)
                ldm_x4(af[im], smem_u32(as + (wm + im * 16 + a_r8 + lrow8) * AV_ALD + kk + a_k8));
            #pragma unroll
            for (int j = 0; j < 2; j++)
                ldm_x4_t(bw[j], smem_u32(bs + (kk + b_k8 + lrow8) * AV_BLD + wn + j * 16 + b_n8));
            #pragma unroll
            for (int im = 0; im < 2; im++)
                #pragma unroll
                for (int j = 0; j < 2; j++) {
                    mma_f16(acc[im][2 * j + 0], af[im], bw[j][0], bw[j][1]);
                    mma_f16(acc[im][2 * j + 1], af[im], bw[j][2], bw[j][3]);
                }
        }

        // p_norm write-back: this thread's 16 halves -> fp32 out
        {
            const __half2* srcp = (const __half2*)(as + prow * AV_ALD + pc);
            float* dst = Pout + (size_t)(m0 + prow) * TT + it * 32 + pc;
            #pragma unroll
            for (int i = 0; i < 4; i++) {
                float2 v0 = __half22float2(srcp[2 * i]);
                float2 v1 = __half22float2(srcp[2 * i + 1]);
                *(float4*)(dst + 4 * i) =
                    make_float4(v0.x * pinv, v0.y * pinv, v1.x * pinv, v1.y * pinv);
            }
        }
    }

    // epilogue: nv_h = half(acc * inv[row])
    #pragma unroll
    for (int im = 0; im < 2; im++) {
        const int r0 = m0 + wm + im * 16 + lr;
        const int r1 = r0 + 8;
        const float i0 = inv[(size_t)z * TT + r0];
        const float i1 = inv[(size_t)z * TT + r1];
        #pragma unroll
        for (int in = 0; in < 4; in++) {
            const int cb = wn + in * 8 + 2 * lc;
            const float* ac = acc[im][in];
            *(__half2*)(C + (size_t)r0 * DIM + cb) = __floats2half2_rn(ac[0] * i0, ac[1] * i0);
            *(__half2*)(C + (size_t)r1 * DIM + cb) = __floats2half2_rn(ac[2] * i1, ac[3] * i1);
        }
    }
}

// ---------------- host launch ----------------
extern "C" void kernel_launch(void* const* d_in, const int* in_sizes, int n_in,
                              void* d_out, int out_size)
{
    const float* X      = (const float*)d_in[0];
    const float* WQ     = (const float*)d_in[1];
    const float* WK     = (const float*)d_in[2];
    const float* WV     = (const float*)d_in[3];
    const float* WO     = (const float*)d_in[4];
    const float* attn_g = (const float*)d_in[5];
    const float* attn_b = (const float*)d_in[6];
    const float* ff_g   = (const float*)d_in[7];
    const float* ff_b   = (const float*)d_in[8];
    const float* fW1    = (const float*)d_in[9];
    const float* fb1    = (const float*)d_in[10];
    const float* fW2    = (const float*)d_in[11];
    const float* fb2    = (const float*)d_in[12];
    float* out0 = (float*)d_out;

    __half *nXh, *QKVh, *nvh, *preffh, *hiddenh, *Wth, *WOh, *fW1h, *fW2h, *Ph;
    float *seq, *preff, *part, *inv, *Sfb;
    cudaGetSymbolAddress((void**)&nXh,     g_nXh);
    cudaGetSymbolAddress((void**)&QKVh,    g_QKVh);
    cudaGetSymbolAddress((void**)&nvh,     g_nvh);
    cudaGetSymbolAddress((void**)&seq,     g_seq);
    cudaGetSymbolAddress((void**)&preff,   g_preff);
    cudaGetSymbolAddress((void**)&preffh,  g_preffh);
    cudaGetSymbolAddress((void**)&hiddenh, g_hiddenh);
    cudaGetSymbolAddress((void**)&Wth,     g_Wth);
    cudaGetSymbolAddress((void**)&WOh,     g_WOh);
    cudaGetSymbolAddress((void**)&fW1h,    g_fW1h);
    cudaGetSymbolAddress((void**)&fW2h,    g_fW2h);
    cudaGetSymbolAddress((void**)&Ph,      g_Ph);
    cudaGetSymbolAddress((void**)&part,    g_part);
    cudaGetSymbolAddress((void**)&inv,     g_inv);
    cudaGetSymbolAddress((void**)&Sfb,     g_Sfb);

    cudaFuncSetAttribute(hgemm, cudaFuncAttributeMaxDynamicSharedMemorySize, HG_SMEM);
    cudaFuncSetAttribute(av_kernel, cudaFuncAttributeMaxDynamicSharedMemorySize, AV_SMEM);

    const long long xel     = (long long)BT * DIM;
    const long long attn_el = (long long)NZ * TT * TT;
    float* attn = ((long long)out_size >= xel + attn_el) ? (out0 + xel) : Sfb;

    // 1) nX_h = half(LN(X))
    ln_kernel<<<BT, 256>>>(X, attn_g, attn_b, nullptr, nullptr, nXh);

    // 2) weights -> half, transposed layouts
    wtrans_kernel<<<(DIM * DIM + 255) / 256, 256>>>(WQ, Wth, 0);
    wtrans_kernel<<<(DIM * DIM + 255) / 256, 256>>>(WK, Wth, DIM);
    wtrans_kernel<<<(DIM * DIM + 255) / 256, 256>>>(WV, Wth, 2 * DIM);
    transp_kernel<<<dim3(DIM / 32, DIM / 32), dim3(32, 8)>>>(WO,  WOh,  DIM, DIM);
    transp_kernel<<<dim3(FFD / 32, DIM / 32), dim3(32, 8)>>>(fW1, fW1h, DIM, FFD);
    transp_kernel<<<dim3(DIM / 32, FFD / 32), dim3(32, 8)>>>(fW2, fW2h, FFD, DIM);

    // 3) QKV_h = nX_h @ Wt^T (half out)
    hgemm<<<dim3(D3 / 128, BT / 128), 256, HG_SMEM>>>(
        BT, D3, DIM, nXh, DIM, Wth, DIM, QKVh, D3, 0, nullptr, nullptr, 0, 1);

    // 4) p_un(h) = exp(scores), partial sums
    scores_kernel<<<dim3(KTILES, TT / 128, NZ), 256>>>(QKVh, Ph, part);

    // 5) inv = 1 / rowsum
    rowinv_kernel<<<(ROWS_ALL + 255) / 256, 256>>>(part, inv);

    // 6) AV (fp16 probs) + p_norm fp32 out + nv_h
    av_kernel<<<dim3(TT / 128, NZ), 256, AV_SMEM>>>(Ph, QKVh, inv, nvh, attn);

    // 7) seq = nv_h @ WO^T (fp32 out)
    hgemm<<<dim3(DIM / 128, BT / 128), 256, HG_SMEM>>>(
        BT, DIM, DIM, nvh, DIM, WOh, DIM, seq, DIM, 0, nullptr, nullptr, 0, 0);

    // 8) pre_ff = X + LN(seq): fp32 + half copies
    ln_kernel<<<BT, 256>>>(seq, ff_g, ff_b, X, preff, preffh);

    // 9) hidden_h = half(gelu(preff_h @ fW1^T + fb1))
    hgemm<<<dim3(FFD / 128, BT / 128), 256, HG_SMEM>>>(
        BT, FFD, DIM, preffh, DIM, fW1h, DIM, hiddenh, FFD, 1, fb1, nullptr, 0, 1);

    // 10) out = hidden_h @ fW2^T + fb2 + preff (fp32)
    hgemm<<<dim3(DIM / 128, BT / 128), 256, HG_SMEM>>>(
        BT, DIM, FFD, hiddenh, FFD, fW2h, FFD, out0, DIM, 2, fb2, preff, DIM, 0);
}

// round 10
// speedup vs baseline: 4.7781x; 1.0014x over previous
#include <cuda_runtime.h>
#include <cuda_fp16.h>
#include <math.h>
#include <stdint.h>

#define BB    4
#define TT    2048
#define DIM   1024
#define NH    16
#define HP    64
#define FFD   4096
#define BT    (BB*TT)          // 8192
#define D3    (3*DIM)          // 3072
#define NZ    (BB*NH)          // 64 batch-heads
#define ROWS_ALL (NZ*TT)       // 131072
#define KTILES (TT/128)        // 16

// ---------------- scratch ----------------
__device__ __half g_nXh[(size_t)BT*DIM];
__device__ __half g_QKVh[(size_t)BT*D3];
__device__ __half g_nvh[(size_t)BT*DIM];
__device__ float  g_seq[(size_t)BT*DIM];
__device__ float  g_preff[(size_t)BT*DIM];
__device__ __half g_preffh[(size_t)BT*DIM];
__device__ __half g_hiddenh[(size_t)BT*FFD];
__device__ __half g_Wth[(size_t)D3*DIM];         // QKV weights permuted+transposed [3D][D]
__device__ __half g_WOh[(size_t)DIM*DIM];        // WO^T [D][D]
__device__ __half g_fW1h[(size_t)FFD*DIM];       // fW1^T [FF][D]
__device__ __half g_fW2h[(size_t)DIM*FFD];       // fW2^T [D][FF]
__device__ __half g_Ph[(size_t)NZ*TT*TT];        // unnormalized probs (fp16)
__device__ float  g_part[(size_t)ROWS_ALL*KTILES];
__device__ float  g_inv[(size_t)ROWS_ALL];
__device__ float  g_Sfb[(size_t)NZ*TT*TT];       // attn fallback if d_out lacks room

// ---------------- helpers ----------------
__device__ __forceinline__ float gelu_exact(float x)
{
    return 0.5f * x * (1.0f + erff(x * 0.70710678118654752440f));
}

__device__ __forceinline__ uint32_t smem_u32(const void* p)
{
    return (uint32_t)__cvta_generic_to_shared(p);
}
__device__ __forceinline__ void cpa16(uint32_t dst, const void* src)
{
    asm volatile("cp.async.cg.shared.global [%0], [%1], 16;" :: "r"(dst), "l"(src));
}
__device__ __forceinline__ void cpa_commit() { asm volatile("cp.async.commit_group;"); }
template<int N>
__device__ __forceinline__ void cpa_wait() { asm volatile("cp.async.wait_group %0;" :: "n"(N)); }

__device__ __forceinline__ void ldm_x4(uint32_t r[4], uint32_t addr)
{
    asm volatile("ldmatrix.sync.aligned.m8n8.x4.shared.b16 {%0,%1,%2,%3}, [%4];"
                 : "=r"(r[0]), "=r"(r[1]), "=r"(r[2]), "=r"(r[3]) : "r"(addr));
}
__device__ __forceinline__ void ldm_x4_t(uint32_t r[4], uint32_t addr)
{
    asm volatile("ldmatrix.sync.aligned.m8n8.x4.trans.shared.b16 {%0,%1,%2,%3}, [%4];"
                 : "=r"(r[0]), "=r"(r[1]), "=r"(r[2]), "=r"(r[3]) : "r"(addr));
}

__device__ __forceinline__ void mma_f16(float c[4], const uint32_t a[4], uint32_t b0, uint32_t b1)
{
    asm volatile(
        "mma.sync.aligned.m16n8k16.row.col.f32.f16.f16.f32 "
        "{%0,%1,%2,%3}, {%4,%5,%6,%7}, {%8,%9}, {%0,%1,%2,%3};"
        : "+f"(c[0]), "+f"(c[1]), "+f"(c[2]), "+f"(c[3])
        : "r"(a[0]), "r"(a[1]), "r"(a[2]), "r"(a[3]), "r"(b0), "r"(b1));
}

// ---------------- layernorm: optional fp32 out, optional half out ----------------
__global__ void ln_kernel(const float* __restrict__ x,
                          const float* __restrict__ g,
                          const float* __restrict__ b,
                          const float* __restrict__ resid,
                          float* __restrict__ outf,
                          __half* __restrict__ outh)
{
    const size_t row = blockIdx.x;
    const float4* xr = (const float4*)(x + row * (size_t)DIM);
    const int tid = threadIdx.x;
    float4 xv = xr[tid];

    float s  = xv.x + xv.y + xv.z + xv.w;
    float ss = xv.x*xv.x + xv.y*xv.y + xv.z*xv.z + xv.w*xv.w;

    #pragma unroll
    for (int o = 16; o > 0; o >>= 1) {
        s  += __shfl_xor_sync(0xffffffffu, s,  o);
        ss += __shfl_xor_sync(0xffffffffu, ss, o);
    }
    __shared__ float rs[8], rss[8];
    int wid = tid >> 5, lane = tid & 31;
    if (lane == 0) { rs[wid] = s; rss[wid] = ss; }
    __syncthreads();
    __shared__ float s_mean, s_rstd;
    if (tid == 0) {
        float ts = 0.f, tss = 0.f;
        #pragma unroll
        for (int i = 0; i < 8; i++) { ts += rs[i]; tss += rss[i]; }
        float mean = ts * (1.0f / DIM);
        float var  = tss * (1.0f / DIM) - mean * mean;
        s_mean = mean;
        s_rstd = rsqrtf(var + 1e-5f);
    }
    __syncthreads();
    const float mean = s_mean, rstd = s_rstd;

    const float4 gv = ((const float4*)g)[tid];
    const float4 bv = ((const float4*)b)[tid];
    float4 o4;
    o4.x = (xv.x - mean) * rstd * gv.x + bv.x;
    o4.y = (xv.y - mean) * rstd * gv.y + bv.y;
    o4.z = (xv.z - mean) * rstd * gv.z + bv.z;
    o4.w = (xv.w - mean) * rstd * gv.w + bv.w;
    if (resid) {
        const float4 rv = ((const float4*)(resid + row * (size_t)DIM))[tid];
        o4.x += rv.x; o4.y += rv.y; o4.z += rv.z; o4.w += rv.w;
    }
    if (outf) ((float4*)(outf + row * (size_t)DIM))[tid] = o4;
    if (outh) {
        __half2* oh = (__half2*)(outh + row * (size_t)DIM);
        oh[tid * 2 + 0] = __floats2half2_rn(o4.x, o4.y);
        oh[tid * 2 + 1] = __floats2half2_rn(o4.z, o4.w);
    }
}

// ---------------- permute (H,D,P) -> rows of [3D][D], half ----------------
__global__ void wtrans_kernel(const float* __restrict__ w, __half* __restrict__ o, int rowoff)
{
    int idx = blockIdx.x * blockDim.x + threadIdx.x;
    if (idx >= DIM * DIM) return;
    int p = idx & 63;
    int d = (idx >> 6) & 1023;
    int h = idx >> 16;
    o[(size_t)(rowoff + h * HP + p) * DIM + d] = __float2half(w[idx]);
}

// ---------------- tiled transpose: dst_h[c][r] = half(src[r][c]) ----------------
__global__ void transp_kernel(const float* __restrict__ src, __half* __restrict__ dst, int R, int C)
{
    __shared__ float t[32][33];
    int c0 = blockIdx.x * 32, r0 = blockIdx.y * 32;
    #pragma unroll
    for (int j = 0; j < 32; j += 8)
        t[threadIdx.y + j][threadIdx.x] = src[(size_t)(r0 + threadIdx.y + j) * C + c0 + threadIdx.x];
    __syncthreads();
    #pragma unroll
    for (int j = 0; j < 32; j += 8)
        dst[(size_t)(c0 + threadIdx.y + j) * R + r0 + threadIdx.x] = __float2half(t[threadIdx.x][threadIdx.y + j]);
}

// ---------------- rowsum -> inverse ----------------
__global__ void rowinv_kernel(const float* __restrict__ part, float* __restrict__ inv)
{
    int idx = blockIdx.x * blockDim.x + threadIdx.x;
    if (idx >= ROWS_ALL) return;
    const float4* p = (const float4*)(part + (size_t)idx * KTILES);
    float s = 0.f;
    #pragma unroll
    for (int i = 0; i < KTILES / 4; i++) {
        float4 v = p[i];
        s += v.x + v.y + v.z + v.w;
    }
    inv[idx] = 1.0f / s;
}

// ================= fp16 dense GEMM (NT): C[m,n] = sum_k A[m,k]*Bt[n,k] =================
// 128x128x32 tile, 3-stage cp.async, ldmatrix + m16n8k16. 8 warps (2x4), warp 64x32.
#define HG_LD     40                      // halves per row (32 data + 8 pad)
#define HG_STAGE  (128*HG_LD)             // halves per operand stage
#define HG_SMEM   (3 * 2 * HG_STAGE * 2)  // bytes = 61440

__global__ __launch_bounds__(256, 2) void hgemm(
    int M, int N, int K,
    const __half* __restrict__ A, int lda,
    const __half* __restrict__ Bt, int ldb,
    void* __restrict__ Cv, int ldc,
    int epi, const float* __restrict__ bias,
    const float* __restrict__ resid, int ldr, int out_half)
{
    extern __shared__ __half hsm[];
    __half* Asm = hsm;
    __half* Bsm = hsm + 3 * HG_STAGE;

    const int tid  = threadIdx.x;
    const int m0   = blockIdx.y * 128;
    const int n0   = blockIdx.x * 128;
    const int w    = tid >> 5, lane = tid & 31;
    const int lr   = lane >> 2, lc = lane & 3;
    const int wm   = (w & 1) * 64;
    const int wn   = (w >> 1) * 32;

    const int lrow = tid >> 1;
    const int lcol = (tid & 1) * 16;

    const int sel   = lane >> 3;
    const int off8  = (sel & 1) * 8;
    const int koff8 = (sel >> 1) * 8;
    const int lrow8 = lane & 7;

    float acc[4][4][4];
    #pragma unroll
    for (int i = 0; i < 4; i++)
        #pragma unroll
        for (int j = 0; j < 4; j++)
            #pragma unroll
            for (int q = 0; q < 4; q++) acc[i][j][q] = 0.f;

    auto load_stage = [&](int st, int k0) {
        __half* as = Asm + st * HG_STAGE;
        __half* bs = Bsm + st * HG_STAGE;
        #pragma unroll
        for (int i = 0; i < 2; i++) {
            int c = lcol + i * 8;
            cpa16(smem_u32(as + lrow * HG_LD + c), A  + (size_t)(m0 + lrow) * lda + k0 + c);
            cpa16(smem_u32(bs + lrow * HG_LD + c), Bt + (size_t)(n0 + lrow) * ldb + k0 + c);
        }
    };

    const int kiters = K >> 5;
    load_stage(0, 0);  cpa_commit();
    load_stage(1, 32); cpa_commit();

    for (int it = 0; it < kiters; it++) {
        cpa_wait<1>();
        __syncthreads();

        const int nxt = it + 2;
        if (nxt < kiters) load_stage(nxt % 3, nxt * 32);
        cpa_commit();

        const __half* as = Asm + (it % 3) * HG_STAGE;
        const __half* bs = Bsm + (it % 3) * HG_STAGE;

        #pragma unroll
        for (int kk = 0; kk < 32; kk += 16) {
            uint32_t af[4][4], bf[2][4];
            #pragma unroll
            for (int im = 0; im < 4; im++)
                ldm_x4(af[im], smem_u32(as + (wm + im * 16 + off8 + lrow8) * HG_LD + kk + koff8));
            #pragma unroll
            for (int j = 0; j < 2; j++)
                ldm_x4(bf[j], smem_u32(bs + (wn + j * 16 + off8 + lrow8) * HG_LD + kk + koff8));
            #pragma unroll
            for (int im = 0; im < 4; im++)
                #pragma unroll
                for (int j = 0; j < 2; j++) {
                    mma_f16(acc[im][2 * j + 0], af[im], bf[j][0], bf[j][2]);
                    mma_f16(acc[im][2 * j + 1], af[im], bf[j][1], bf[j][3]);
                }
        }
    }

    // epilogue
    #pragma unroll
    for (int im = 0; im < 4; im++) {
        const int r0 = m0 + wm + im * 16 + lr;
        const int r1 = r0 + 8;
        #pragma unroll
        for (int in = 0; in < 4; in++) {
            const int cb = n0 + wn + in * 8 + 2 * lc;
            const float* ac = acc[im][in];
            float b0 = 0.f, b1 = 0.f;
            if (epi != 0) { b0 = bias[cb]; b1 = bias[cb + 1]; }

            float v0 = ac[0], v1 = ac[1];
            if (epi == 1) { v0 = gelu_exact(v0 + b0); v1 = gelu_exact(v1 + b1); }
            else if (epi == 2) {
                const float2 rv = *(const float2*)(resid + (size_t)r0 * ldr + cb);
                v0 += b0 + rv.x; v1 += b1 + rv.y;
            }
            float v2 = ac[2], v3 = ac[3];
            if (epi == 1) { v2 = gelu_exact(v2 + b0); v3 = gelu_exact(v3 + b1); }
            else if (epi == 2) {
                const float2 rv = *(const float2*)(resid + (size_t)r1 * ldr + cb);
                v2 += b0 + rv.x; v3 += b1 + rv.y;
            }
            if (out_half) {
                __half* C = (__half*)Cv;
                *(__half2*)(C + (size_t)r0 * ldc + cb) = __floats2half2_rn(v0, v1);
                *(__half2*)(C + (size_t)r1 * ldc + cb) = __floats2half2_rn(v2, v3);
            } else {
                float* C = (float*)Cv;
                *(float2*)(C + (size_t)r0 * ldc + cb) = make_float2(v0, v1);
                *(float2*)(C + (size_t)r1 * ldc + cb) = make_float2(v2, v3);
            }
        }
    }
}

// ================= scores: p_un(h) = exp(K.Q^T/8) + partial row sums ==========
#define SC_LD 72

__global__ __launch_bounds__(256, 2) void scores_kernel(
    const __half* __restrict__ QKVh, __half* __restrict__ Ph, float* __restrict__ part)
{
    __shared__ __half sA[128 * SC_LD];
    __shared__ __half sB[128 * SC_LD];
    __shared__ float s_part[4][128];

    const int z  = blockIdx.z;
    const int bb = z >> 4, hh = z & 15;
    const __half* A = QKVh + DIM + (size_t)bb * TT * D3 + hh * HP;   // K proj
    const __half* B = QKVh +        (size_t)bb * TT * D3 + hh * HP;  // Q proj
    __half* C = Ph + (size_t)z * TT * TT;

    const int tid  = threadIdx.x;
    const int m0   = blockIdx.y * 128;
    const int n0   = blockIdx.x * 128;
    const int w    = tid >> 5, lane = tid & 31;
    const int lr   = lane >> 2, lc = lane & 3;
    const int wm   = (w & 1) * 64;
    const int wn   = (w >> 1) * 32;
    const int wni  = w >> 1;

    const int sel   = lane >> 3;
    const int off8  = (sel & 1) * 8;
    const int koff8 = (sel >> 1) * 8;
    const int lrow8 = lane & 7;

    #pragma unroll
    for (int i = 0; i < 4; i++) {
        int g = tid + i * 256;
        int row = g >> 3, c8 = (g & 7) * 8;
        cpa16(smem_u32(sA + row * SC_LD + c8), A + (size_t)(m0 + row) * D3 + c8);
        cpa16(smem_u32(sB + row * SC_LD + c8), B + (size_t)(n0 + row) * D3 + c8);
    }
    cpa_commit();
    cpa_wait<0>();
    __syncthreads();

    float acc[4][4][4];
    #pragma unroll
    for (int i = 0; i < 4; i++)
        #pragma unroll
        for (int j = 0; j < 4; j++)
            #pragma unroll
            for (int q = 0; q < 4; q++) acc[i][j][q] = 0.f;

    #pragma unroll
    for (int kk = 0; kk < 64; kk += 16) {
        uint32_t af[4][4], bf[2][4];
        #pragma unroll
        for (int im = 0; im < 4; im++)
            ldm_x4(af[im], smem_u32(sA + (wm + im * 16 + off8 + lrow8) * SC_LD + kk + koff8));
        #pragma unroll
        for (int j = 0; j < 2; j++)
            ldm_x4(bf[j], smem_u32(sB + (wn + j * 16 + off8 + lrow8) * SC_LD + kk + koff8));
        #pragma unroll
        for (int im = 0; im < 4; im++)
            #pragma unroll
            for (int j = 0; j < 2; j++) {
                mma_f16(acc[im][2 * j + 0], af[im], bf[j][0], bf[j][2]);
                mma_f16(acc[im][2 * j + 1], af[im], bf[j][1], bf[j][3]);
            }
    }

    // epilogue: exp, half store, deterministic partial row sums
    #pragma unroll
    for (int im = 0; im < 4; im++) {
        const int r0 = m0 + wm + im * 16 + lr;
        const int r1 = r0 + 8;
        float sum0 = 0.f, sum1 = 0.f;
        #pragma unroll
        for (int in = 0; in < 4; in++) {
            const int cb = n0 + wn + in * 8 + 2 * lc;
            float* ac = acc[im][in];
            float e0 = __expf(0.125f * ac[0]);
            float e1 = __expf(0.125f * ac[1]);
            float e2 = __expf(0.125f * ac[2]);
            float e3 = __expf(0.125f * ac[3]);
            sum0 += e0 + e1;
            sum1 += e2 + e3;
            *(__half2*)(C + (size_t)r0 * TT + cb) = __floats2half2_rn(e0, e1);
            *(__half2*)(C + (size_t)r1 * TT + cb) = __floats2half2_rn(e2, e3);
        }
        sum0 += __shfl_xor_sync(0xffffffffu, sum0, 1);
        sum0 += __shfl_xor_sync(0xffffffffu, sum0, 2);
        sum1 += __shfl_xor_sync(0xffffffffu, sum1, 1);
        sum1 += __shfl_xor_sync(0xffffffffu, sum1, 2);
        if (lc == 0) {
            s_part[wni][wm + im * 16 + lr]     = sum0;
            s_part[wni][wm + im * 16 + 8 + lr] = sum1;
        }
    }
    __syncthreads();
    if (tid < 128) {
        float t = s_part[0][tid] + s_part[1][tid] + s_part[2][tid] + s_part[3][tid];
        part[((size_t)z * TT + m0 + tid) * KTILES + blockIdx.x] = t;
    }
}

// ================= AV: nv = (p_un @ V) * inv; p_norm fp32 -> attn out =================
// tile 128x64x32. A = p_un fp16 (ldmatrix), B = V half via ldmatrix.trans.
#define AV_ALD    40                        // halves per A row (32 + 8 pad)
#define AV_ASTG   (128*AV_ALD)              // halves
#define AV_BLD    72                        // halves per B row (64 + 8 pad)
#define AV_BSTG   (32*AV_BLD)               // halves
#define AV_SMEM   (3 * (AV_ASTG + AV_BSTG) * 2)   // 44544 B

__global__ __launch_bounds__(256, 2) void av_kernel(
    const __half* __restrict__ Ph, const __half* __restrict__ QKVh,
    const float* __restrict__ inv, __half* __restrict__ nvh,
    float* __restrict__ attn)
{
    extern __shared__ __half avh[];
    __half* Ah = avh;
    __half* Bh = avh + 3 * AV_ASTG;

    const int z  = blockIdx.y;
    const int bb = z >> 4, hh = z & 15;
    const __half* Pun = Ph + (size_t)z * TT * TT;
    const __half* V = QKVh + 2 * DIM + (size_t)bb * TT * D3 + hh * HP;
    __half* C = nvh + (size_t)bb * TT * DIM + hh * HP;
    float* Pout = attn + (size_t)z * TT * TT;

    const int tid  = threadIdx.x;
    const int m0   = blockIdx.x * 128;
    const int w    = tid >> 5, lane = tid & 31;
    const int lr   = lane >> 2, lc = lane & 3;
    const int wm   = (w & 3) * 32;      // 4 warps in m
    const int wn   = (w >> 2) * 32;     // 2 warps in n

    const int sel   = lane >> 3;
    const int a_r8  = (sel & 1) * 8;    // A ldmatrix row offset
    const int a_k8  = (sel >> 1) * 8;   // A ldmatrix k offset
    const int b_k8  = (sel & 1) * 8;    // B trans k offset
    const int b_n8  = (sel >> 1) * 8;   // B trans n offset
    const int lrow8 = lane & 7;

    // A load: row tid>>1, 2 chunks of 8 halves at (tid&1)*16 + {0,8}
    const int prow = tid >> 1;
    const int pc   = (tid & 1) * 16;
    // B load: row tid>>3 (0..31), chunk (tid&7)*8
    const int brow = tid >> 3;
    const int bc8  = (tid & 7) * 8;

    const float pinv = inv[(size_t)z * TT + m0 + prow];

    float acc[2][4][4];
    #pragma unroll
    for (int i = 0; i < 2; i++)
        #pragma unroll
        for (int j = 0; j < 4; j++)
            #pragma unroll
            for (int q = 0; q < 4; q++) acc[i][j][q] = 0.f;

    auto load_stage = [&](int st, int k0) {
        __half* as = Ah + st * AV_ASTG;
        const __half* src = Pun + (size_t)(m0 + prow) * TT + k0 + pc;
        cpa16(smem_u32(as + prow * AV_ALD + pc),     src);
        cpa16(smem_u32(as + prow * AV_ALD + pc + 8), src + 8);
        __half* bs = Bh + st * AV_BSTG;
        cpa16(smem_u32(bs + brow * AV_BLD + bc8), V + (size_t)(k0 + brow) * D3 + bc8);
    };

    const int kiters = TT >> 5;   // 64
    load_stage(0, 0);  cpa_commit();
    load_stage(1, 32); cpa_commit();

    for (int it = 0; it < kiters; it++) {
        cpa_wait<1>();
        __syncthreads();

        const int nxt = it + 2;
        if (nxt < kiters) load_stage(nxt % 3, nxt * 32);
        cpa_commit();

        const __half* as = Ah + (it % 3) * AV_ASTG;
        const __half* bs = Bh + (it % 3) * AV_BSTG;

        #pragma unroll
        for (int kk = 0; kk < 32; kk += 16) {
            uint32_t af[2][4], bw[2][4];
            #pragma unroll
            for (int im = 0; im < 2; im++)
                ldm_x4(af[im], smem_u32(as + (wm + im * 16 + a_r8 + lrow8) * AV_ALD + kk + a_k8));
            #pragma unroll
            for (int j = 0; j < 2; j++)
                ldm_x4_t(bw[j], smem_u32(bs + (kk + b_k8 + lrow8) * AV_BLD + wn + j * 16 + b_n8));
            #pragma unroll
            for (int im = 0; im < 2; im++)
                #pragma unroll
                for (int j = 0; j < 2; j++) {
                    mma_f16(acc[im][2 * j + 0], af[im], bw[j][0], bw[j][1]);
                    mma_f16(acc[im][2 * j + 1], af[im], bw[j][2], bw[j][3]);
                }
        }

        // p_norm write-back: this thread's 16 halves -> fp32 out
        {
            const __half2* srcp = (const __half2*)(as + prow * AV_ALD + pc);
            float* dst = Pout + (size_t)(m0 + prow) * TT + it * 32 + pc;
            #pragma unroll
            for (int i = 0; i < 4; i++) {
                float2 v0 = __half22float2(srcp[2 * i]);
                float2 v1 = __half22float2(srcp[2 * i + 1]);
                *(float4*)(dst + 4 * i) =
                    make_float4(v0.x * pinv, v0.y * pinv, v1.x * pinv, v1.y * pinv);
            }
        }
    }

    // epilogue: nv_h = half(acc * inv[row])
    #pragma unroll
    for (int im = 0; im < 2; im++) {
        const int r0 = m0 + wm + im * 16 + lr;
        const int r1 = r0 + 8;
        const float i0 = inv[(size_t)z * TT + r0];
        const float i1 = inv[(size_t)z * TT + r1];
        #pragma unroll
        for (int in = 0; in < 4; in++) {
            const int cb = wn + in * 8 + 2 * lc;
            const float* ac = acc[im][in];
            *(__half2*)(C + (size_t)r0 * DIM + cb) = __floats2half2_rn(ac[0] * i0, ac[1] * i0);
            *(__half2*)(C + (size_t)r1 * DIM + cb) = __floats2half2_rn(ac[2] * i1, ac[3] * i1);
        }
    }
}

// ---------------- host launch ----------------
extern "C" void kernel_launch(void* const* d_in, const int* in_sizes, int n_in,
                              void* d_out, int out_size)
{
    const float* X      = (const float*)d_in[0];
    const float* WQ     = (const float*)d_in[1];
    const float* WK     = (const float*)d_in[2];
    const float* WV     = (const float*)d_in[3];
    const float* WO     = (const float*)d_in[4];
    const float* attn_g = (const float*)d_in[5];
    const float* attn_b = (const float*)d_in[6];
    const float* ff_g   = (const float*)d_in[7];
    const float* ff_b   = (const float*)d_in[8];
    const float* fW1    = (const float*)d_in[9];
    const float* fb1    = (const float*)d_in[10];
    const float* fW2    = (const float*)d_in[11];
    const float* fb2    = (const float*)d_in[12];
    float* out0 = (float*)d_out;

    __half *nXh, *QKVh, *nvh, *preffh, *hiddenh, *Wth, *WOh, *fW1h, *fW2h, *Ph;
    float *seq, *preff, *part, *inv, *Sfb;
    cudaGetSymbolAddress((void**)&nXh,     g_nXh);
    cudaGetSymbolAddress((void**)&QKVh,    g_QKVh);
    cudaGetSymbolAddress((void**)&nvh,     g_nvh);
    cudaGetSymbolAddress((void**)&seq,     g_seq);
    cudaGetSymbolAddress((void**)&preff,   g_preff);
    cudaGetSymbolAddress((void**)&preffh,  g_preffh);
    cudaGetSymbolAddress((void**)&hiddenh, g_hiddenh);
    cudaGetSymbolAddress((void**)&Wth,     g_Wth);
    cudaGetSymbolAddress((void**)&WOh,     g_WOh);
    cudaGetSymbolAddress((void**)&fW1h,    g_fW1h);
    cudaGetSymbolAddress((void**)&fW2h,    g_fW2h);
    cudaGetSymbolAddress((void**)&Ph,      g_Ph);
    cudaGetSymbolAddress((void**)&part,    g_part);
    cudaGetSymbolAddress((void**)&inv,     g_inv);
    cudaGetSymbolAddress((void**)&Sfb,     g_Sfb);

    cudaFuncSetAttribute(hgemm, cudaFuncAttributeMaxDynamicSharedMemorySize, HG_SMEM);
    cudaFuncSetAttribute(av_kernel, cudaFuncAttributeMaxDynamicSharedMemorySize, AV_SMEM);

    const long long xel     = (long long)BT * DIM;
    const long long attn_el = (long long)NZ * TT * TT;
    float* attn = ((long long)out_size >= xel + attn_el) ? (out0 + xel) : Sfb;

    // 1) nX_h = half(LN(X))
    ln_kernel<<<BT, 256>>>(X, attn_g, attn_b, nullptr, nullptr, nXh);

    // 2) weights -> half, transposed layouts
    wtrans_kernel<<<(DIM * DIM + 255) / 256, 256>>>(WQ, Wth, 0);
    wtrans_kernel<<<(DIM * DIM + 255) / 256, 256>>>(WK, Wth, DIM);
    wtrans_kernel<<<(DIM * DIM + 255) / 256, 256>>>(WV, Wth, 2 * DIM);
    transp_kernel<<<dim3(DIM / 32, DIM / 32), dim3(32, 8)>>>(WO,  WOh,  DIM, DIM);
    transp_kernel<<<dim3(FFD / 32, DIM / 32), dim3(32, 8)>>>(fW1, fW1h, DIM, FFD);
    transp_kernel<<<dim3(DIM / 32, FFD / 32), dim3(32, 8)>>>(fW2, fW2h, FFD, DIM);

    // 3) QKV_h = nX_h @ Wt^T (half out)
    hgemm<<<dim3(D3 / 128, BT / 128), 256, HG_SMEM>>>(
        BT, D3, DIM, nXh, DIM, Wth, DIM, QKVh, D3, 0, nullptr, nullptr, 0, 1);

    // 4) p_un(h) = exp(scores), partial sums
    scores_kernel<<<dim3(KTILES, TT / 128, NZ), 256>>>(QKVh, Ph, part);

    // 5) inv = 1 / rowsum
    rowinv_kernel<<<(ROWS_ALL + 255) / 256, 256>>>(part, inv);

    // 6) AV (fp16 probs) + p_norm fp32 out + nv_h
    av_kernel<<<dim3(TT / 128, NZ), 256, AV_SMEM>>>(Ph, QKVh, inv, nvh, attn);

    // 7) seq = nv_h @ WO^T (fp32 out)
    hgemm<<<dim3(DIM / 128, BT / 128), 256, HG_SMEM>>>(
        BT, DIM, DIM, nvh, DIM, WOh, DIM, seq, DIM, 0, nullptr, nullptr, 0, 0);

    // 8) pre_ff = X + LN(seq): fp32 + half copies
    ln_kernel<<<BT, 256>>>(seq, ff_g, ff_b, X, preff, preffh);

    // 9) hidden_h = half(gelu(preff_h @ fW1^T + fb1))
    hgemm<<<dim3(FFD / 128, BT / 128), 256, HG_SMEM>>>(
        BT, FFD, DIM, preffh, DIM, fW1h, DIM, hiddenh, FFD, 1, fb1, nullptr, 0, 1);

    // 10) out = hidden_h @ fW2^T + fb2 + preff (fp32)
    hgemm<<<dim3(DIM / 128, BT / 128), 256, HG_SMEM>>>(
        BT, DIM, FFD, hiddenh, FFD, fW2h, FFD, out0, DIM, 2, fb2, preff, DIM, 0);
}

// round 12
// speedup vs baseline: 4.8069x; 1.0060x over previous
#include <cuda_runtime.h>
#include <cuda_fp16.h>
#include <math.h>
#include <stdint.h>

#define BB    4
#define TT    2048
#define DIM   1024
#define NH    16
#define HP    64
#define FFD   4096
#define BT    (BB*TT)          // 8192
#define D3    (3*DIM)          // 3072
#define NZ    (BB*NH)          // 64 batch-heads
#define ROWS_ALL (NZ*TT)       // 131072
#define KTILES (TT/128)        // 16

// ---------------- scratch ----------------
__device__ __half g_nXh[(size_t)BT*DIM];
__device__ __half g_QKVh[(size_t)BT*D3];
__device__ __half g_nvh[(size_t)BT*DIM];
__device__ float  g_seq[(size_t)BT*DIM];
__device__ float  g_preff[(size_t)BT*DIM];
__device__ __half g_preffh[(size_t)BT*DIM];
__device__ __half g_hiddenh[(size_t)BT*FFD];
__device__ __half g_Wth[(size_t)D3*DIM];         // QKV weights permuted+transposed [3D][D]
__device__ __half g_WOh[(size_t)DIM*DIM];        // WO^T [D][D]
__device__ __half g_fW1h[(size_t)FFD*DIM];       // fW1^T [FF][D]
__device__ __half g_fW2h[(size_t)DIM*FFD];       // fW2^T [D][FF]
__device__ __half g_Ph[(size_t)NZ*TT*TT];        // unnormalized probs (fp16)
__device__ float  g_part[(size_t)ROWS_ALL*KTILES];
__device__ float  g_inv[(size_t)ROWS_ALL];
__device__ float  g_Sfb[(size_t)NZ*TT*TT];       // attn fallback if d_out lacks room

// ---------------- aux stream/events (created at module load, before checkpoints) -------
struct Aux {
    cudaStream_t s2;
    cudaEvent_t  fork, join;
    Aux() {
        cudaStreamCreateWithFlags(&s2, cudaStreamNonBlocking);
        cudaEventCreateWithFlags(&fork, cudaEventDisableTiming);
        cudaEventCreateWithFlags(&join, cudaEventDisableTiming);
    }
};
static Aux g_aux;

// ---------------- helpers ----------------
__device__ __forceinline__ float gelu_exact(float x)
{
    return 0.5f * x * (1.0f + erff(x * 0.70710678118654752440f));
}

__device__ __forceinline__ uint32_t smem_u32(const void* p)
{
    return (uint32_t)__cvta_generic_to_shared(p);
}
__device__ __forceinline__ void cpa16(uint32_t dst, const void* src)
{
    asm volatile("cp.async.cg.shared.global [%0], [%1], 16;" :: "r"(dst), "l"(src));
}
__device__ __forceinline__ void cpa_commit() { asm volatile("cp.async.commit_group;"); }
template<int N>
__device__ __forceinline__ void cpa_wait() { asm volatile("cp.async.wait_group %0;" :: "n"(N)); }

__device__ __forceinline__ void ldm_x4(uint32_t r[4], uint32_t addr)
{
    asm volatile("ldmatrix.sync.aligned.m8n8.x4.shared.b16 {%0,%1,%2,%3}, [%4];"
                 : "=r"(r[0]), "=r"(r[1]), "=r"(r[2]), "=r"(r[3]) : "r"(addr));
}
__device__ __forceinline__ void ldm_x4_t(uint32_t r[4], uint32_t addr)
{
    asm volatile("ldmatrix.sync.aligned.m8n8.x4.trans.shared.b16 {%0,%1,%2,%3}, [%4];"
                 : "=r"(r[0]), "=r"(r[1]), "=r"(r[2]), "=r"(r[3]) : "r"(addr));
}

__device__ __forceinline__ void mma_f16(float c[4], const uint32_t a[4], uint32_t b0, uint32_t b1)
{
    asm volatile(
        "mma.sync.aligned.m16n8k16.row.col.f32.f16.f16.f32 "
        "{%0,%1,%2,%3}, {%4,%5,%6,%7}, {%8,%9}, {%0,%1,%2,%3};"
        : "+f"(c[0]), "+f"(c[1]), "+f"(c[2]), "+f"(c[3])
        : "r"(a[0]), "r"(a[1]), "r"(a[2]), "r"(a[3]), "r"(b0), "r"(b1));
}

// ---------------- layernorm: optional fp32 out, optional half out ----------------
__global__ void ln_kernel(const float* __restrict__ x,
                          const float* __restrict__ g,
                          const float* __restrict__ b,
                          const float* __restrict__ resid,
                          float* __restrict__ outf,
                          __half* __restrict__ outh)
{
    const size_t row = blockIdx.x;
    const float4* xr = (const float4*)(x + row * (size_t)DIM);
    const int tid = threadIdx.x;
    float4 xv = xr[tid];

    float s  = xv.x + xv.y + xv.z + xv.w;
    float ss = xv.x*xv.x + xv.y*xv.y + xv.z*xv.z + xv.w*xv.w;

    #pragma unroll
    for (int o = 16; o > 0; o >>= 1) {
        s  += __shfl_xor_sync(0xffffffffu, s,  o);
        ss += __shfl_xor_sync(0xffffffffu, ss, o);
    }
    __shared__ float rs[8], rss[8];
    int wid = tid >> 5, lane = tid & 31;
    if (lane == 0) { rs[wid] = s; rss[wid] = ss; }
    __syncthreads();
    __shared__ float s_mean, s_rstd;
    if (tid == 0) {
        float ts = 0.f, tss = 0.f;
        #pragma unroll
        for (int i = 0; i < 8; i++) { ts += rs[i]; tss += rss[i]; }
        float mean = ts * (1.0f / DIM);
        float var  = tss * (1.0f / DIM) - mean * mean;
        s_mean = mean;
        s_rstd = rsqrtf(var + 1e-5f);
    }
    __syncthreads();
    const float mean = s_mean, rstd = s_rstd;

    const float4 gv = ((const float4*)g)[tid];
    const float4 bv = ((const float4*)b)[tid];
    float4 o4;
    o4.x = (xv.x - mean) * rstd * gv.x + bv.x;
    o4.y = (xv.y - mean) * rstd * gv.y + bv.y;
    o4.z = (xv.z - mean) * rstd * gv.z + bv.z;
    o4.w = (xv.w - mean) * rstd * gv.w + bv.w;
    if (resid) {
        const float4 rv = ((const float4*)(resid + row * (size_t)DIM))[tid];
        o4.x += rv.x; o4.y += rv.y; o4.z += rv.z; o4.w += rv.w;
    }
    if (outf) ((float4*)(outf + row * (size_t)DIM))[tid] = o4;
    if (outh) {
        __half2* oh = (__half2*)(outh + row * (size_t)DIM);
        oh[tid * 2 + 0] = __floats2half2_rn(o4.x, o4.y);
        oh[tid * 2 + 1] = __floats2half2_rn(o4.z, o4.w);
    }
}

// ------- permute (H,D,P) -> rows of [3D][D], half, coalesced via smem tiles -------
// src w[h][d][p]; dst[(rowoff + h*HP + p)][d]. Per h: transpose DxP.
__global__ void wtrans_kernel(const float* __restrict__ w, __half* __restrict__ o, int rowoff)
{
    __shared__ float t[32][33];
    const int h  = blockIdx.z;
    const int p0 = blockIdx.x * 32;
    const int d0 = blockIdx.y * 32;
    const float* src = w + ((size_t)h * DIM + d0) * HP + p0;
    #pragma unroll
    for (int j = 0; j < 32; j += 8)
        t[threadIdx.y + j][threadIdx.x] = src[(size_t)(threadIdx.y + j) * HP + threadIdx.x];
    __syncthreads();
    #pragma unroll
    for (int j = 0; j < 32; j += 8)
        o[(size_t)(rowoff + h * HP + p0 + threadIdx.y + j) * DIM + d0 + threadIdx.x] =
            __float2half(t[threadIdx.x][threadIdx.y + j]);
}

// ---------------- tiled transpose: dst_h[c][r] = half(src[r][c]) ----------------
__global__ void transp_kernel(const float* __restrict__ src, __half* __restrict__ dst, int R, int C)
{
    __shared__ float t[32][33];
    int c0 = blockIdx.x * 32, r0 = blockIdx.y * 32;
    #pragma unroll
    for (int j = 0; j < 32; j += 8)
        t[threadIdx.y + j][threadIdx.x] = src[(size_t)(r0 + threadIdx.y + j) * C + c0 + threadIdx.x];
    __syncthreads();
    #pragma unroll
    for (int j = 0; j < 32; j += 8)
        dst[(size_t)(c0 + threadIdx.y + j) * R + r0 + threadIdx.x] = __float2half(t[threadIdx.x][threadIdx.y + j]);
}

// ---------------- rowsum -> inverse ----------------
__global__ void rowinv_kernel(const float* __restrict__ part, float* __restrict__ inv)
{
    int idx = blockIdx.x * blockDim.x + threadIdx.x;
    if (idx >= ROWS_ALL) return;
    const float4* p = (const float4*)(part + (size_t)idx * KTILES);
    float s = 0.f;
    #pragma unroll
    for (int i = 0; i < KTILES / 4; i++) {
        float4 v = p[i];
        s += v.x + v.y + v.z + v.w;
    }
    inv[idx] = 1.0f / s;
}

// ---------------- p_norm: attn[row][k] = float(Ph[row][k]) * inv[row] ----------------
__global__ void pnorm_kernel(const __half* __restrict__ Ph,
                             const float* __restrict__ inv,
                             float* __restrict__ attn)
{
    const size_t row = blockIdx.x;
    const float s = inv[row];
    const __half2* src = (const __half2*)(Ph + row * (size_t)TT);
    float4* dst = (float4*)(attn + row * (size_t)TT);
    const int tid = threadIdx.x;
    #pragma unroll
    for (int i = 0; i < 2; i++) {
        const int e = tid + i * 256;          // half2-quad index (0..511)
        float2 a = __half22float2(src[e * 2 + 0]);
        float2 b = __half22float2(src[e * 2 + 1]);
        dst[e] = make_float4(a.x * s, a.y * s, b.x * s, b.y * s);
    }
}

// ================= fp16 dense GEMM (NT): C[m,n] = sum_k A[m,k]*Bt[n,k] =================
// 128x128x32 tile, 4-stage cp.async, ldmatrix + m16n8k16. 8 warps (2x4), warp 64x32.
#define HG_LD     40                      // halves per row (32 data + 8 pad)
#define HG_STAGE  (128*HG_LD)             // halves per operand stage
#define HG_SMEM   (4 * 2 * HG_STAGE * 2)  // bytes = 81920

__global__ __launch_bounds__(256, 2) void hgemm(
    int M, int N, int K,
    const __half* __restrict__ A, int lda,
    const __half* __restrict__ Bt, int ldb,
    void* __restrict__ Cv, int ldc,
    int epi, const float* __restrict__ bias,
    const float* __restrict__ resid, int ldr, int out_half)
{
    extern __shared__ __half hsm[];
    __half* Asm = hsm;
    __half* Bsm = hsm + 4 * HG_STAGE;

    const int tid  = threadIdx.x;
    const int m0   = blockIdx.y * 128;
    const int n0   = blockIdx.x * 128;
    const int w    = tid >> 5, lane = tid & 31;
    const int lr   = lane >> 2, lc = lane & 3;
    const int wm   = (w & 1) * 64;
    const int wn   = (w >> 1) * 32;

    const int lrow = tid >> 1;
    const int lcol = (tid & 1) * 16;

    const int sel   = lane >> 3;
    const int off8  = (sel & 1) * 8;
    const int koff8 = (sel >> 1) * 8;
    const int lrow8 = lane & 7;

    float acc[4][4][4];
    #pragma unroll
    for (int i = 0; i < 4; i++)
        #pragma unroll
        for (int j = 0; j < 4; j++)
            #pragma unroll
            for (int q = 0; q < 4; q++) acc[i][j][q] = 0.f;

    auto load_stage = [&](int st, int k0) {
        __half* as = Asm + st * HG_STAGE;
        __half* bs = Bsm + st * HG_STAGE;
        #pragma unroll
        for (int i = 0; i < 2; i++) {
            int c = lcol + i * 8;
            cpa16(smem_u32(as + lrow * HG_LD + c), A  + (size_t)(m0 + lrow) * lda + k0 + c);
            cpa16(smem_u32(bs + lrow * HG_LD + c), Bt + (size_t)(n0 + lrow) * ldb + k0 + c);
        }
    };

    const int kiters = K >> 5;
    load_stage(0, 0);  cpa_commit();
    load_stage(1, 32); cpa_commit();
    load_stage(2, 64); cpa_commit();

    for (int it = 0; it < kiters; it++) {
        cpa_wait<2>();
        __syncthreads();

        const int nxt = it + 3;
        if (nxt < kiters) load_stage(nxt & 3, nxt * 32);
        cpa_commit();

        const __half* as = Asm + (it & 3) * HG_STAGE;
        const __half* bs = Bsm + (it & 3) * HG_STAGE;

        #pragma unroll
        for (int kk = 0; kk < 32; kk += 16) {
            uint32_t af[4][4], bf[2][4];
            #pragma unroll
            for (int im = 0; im < 4; im++)
                ldm_x4(af[im], smem_u32(as + (wm + im * 16 + off8 + lrow8) * HG_LD + kk + koff8));
            #pragma unroll
            for (int j = 0; j < 2; j++)
                ldm_x4(bf[j], smem_u32(bs + (wn + j * 16 + off8 + lrow8) * HG_LD + kk + koff8));
            #pragma unroll
            for (int im = 0; im < 4; im++)
                #pragma unroll
                for (int j = 0; j < 2; j++) {
                    mma_f16(acc[im][2 * j + 0], af[im], bf[j][0], bf[j][2]);
                    mma_f16(acc[im][2 * j + 1], af[im], bf[j][1], bf[j][3]);
                }
        }
    }

    // epilogue
    #pragma unroll
    for (int im = 0; im < 4; im++) {
        const int r0 = m0 + wm + im * 16 + lr;
        const int r1 = r0 + 8;
        #pragma unroll
        for (int in = 0; in < 4; in++) {
            const int cb = n0 + wn + in * 8 + 2 * lc;
            const float* ac = acc[im][in];
            float b0 = 0.f, b1 = 0.f;
            if (epi != 0) { b0 = bias[cb]; b1 = bias[cb + 1]; }

            float v0 = ac[0], v1 = ac[1];
            if (epi == 1) { v0 = gelu_exact(v0 + b0); v1 = gelu_exact(v1 + b1); }
            else if (epi == 2) {
                const float2 rv = *(const float2*)(resid + (size_t)r0 * ldr + cb);
                v0 += b0 + rv.x; v1 += b1 + rv.y;
            }
            float v2 = ac[2], v3 = ac[3];
            if (epi == 1) { v2 = gelu_exact(v2 + b0); v3 = gelu_exact(v3 + b1); }
            else if (epi == 2) {
                const float2 rv = *(const float2*)(resid + (size_t)r1 * ldr + cb);
                v2 += b0 + rv.x; v3 += b1 + rv.y;
            }
            if (out_half) {
                __half* C = (__half*)Cv;
                *(__half2*)(C + (size_t)r0 * ldc + cb) = __floats2half2_rn(v0, v1);
                *(__half2*)(C + (size_t)r1 * ldc + cb) = __floats2half2_rn(v2, v3);
            } else {
                float* C = (float*)Cv;
                *(float2*)(C + (size_t)r0 * ldc + cb) = make_float2(v0, v1);
                *(float2*)(C + (size_t)r1 * ldc + cb) = make_float2(v2, v3);
            }
        }
    }
}

// ================= scores: p_un(h) = exp(K.Q^T/8) + partial row sums ==========
#define SC_LD 72

__global__ __launch_bounds__(256, 2) void scores_kernel(
    const __half* __restrict__ QKVh, __half* __restrict__ Ph, float* __restrict__ part)
{
    __shared__ __half sA[128 * SC_LD];
    __shared__ __half sB[128 * SC_LD];
    __shared__ float s_part[4][128];

    const int z  = blockIdx.z;
    const int bb = z >> 4, hh = z & 15;
    const __half* A = QKVh + DIM + (size_t)bb * TT * D3 + hh * HP;   // K proj
    const __half* B = QKVh +        (size_t)bb * TT * D3 + hh * HP;  // Q proj
    __half* C = Ph + (size_t)z * TT * TT;

    const int tid  = threadIdx.x;
    const int m0   = blockIdx.y * 128;
    const int n0   = blockIdx.x * 128;
    const int w    = tid >> 5, lane = tid & 31;
    const int lr   = lane >> 2, lc = lane & 3;
    const int wm   = (w & 1) * 64;
    const int wn   = (w >> 1) * 32;
    const int wni  = w >> 1;

    const int sel   = lane >> 3;
    const int off8  = (sel & 1) * 8;
    const int koff8 = (sel >> 1) * 8;
    const int lrow8 = lane & 7;

    #pragma unroll
    for (int i = 0; i < 4; i++) {
        int g = tid + i * 256;
        int row = g >> 3, c8 = (g & 7) * 8;
        cpa16(smem_u32(sA + row * SC_LD + c8), A + (size_t)(m0 + row) * D3 + c8);
        cpa16(smem_u32(sB + row * SC_LD + c8), B + (size_t)(n0 + row) * D3 + c8);
    }
    cpa_commit();
    cpa_wait<0>();
    __syncthreads();

    float acc[4][4][4];
    #pragma unroll
    for (int i = 0; i < 4; i++)
        #pragma unroll
        for (int j = 0; j < 4; j++)
            #pragma unroll
            for (int q = 0; q < 4; q++) acc[i][j][q] = 0.f;

    #pragma unroll
    for (int kk = 0; kk < 64; kk += 16) {
        uint32_t af[4][4], bf[2][4];
        #pragma unroll
        for (int im = 0; im < 4; im++)
            ldm_x4(af[im], smem_u32(sA + (wm + im * 16 + off8 + lrow8) * SC_LD + kk + koff8));
        #pragma unroll
        for (int j = 0; j < 2; j++)
            ldm_x4(bf[j], smem_u32(sB + (wn + j * 16 + off8 + lrow8) * SC_LD + kk + koff8));
        #pragma unroll
        for (int im = 0; im < 4; im++)
            #pragma unroll
            for (int j = 0; j < 2; j++) {
                mma_f16(acc[im][2 * j + 0], af[im], bf[j][0], bf[j][2]);
                mma_f16(acc[im][2 * j + 1], af[im], bf[j][1], bf[j][3]);
            }
    }

    // epilogue: exp, half store, deterministic partial row sums
    #pragma unroll
    for (int im = 0; im < 4; im++) {
        const int r0 = m0 + wm + im * 16 + lr;
        const int r1 = r0 + 8;
        float sum0 = 0.f, sum1 = 0.f;
        #pragma unroll
        for (int in = 0; in < 4; in++) {
            const int cb = n0 + wn + in * 8 + 2 * lc;
            float* ac = acc[im][in];
            float e0 = __expf(0.125f * ac[0]);
            float e1 = __expf(0.125f * ac[1]);
            float e2 = __expf(0.125f * ac[2]);
            float e3 = __expf(0.125f * ac[3]);
            sum0 += e0 + e1;
            sum1 += e2 + e3;
            *(__half2*)(C + (size_t)r0 * TT + cb) = __floats2half2_rn(e0, e1);
            *(__half2*)(C + (size_t)r1 * TT + cb) = __floats2half2_rn(e2, e3);
        }
        sum0 += __shfl_xor_sync(0xffffffffu, sum0, 1);
        sum0 += __shfl_xor_sync(0xffffffffu, sum0, 2);
        sum1 += __shfl_xor_sync(0xffffffffu, sum1, 1);
        sum1 += __shfl_xor_sync(0xffffffffu, sum1, 2);
        if (lc == 0) {
            s_part[wni][wm + im * 16 + lr]     = sum0;
            s_part[wni][wm + im * 16 + 8 + lr] = sum1;
        }
    }
    __syncthreads();
    if (tid < 128) {
        float t = s_part[0][tid] + s_part[1][tid] + s_part[2][tid] + s_part[3][tid];
        part[((size_t)z * TT + m0 + tid) * KTILES + blockIdx.x] = t;
    }
}

// ================= AV: nv = (p_un @ V) * inv  (no attn write-back) =================
// tile 128x64x32. A = p_un fp16 (ldmatrix), B = V half via ldmatrix.trans.
#define AV_ALD    40                        // halves per A row (32 + 8 pad)
#define AV_ASTG   (128*AV_ALD)              // halves
#define AV_BLD    72                        // halves per B row (64 + 8 pad)
#define AV_BSTG   (32*AV_BLD)               // halves
#define AV_SMEM   (3 * (AV_ASTG + AV_BSTG) * 2)   // 44544 B

__global__ __launch_bounds__(256, 2) void av_kernel(
    const __half* __restrict__ Ph, const __half* __restrict__ QKVh,
    const float* __restrict__ inv, __half* __restrict__ nvh)
{
    extern __shared__ __half avh[];
    __half* Ah = avh;
    __half* Bh = avh + 3 * AV_ASTG;

    const int z  = blockIdx.y;
    const int bb = z >> 4, hh = z & 15;
    const __half* Pun = Ph + (size_t)z * TT * TT;
    const __half* V = QKVh + 2 * DIM + (size_t)bb * TT * D3 + hh * HP;
    __half* C = nvh + (size_t)bb * TT * DIM + hh * HP;

    const int tid  = threadIdx.x;
    const int m0   = blockIdx.x * 128;
    const int w    = tid >> 5, lane = tid & 31;
    const int lr   = lane >> 2, lc = lane & 3;
    const int wm   = (w & 3) * 32;      // 4 warps in m
    const int wn   = (w >> 2) * 32;     // 2 warps in n

    const int sel   = lane >> 3;
    const int a_r8  = (sel & 1) * 8;
    const int a_k8  = (sel >> 1) * 8;
    const int b_k8  = (sel & 1) * 8;
    const int b_n8  = (sel >> 1) * 8;
    const int lrow8 = lane & 7;

    const int prow = tid >> 1;
    const int pc   = (tid & 1) * 16;
    const int brow = tid >> 3;
    const int bc8  = (tid & 7) * 8;

    float acc[2][4][4];
    #pragma unroll
    for (int i = 0; i < 2; i++)
        #pragma unroll
        for (int j = 0; j < 4; j++)
            #pragma unroll
            for (int q = 0; q < 4; q++) acc[i][j][q] = 0.f;

    auto load_stage = [&](int st, int k0) {
        __half* as = Ah + st * AV_ASTG;
        const __half* src = Pun + (size_t)(m0 + prow) * TT + k0 + pc;
        cpa16(smem_u32(as + prow * AV_ALD + pc),     src);
        cpa16(smem_u32(as + prow * AV_ALD + pc + 8), src + 8);
        __half* bs = Bh + st * AV_BSTG;
        cpa16(smem_u32(bs + brow * AV_BLD + bc8), V + (size_t)(k0 + brow) * D3 + bc8);
    };

    const int kiters = TT >> 5;   // 64
    load_stage(0, 0);  cpa_commit();
    load_stage(1, 32); cpa_commit();

    for (int it = 0; it < kiters; it++) {
        cpa_wait<1>();
        __syncthreads();

        const int nxt = it + 2;
        if (nxt < kiters) load_stage(nxt % 3, nxt * 32);
        cpa_commit();

        const __half* as = Ah + (it % 3) * AV_ASTG;
        const __half* bs = Bh + (it % 3) * AV_BSTG;

        #pragma unroll
        for (int kk = 0; kk < 32; kk += 16) {
            uint32_t af[2][4], bw[2][4];
            #pragma unroll
            for (int im = 0; im < 2; im++)
                ldm_x4(af[im], smem_u32(as + (wm + im * 16 + a_r8 + lrow8) * AV_ALD + kk + a_k8));
            #pragma unroll
            for (int j = 0; j < 2; j++)
                ldm_x4_t(bw[j], smem_u32(bs + (kk + b_k8 + lrow8) * AV_BLD + wn + j * 16 + b_n8));
            #pragma unroll
            for (int im = 0; im < 2; im++)
                #pragma unroll
                for (int j = 0; j < 2; j++) {
                    mma_f16(acc[im][2 * j + 0], af[im], bw[j][0], bw[j][1]);
                    mma_f16(acc[im][2 * j + 1], af[im], bw[j][2], bw[j][3]);
                }
        }
    }

    // epilogue: nv_h = half(acc * inv[row])
    #pragma unroll
    for (int im = 0; im < 2; im++) {
        const int r0 = m0 + wm + im * 16 + lr;
        const int r1 = r0 + 8;
        const float i0 = inv[(size_t)z * TT + r0];
        const float i1 = inv[(size_t)z * TT + r1];
        #pragma unroll
        for (int in = 0; in < 4; in++) {
            const int cb = wn + in * 8 + 2 * lc;
            const float* ac = acc[im][in];
            *(__half2*)(C + (size_t)r0 * DIM + cb) = __floats2half2_rn(ac[0] * i0, ac[1] * i0);
            *(__half2*)(C + (size_t)r1 * DIM + cb) = __floats2half2_rn(ac[2] * i1, ac[3] * i1);
        }
    }
}

// ---------------- host launch ----------------
extern "C" void kernel_launch(void* const* d_in, const int* in_sizes, int n_in,
                              void* d_out, int out_size)
{
    const float* X      = (const float*)d_in[0];
    const float* WQ     = (const float*)d_in[1];
    const float* WK     = (const float*)d_in[2];
    const float* WV     = (const float*)d_in[3];
    const float* WO     = (const float*)d_in[4];
    const float* attn_g = (const float*)d_in[5];
    const float* attn_b = (const float*)d_in[6];
    const float* ff_g   = (const float*)d_in[7];
    const float* ff_b   = (const float*)d_in[8];
    const float* fW1    = (const float*)d_in[9];
    const float* fb1    = (const float*)d_in[10];
    const float* fW2    = (const float*)d_in[11];
    const float* fb2    = (const float*)d_in[12];
    float* out0 = (float*)d_out;

    __half *nXh, *QKVh, *nvh, *preffh, *hiddenh, *Wth, *WOh, *fW1h, *fW2h, *Ph;
    float *seq, *preff, *part, *inv, *Sfb;
    cudaGetSymbolAddress((void**)&nXh,     g_nXh);
    cudaGetSymbolAddress((void**)&QKVh,    g_QKVh);
    cudaGetSymbolAddress((void**)&nvh,     g_nvh);
    cudaGetSymbolAddress((void**)&seq,     g_seq);
    cudaGetSymbolAddress((void**)&preff,   g_preff);
    cudaGetSymbolAddress((void**)&preffh,  g_preffh);
    cudaGetSymbolAddress((void**)&hiddenh, g_hiddenh);
    cudaGetSymbolAddress((void**)&Wth,     g_Wth);
    cudaGetSymbolAddress((void**)&WOh,     g_WOh);
    cudaGetSymbolAddress((void**)&fW1h,    g_fW1h);
    cudaGetSymbolAddress((void**)&fW2h,    g_fW2h);
    cudaGetSymbolAddress((void**)&Ph,      g_Ph);
    cudaGetSymbolAddress((void**)&part,    g_part);
    cudaGetSymbolAddress((void**)&inv,     g_inv);
    cudaGetSymbolAddress((void**)&Sfb,     g_Sfb);

    cudaFuncSetAttribute(hgemm, cudaFuncAttributeMaxDynamicSharedMemorySize, HG_SMEM);
    cudaFuncSetAttribute(av_kernel, cudaFuncAttributeMaxDynamicSharedMemorySize, AV_SMEM);

    const long long xel     = (long long)BT * DIM;
    const long long attn_el = (long long)NZ * TT * TT;
    float* attn = ((long long)out_size >= xel + attn_el) ? (out0 + xel) : Sfb;

    // 1) nX_h = half(LN(X))
    ln_kernel<<<BT, 256>>>(X, attn_g, attn_b, nullptr, nullptr, nXh);

    // 2) weights -> half, transposed layouts
    wtrans_kernel<<<dim3(HP / 32, DIM / 32, NH), dim3(32, 8)>>>(WQ, Wth, 0);
    wtrans_kernel<<<dim3(HP / 32, DIM / 32, NH), dim3(32, 8)>>>(WK, Wth, DIM);
    wtrans_kernel<<<dim3(HP / 32, DIM / 32, NH), dim3(32, 8)>>>(WV, Wth, 2 * DIM);
    transp_kernel<<<dim3(DIM / 32, DIM / 32), dim3(32, 8)>>>(WO,  WOh,  DIM, DIM);
    transp_kernel<<<dim3(FFD / 32, DIM / 32), dim3(32, 8)>>>(fW1, fW1h, DIM, FFD);
    transp_kernel<<<dim3(DIM / 32, FFD / 32), dim3(32, 8)>>>(fW2, fW2h, FFD, DIM);

    // 3) QKV_h = nX_h @ Wt^T (half out)
    hgemm<<<dim3(D3 / 128, BT / 128), 256, HG_SMEM>>>(
        BT, D3, DIM, nXh, DIM, Wth, DIM, QKVh, D3, 0, nullptr, nullptr, 0, 1);

    // 4) p_un(h) = exp(scores), partial sums
    scores_kernel<<<dim3(KTILES, TT / 128, NZ), 256>>>(QKVh, Ph, part);

    // 5) inv = 1 / rowsum
    rowinv_kernel<<<(ROWS_ALL + 255) / 256, 256>>>(part, inv);

    // --- fork: attn output (leaf of dataflow) overlaps with AV/WO/FF chain ---
    cudaEventRecord(g_aux.fork, 0);
    cudaStreamWaitEvent(g_aux.s2, g_aux.fork, 0);
    pnorm_kernel<<<ROWS_ALL, 256, 0, g_aux.s2>>>(Ph, inv, attn);
    cudaEventRecord(g_aux.join, g_aux.s2);

    // 6) AV (nv only)
    av_kernel<<<dim3(TT / 128, NZ), 256, AV_SMEM>>>(Ph, QKVh, inv, nvh);

    // 7) seq = nv_h @ WO^T (fp32 out)
    hgemm<<<dim3(DIM / 128, BT / 128), 256, HG_SMEM>>>(
        BT, DIM, DIM, nvh, DIM, WOh, DIM, seq, DIM, 0, nullptr, nullptr, 0, 0);

    // 8) pre_ff = X + LN(seq): fp32 + half copies
    ln_kernel<<<BT, 256>>>(seq, ff_g, ff_b, X, preff, preffh);

    // 9) hidden_h = half(gelu(preff_h @ fW1^T + fb1))
    hgemm<<<dim3(FFD / 128, BT / 128), 256, HG_SMEM>>>(
        BT, FFD, DIM, preffh, DIM, fW1h, DIM, hiddenh, FFD, 1, fb1, nullptr, 0, 1);

    // 10) out = hidden_h @ fW2^T + fb2 + preff (fp32)
    hgemm<<<dim3(DIM / 128, BT / 128), 256, HG_SMEM>>>(
        BT, DIM, FFD, hiddenh, FFD, fW2h, FFD, out0, DIM, 2, fb2, preff, DIM, 0);

    // --- join forked stream before capture ends ---
    cudaStreamWaitEvent(0, g_aux.join, 0);
}